// round 11
// baseline (speedup 1.0000x reference)
#include <cuda_runtime.h>
#include <cuda_bf16.h>
#include <cstdint>

#define TT 16
#define NU 4096
#define EE 128
#define HH 128
#define G4 512
#define LPATH 32
#define NPATH 1024
#define NB 8
#define VOCAB 16384

typedef unsigned long long u64;

__device__ __forceinline__ uint32_t smem_to_u32(const void* p) {
    uint32_t a;
    asm("{ .reg .u64 t; cvta.to.shared.u64 t, %1; cvt.u32.u64 %0, t; }" : "=r"(a) : "l"(p));
    return a;
}
#define LDSM_X4(r, addr) \
    asm volatile("ldmatrix.sync.aligned.m8n8.x4.shared.b16 {%0,%1,%2,%3}, [%4];" \
        : "=r"((r)[0]), "=r"((r)[1]), "=r"((r)[2]), "=r"((r)[3]) : "r"(addr))
__device__ __forceinline__ void mma16816(float* c, const uint32_t* a, uint32_t b0, uint32_t b1) {
    asm volatile("mma.sync.aligned.m16n8k16.row.col.f32.bf16.bf16.f32 "
        "{%0,%1,%2,%3}, {%4,%5,%6,%7}, {%8,%9}, {%0,%1,%2,%3};"
        : "+f"(c[0]), "+f"(c[1]), "+f"(c[2]), "+f"(c[3])
        : "r"(a[0]), "r"(a[1]), "r"(a[2]), "r"(a[3]), "r"(b0), "r"(b1));
}
__device__ __forceinline__ void ffma2(u64& d, u64 a, u64 b) {
    asm("fma.rn.f32x2 %0, %1, %2, %0;" : "+l"(d) : "l"(a), "l"(b));
}
__device__ __forceinline__ u64 dup2(float x) {
    u64 r; asm("mov.b64 %0, {%1, %1};" : "=l"(r) : "f"(x)); return r;
}
__device__ __forceinline__ float2 unpack2(u64 v) {
    float2 f; asm("mov.b64 {%0, %1}, %2;" : "=f"(f.x), "=f"(f.y) : "l"(v)); return f;
}
#define CP_ASYNC16(dst_u32, src_ptr) \
    asm volatile("cp.async.cg.shared.global [%0], [%1], 16;" :: "r"(dst_u32), "l"(src_ptr))
#define CP_COMMIT asm volatile("cp.async.commit_group;" ::: "memory")
#define CP_WAIT0  asm volatile("cp.async.wait_group 0;" ::: "memory")

// ============ device scratch ============
__device__ int   g_tok_len[NU];
__device__ int   g_p_len[NPATH], g_p_fe[NPATH], g_p_off[NPATH], g_p_un[NPATH];
__device__ float g_VTf[VOCAB * G4], g_VTb[VOCAB * G4];
__device__ float g_PTf[NU * G4],    g_PTb[NU * G4];
__device__ float g_lin[TT * NU * EE];
__device__ float g_WhT[4][HH * G4];     // packed [k][cell][gate]
__device__ float g_bperm[2][G4];        // permuted tl biases
__device__ float g_zero[G4];
__device__ __nv_bfloat16 g_emb_h[VOCAB * EE],  g_emb_l[VOCAB * EE];
__device__ __nv_bfloat16 g_Hcat_h[TT * NU * 2 * HH], g_Hcat_l[TT * NU * 2 * HH];
__device__ __nv_bfloat16 g_tf_h[NU * EE], g_tf_l[NU * EE];
__device__ __nv_bfloat16 g_Hp_h[LPATH * NPATH * 2 * HH], g_Hp_l[LPATH * NPATH * 2 * HH];
__device__ __nv_bfloat16 g_Wih[4][G4 * EE], g_Wil[4][G4 * EE];
__device__ __nv_bfloat16 g_W2h[2][EE * 2 * HH], g_W2l[2][EE * 2 * HH];

// ============ setup kernels ============
__global__ void k_tok_len(const int* __restrict__ units) {
    int n = blockIdx.x * blockDim.x + threadIdx.x;
    if (n >= NU) return;
    int len = TT;
    for (int t = 0; t < TT; t++) if (units[t * NU + n] == 0) { len = t; break; }
    g_tok_len[n] = len;
}
// y<4: pack Wh as [k][cell][gate]; y==4: permute tl biases
__global__ void k_transpose4(const float* __restrict__ W0, const float* __restrict__ W1,
                             const float* __restrict__ W2, const float* __restrict__ W3,
                             const float* __restrict__ B0, const float* __restrict__ B1) {
    int w = blockIdx.y;
    int idx = blockIdx.x * blockDim.x + threadIdx.x;
    if (w == 4) {
        if (idx >= 2 * G4) return;
        int wq = idx >> 9, i = idx & 511;
        g_bperm[wq][(i & 127) * 4 + (i >> 7)] = (wq ? B1 : B0)[i];
        return;
    }
    const float* W = (w == 0) ? W0 : (w == 1) ? W1 : (w == 2) ? W2 : W3;
    if (idx >= G4 * HH) return;
    int kk = idx & 127, j = idx >> 7;
    int gate = j >> 7, cell = j & 127;
    g_WhT[w][kk * G4 + cell * 4 + gate] = W[idx];
}
__global__ void k_plen(const int* __restrict__ paths,
                       const int* __restrict__ upd, const int* __restrict__ ppd) {
    int p = blockIdx.x * blockDim.x + threadIdx.x;
    if (p >= NPATH) return;
    int dd = NB - 1, cum = 0;
    for (int i = 0; i < NB; i++) { int nx = cum + ppd[i]; if (p >= cum && p < nx) { dd = i; break; } cum = nx; }
    int off = 0;
    for (int i = 0; i < dd; i++) off += upd[i];
    int un = upd[dd];
    int fe = LPATH;
    for (int t = 0; t < LPATH; t++) if (paths[t * NPATH + p] == -1) { fe = t; break; }
    int plen = LPATH;
    for (int t = 0; t < LPATH; t++) {
        bool msk;
        if (t >= fe) msk = true;
        else { int v = paths[t * NPATH + p]; msk = (v < 0) || (v > un); }
        if (msk) { plen = t; break; }
    }
    g_p_len[p] = plen; g_p_fe[p] = fe; g_p_off[p] = off; g_p_un[p] = un;
}

__device__ __forceinline__ void hilo_store(__nv_bfloat16* hi, __nv_bfloat16* lo, int i, float4 v) {
    __nv_bfloat16 h0 = __float2bfloat16(v.x), h1 = __float2bfloat16(v.y);
    __nv_bfloat16 h2 = __float2bfloat16(v.z), h3 = __float2bfloat16(v.w);
    __nv_bfloat162* H = reinterpret_cast<__nv_bfloat162*>(hi);
    __nv_bfloat162* L = reinterpret_cast<__nv_bfloat162*>(lo);
    H[2 * i] = __nv_bfloat162(h0, h1); H[2 * i + 1] = __nv_bfloat162(h2, h3);
    L[2 * i] = __nv_bfloat162(__float2bfloat16(v.x - __bfloat162float(h0)),
                              __float2bfloat16(v.y - __bfloat162float(h1)));
    L[2 * i + 1] = __nv_bfloat162(__float2bfloat16(v.z - __bfloat162float(h2)),
                                  __float2bfloat16(v.w - __bfloat162float(h3)));
}
struct HiloArgs { const float* s[4]; __nv_bfloat16* h[4]; __nv_bfloat16* l[4]; int n[4]; int pm[4]; };
__global__ void k_hilo_multi(HiloArgs a) {
    int seg = blockIdx.y;
    int i = blockIdx.x * blockDim.x + threadIdx.x;
    if (i >= a.n[seg]) return;
    float4 v = reinterpret_cast<const float4*>(a.s[seg])[i];
    int di = i;
    if (a.pm[seg]) {                 // permute 512 rows: j' = (cell<<2)|gate
        int j = i >> 5, off = i & 31;
        di = ((((j & 127) << 2) | (j >> 7)) << 5) | off;
    }
    hilo_store(a.h[seg], a.l[seg], di, v);
}

// ============ warp-MMA split-bf16 GEMM (R10 dual, passing) ============
template <int K>
__global__ __launch_bounds__(256) void k_mm2(
    const __nv_bfloat16* __restrict__ Ah, const __nv_bfloat16* __restrict__ Al,
    const __nv_bfloat16* __restrict__ Bh0, const __nv_bfloat16* __restrict__ Bl0,
    const float* __restrict__ bias0, float* __restrict__ C0,
    const __nv_bfloat16* __restrict__ Bh1, const __nv_bfloat16* __restrict__ Bl1,
    const float* __restrict__ bias1, float* __restrict__ C1, int Ntot)
{
    const __nv_bfloat16* __restrict__ Bh = blockIdx.z ? Bh1 : Bh0;
    const __nv_bfloat16* __restrict__ Bl = blockIdx.z ? Bl1 : Bl0;
    const float* __restrict__ bias = blockIdx.z ? bias1 : bias0;
    float* __restrict__ C = blockIdx.z ? C1 : C0;

    constexpr int LDS = 72;
    extern __shared__ __nv_bfloat16 sm[];
    __nv_bfloat16* sAh = sm;
    __nv_bfloat16* sAl = sAh + 128 * LDS;
    __nv_bfloat16* sBh = sAl + 128 * LDS;
    __nv_bfloat16* sBl = sBh + 128 * LDS;

    const int tid = threadIdx.x, lane = tid & 31, wid = tid >> 5;
    const int m0 = blockIdx.y * 128, n0 = blockIdx.x * 128;
    const int wm = (wid & 3) * 32, wn = (wid >> 2) * 64;
    const int g = lane >> 2, tg = lane & 3;
    const int seg = lane >> 3, i8 = lane & 7;
    const uint32_t sAh_b = smem_to_u32(sAh), sAl_b = smem_to_u32(sAl);
    const uint32_t sBh_b = smem_to_u32(sBh), sBl_b = smem_to_u32(sBl);

    float acc[2][8][4];
#pragma unroll
    for (int im = 0; im < 2; im++)
#pragma unroll
        for (int jn = 0; jn < 8; jn++)
#pragma unroll
            for (int q = 0; q < 4; q++) acc[im][jn][q] = 0.f;

    for (int kc = 0; kc < K; kc += 64) {
        if (kc) __syncthreads();
        {
            const __nv_bfloat16* srcs[4] = {Ah, Al, Bh, Bl};
            __nv_bfloat16* dsts[4] = {sAh, sAl, sBh, sBl};
            const int r0s[4] = {m0, m0, n0, n0};
#pragma unroll
            for (int t = 0; t < 4; t++) {
                for (int v = tid; v < 1024; v += 256) {
                    int row = v >> 3, q = (v & 7) * 8;
                    *reinterpret_cast<uint4*>(dsts[t] + row * LDS + q) =
                        *reinterpret_cast<const uint4*>(srcs[t] + (size_t)(r0s[t] + row) * K + kc + q);
                }
            }
        }
        __syncthreads();
#pragma unroll
        for (int ks = 0; ks < 4; ks++) {
            const int k0 = ks * 16;
            uint32_t ah[2][4], al[2][4];
#pragma unroll
            for (int im = 0; im < 2; im++) {
                int arow = wm + im * 16 + (seg & 1) * 8 + i8;
                int acol = k0 + (seg >> 1) * 8;
                LDSM_X4(ah[im], sAh_b + (uint32_t)(arow * LDS + acol) * 2u);
                LDSM_X4(al[im], sAl_b + (uint32_t)(arow * LDS + acol) * 2u);
            }
#pragma unroll
            for (int ip = 0; ip < 4; ip++) {
                int brow = wn + ip * 16 + (seg >> 1) * 8 + i8;
                int bcol = k0 + (seg & 1) * 8;
                uint32_t bh4[4], bl4[4];
                LDSM_X4(bh4, sBh_b + (uint32_t)(brow * LDS + bcol) * 2u);
                LDSM_X4(bl4, sBl_b + (uint32_t)(brow * LDS + bcol) * 2u);
#pragma unroll
                for (int im = 0; im < 2; im++) {
#pragma unroll
                    for (int hf = 0; hf < 2; hf++) {
                        float* c = acc[im][ip * 2 + hf];
                        mma16816(c, ah[im], bh4[2 * hf], bh4[2 * hf + 1]);
                        mma16816(c, al[im], bh4[2 * hf], bh4[2 * hf + 1]);
                        mma16816(c, ah[im], bl4[2 * hf], bl4[2 * hf + 1]);
                    }
                }
            }
        }
    }
#pragma unroll
    for (int im = 0; im < 2; im++) {
#pragma unroll
        for (int jn = 0; jn < 8; jn++) {
            int col = n0 + wn + jn * 8 + tg * 2;
            float b0v = bias[col], b1v = bias[col + 1];
            int row0 = m0 + wm + im * 16 + g;
            float2 v0 = make_float2(acc[im][jn][0] + b0v, acc[im][jn][1] + b1v);
            float2 v1 = make_float2(acc[im][jn][2] + b0v, acc[im][jn][3] + b1v);
            *reinterpret_cast<float2*>(C + (size_t)row0 * Ntot + col) = v0;
            *reinterpret_cast<float2*>(C + (size_t)(row0 + 8) * Ntot + col) = v1;
        }
    }
}

// ============ persistent BiLSTM: cell-per-thread, packed weights ============
// Warp = (cellblock cb = wid%4, rowgroup rg = wid/4). Thread owns cell c = cb*32+lane
// (all 4 gates, packed float4 in weights/tables) for 16 rows. h kept DUPLICATED (f32x2)
// in smem so GEMV multiplicands load directly as u64 broadcasts.
__device__ __forceinline__ float sigm(float x) { return 1.f / (1.f + expf(-x)); }

template <int MODE, int TSTEPS, int NSEQ, int ROWS, int THREADS>
__global__ __launch_bounds__(THREADS) void k_lstm(
    const int* __restrict__ idxmat,
    const float* __restrict__ tab_f, const float* __restrict__ tab_b,
    const float* __restrict__ bias_f, const float* __restrict__ bias_b,
    __nv_bfloat16* __restrict__ Hh, __nv_bfloat16* __restrict__ Hl)
{
    constexpr int NCP = 2048 / THREADS;      // float4 cp.asyncs per thread per 32KB chunk
    extern __shared__ char dsm[];
    u64*   hs2   = reinterpret_cast<u64*>(dsm);          // [ROWS][128] dup f32x2
    float* wbuf  = reinterpret_cast<float*>(hs2 + ROWS * 128);  // [2][8192]
    float* sbias = wbuf + 2 * 8192;                      // [512] permuted
    int* slen = reinterpret_cast<int*>(sbias + G4);
    int* sfe = slen + ROWS; int* soff = sfe + ROWS; int* sun = soff + ROWS;

    const int dir = blockIdx.y;
    const float* __restrict__ tab = dir ? tab_b : tab_f;
    const float* __restrict__ WhT = g_WhT[2 * MODE + dir];
    const int n0 = blockIdx.x * ROWS;
    const int tid = threadIdx.x, lane = tid & 31, wid = tid >> 5;
    const int cb = wid & 3, rg = wid >> 2;
    const int c = cb * 32 + lane, c4 = c * 4;
    const int rowbase = rg * 16;
    const uint32_t wbuf_a = smem_to_u32(wbuf);

    if (MODE == 1) {
        const float* b = dir ? bias_b : bias_f;
        for (int i = tid; i < G4; i += THREADS) sbias[(i & 127) * 4 + (i >> 7)] = b[i];
    }
    for (int i = tid; i < ROWS * 128; i += THREADS) hs2[i] = 0ull;
    if (tid < ROWS) {
        int n = n0 + tid;
        slen[tid] = MODE ? g_p_len[n] : g_tok_len[n];
        if (MODE) { sfe[tid] = g_p_fe[n]; soff[tid] = g_p_off[n]; sun[tid] = g_p_un[n]; }
    }
    for (int i = tid; i < 2048; i += THREADS)
        reinterpret_cast<float4*>(wbuf)[i] = reinterpret_cast<const float4*>(WhT)[i];
    __syncthreads();

    float cst[16];
#pragma unroll
    for (int r = 0; r < 16; r++) cst[r] = 0.f;

    for (int s = 0; s < TSTEPS; s++) {
        u64 acc[16][2];
#pragma unroll
        for (int r = 0; r < 16; r++) { acc[r][0] = 0ull; acc[r][1] = 0ull; }

#pragma unroll
        for (int ch = 0; ch < 8; ch++) {
            {   // prefetch next weight chunk (async, no reg cost)
                const int nxt = (ch + 1) & 7;
                const float4* src = reinterpret_cast<const float4*>(WhT + nxt * 8192);
                uint32_t dsta = wbuf_a + (uint32_t)(((ch + 1) & 1) * 8192) * 4u;
#pragma unroll
                for (int t = 0; t < NCP; t++)
                    CP_ASYNC16(dsta + (uint32_t)(tid + t * THREADS) * 16u, src + tid + t * THREADS);
                CP_COMMIT;
            }
            const float* wc = wbuf + (ch & 1) * 8192;
#pragma unroll
            for (int kp = 0; kp < 8; kp++) {
                ulonglong2 w0 = *reinterpret_cast<const ulonglong2*>(&wc[(kp * 2) * G4 + c4]);
                ulonglong2 w1 = *reinterpret_cast<const ulonglong2*>(&wc[(kp * 2 + 1) * G4 + c4]);
                const int k2 = ch * 16 + kp * 2;
#pragma unroll
                for (int r = 0; r < 16; r++) {
                    ulonglong2 hp = *reinterpret_cast<const ulonglong2*>(&hs2[(rowbase + r) * 128 + k2]);
                    ffma2(acc[r][0], hp.x, w0.x); ffma2(acc[r][1], hp.x, w0.y);
                    ffma2(acc[r][0], hp.y, w1.x); ffma2(acc[r][1], hp.y, w1.y);
                }
            }
            CP_WAIT0;
            __syncthreads();
        }

        // pointwise: thread owns cell c, rows rowbase..rowbase+15
#pragma unroll
        for (int r = 0; r < 16; r++) {
            const int row = rowbase + r, n = n0 + row, len = slen[row];
            const int gi = dir ? min(max(len - 1 - s, 0), TSTEPS - 1) : s;
            float2 if_ = unpack2(acc[r][0]), go_ = unpack2(acc[r][1]);
            float4 gvv;
            if (MODE == 0) {
                int id = idxmat[(size_t)gi * NSEQ + n];
                gvv = *reinterpret_cast<const float4*>(&tab[(size_t)id * G4 + c4]);
            } else {
                int pl = idxmat[(size_t)gi * NSEQ + n];
                bool keep = (gi < sfe[row]) && (pl >= 0) && (pl < sun[row]);
                gvv = *reinterpret_cast<const float4*>(&sbias[c4]);
                if (keep) {
                    int gidx = min(pl + soff[row], NU - 1);
                    float4 t4 = *reinterpret_cast<const float4*>(&tab[(size_t)gidx * G4 + c4]);
                    gvv.x += t4.x; gvv.y += t4.y; gvv.z += t4.z; gvv.w += t4.w;
                }
            }
            float iv = if_.x + gvv.x, fv = if_.y + gvv.y;
            float gg = go_.x + gvv.z, ov = go_.y + gvv.w;
            float cn = sigm(fv) * cst[r] + sigm(iv) * tanhf(gg);
            cst[r] = cn;
            float hv = sigm(ov) * tanhf(cn);
            hs2[row * 128 + c] = dup2(hv);
            __nv_bfloat16 hb = __float2bfloat16(hv);
            __nv_bfloat16 lb = __float2bfloat16(hv - __bfloat162float(hb));
            if (s < len) {
                int wi = dir ? (len - 1 - s) : s;
                size_t base = ((size_t)wi * NSEQ + n) * (2 * HH) + dir * HH + c;
                Hh[base] = hb; Hl[base] = lb;
            } else if (dir == 0) {
                __nv_bfloat16 z = __float2bfloat16(0.f);
                size_t b0 = ((size_t)s * NSEQ + n) * (2 * HH) + c;
                Hh[b0] = z; Hl[b0] = z; Hh[b0 + HH] = z; Hl[b0 + HH] = z;
            }
        }
        __syncthreads();
    }
}

// ============ attention pooling ============
__global__ void k_attn(const float* __restrict__ ln_g, const float* __restrict__ ln_b,
                       const float* __restrict__ attn_w, const float* __restrict__ attn_bp) {
    int gwarp = (blockIdx.x * blockDim.x + threadIdx.x) >> 5;
    int lane = threadIdx.x & 31;
    if (gwarp >= NU) return;
    int n = gwarp, len = g_tok_len[n];
    float gg[4], bb[4], aw[4];
#pragma unroll
    for (int q = 0; q < 4; q++) {
        int e = lane + 32 * q;
        gg[q] = ln_g[e]; bb[q] = ln_b[e]; aw[q] = attn_w[e];
    }
    float ab = attn_bp[0];
    float sc[TT], smax = -1e30f;
#pragma unroll
    for (int t = 0; t < TT; t++) {
        sc[t] = -1e30f;
        if (t < len) {
            float o[4], lsum = 0.f;
#pragma unroll
            for (int q = 0; q < 4; q++) {
                o[q] = g_lin[((size_t)t * NU + n) * EE + lane + 32 * q];
                lsum += o[q];
            }
#pragma unroll
            for (int off = 16; off; off >>= 1) lsum += __shfl_xor_sync(0xffffffffu, lsum, off);
            float mean = lsum * (1.f / 128.f);
            float vs = 0.f;
#pragma unroll
            for (int q = 0; q < 4; q++) { float d = o[q] - mean; vs += d * d; }
#pragma unroll
            for (int off = 16; off; off >>= 1) vs += __shfl_xor_sync(0xffffffffu, vs, off);
            float inv = rsqrtf(vs * (1.f / 128.f) + 1e-5f);
            float ssum = 0.f;
#pragma unroll
            for (int q = 0; q < 4; q++)
                ssum += tanhf((o[q] - mean) * inv * gg[q] + bb[q]) * aw[q];
#pragma unroll
            for (int off = 16; off; off >>= 1) ssum += __shfl_xor_sync(0xffffffffu, ssum, off);
            sc[t] = ssum + ab;
            smax = fmaxf(smax, sc[t]);
        }
    }
    float den = 0.f, wts[TT];
#pragma unroll
    for (int t = 0; t < TT; t++) {
        wts[t] = (t < len) ? expf(sc[t] - smax) : 0.f;
        den += wts[t];
    }
    float invden = 1.f / den;
    float accq[4] = {0.f, 0.f, 0.f, 0.f};
#pragma unroll
    for (int t = 0; t < TT; t++) {
        if (t < len) {
            float wt = wts[t] * invden;
#pragma unroll
            for (int q = 0; q < 4; q++)
                accq[q] += wt * g_lin[((size_t)t * NU + n) * EE + lane + 32 * q];
        }
    }
#pragma unroll
    for (int q = 0; q < 4; q++) {
        __nv_bfloat16 h = __float2bfloat16(accq[q]);
        __nv_bfloat16 l = __float2bfloat16(accq[q] - __bfloat162float(h));
        g_tf_h[(size_t)n * EE + lane + 32 * q] = h;
        g_tf_l[(size_t)n * EE + lane + 32 * q] = l;
    }
}

// ============ host launcher ============
extern "C" void kernel_launch(void* const* d_in, const int* in_sizes, int n_in,
                              void* d_out, int out_size) {
    const int*   units  = (const int*)d_in[0];
    const int*   paths  = (const int*)d_in[1];
    const int*   upd    = (const int*)d_in[2];
    const int*   ppd    = (const int*)d_in[3];
    const float* emb    = (const float*)d_in[4];
    const float* tl_Wif = (const float*)d_in[5];
    const float* tl_Whf = (const float*)d_in[6];
    const float* tl_bf  = (const float*)d_in[7];
    const float* tl_Wib = (const float*)d_in[8];
    const float* tl_Whb = (const float*)d_in[9];
    const float* tl_bb  = (const float*)d_in[10];
    const float* lin_W  = (const float*)d_in[11];
    const float* lin_b  = (const float*)d_in[12];
    const float* ln_g   = (const float*)d_in[13];
    const float* ln_bv  = (const float*)d_in[14];
    const float* attn_w = (const float*)d_in[15];
    const float* attn_b = (const float*)d_in[16];
    const float* pl_Wif = (const float*)d_in[17];
    const float* pl_Whf = (const float*)d_in[18];
    const float* pl_bf  = (const float*)d_in[19];
    const float* pl_Wib = (const float*)d_in[20];
    const float* pl_Whb = (const float*)d_in[21];
    const float* pl_bb  = (const float*)d_in[22];
    const float* ul_W   = (const float*)d_in[23];
    const float* ul_b   = (const float*)d_in[24];
    float* out = (float*)d_out;

    void *pVTf, *pVTb, *pPTf, *pPTb, *pZero, *pLin, *pBp;
    cudaGetSymbolAddress(&pVTf, g_VTf);    cudaGetSymbolAddress(&pVTb, g_VTb);
    cudaGetSymbolAddress(&pPTf, g_PTf);    cudaGetSymbolAddress(&pPTb, g_PTb);
    cudaGetSymbolAddress(&pZero, g_zero);  cudaGetSymbolAddress(&pLin, g_lin);
    cudaGetSymbolAddress(&pBp, g_bperm);
    void *pEh, *pEl, *pHch, *pHcl, *pTfh, *pTfl, *pHph, *pHpl, *pWih, *pWil, *pW2h, *pW2l;
    cudaGetSymbolAddress(&pEh, g_emb_h);   cudaGetSymbolAddress(&pEl, g_emb_l);
    cudaGetSymbolAddress(&pHch, g_Hcat_h); cudaGetSymbolAddress(&pHcl, g_Hcat_l);
    cudaGetSymbolAddress(&pTfh, g_tf_h);   cudaGetSymbolAddress(&pTfl, g_tf_l);
    cudaGetSymbolAddress(&pHph, g_Hp_h);   cudaGetSymbolAddress(&pHpl, g_Hp_l);
    cudaGetSymbolAddress(&pWih, g_Wih);    cudaGetSymbolAddress(&pWil, g_Wil);
    cudaGetSymbolAddress(&pW2h, g_W2h);    cudaGetSymbolAddress(&pW2l, g_W2l);
    __nv_bfloat16* Wih = (__nv_bfloat16*)pWih;  __nv_bfloat16* Wil = (__nv_bfloat16*)pWil;
    __nv_bfloat16* W2h = (__nv_bfloat16*)pW2h;  __nv_bfloat16* W2l = (__nv_bfloat16*)pW2l;
    float* bperm = (float*)pBp;

    const int MM_SMEM = 4 * 128 * 72 * 2;
    const int LS_T = 64 * 128 * 8 + 2 * 8192 * 4 + G4 * 4 + 4 * 64 * 4;   // 134144
    const int LS_P = 16 * 128 * 8 + 2 * 8192 * 4 + G4 * 4 + 4 * 16 * 4;   // 84224
    cudaFuncSetAttribute(k_mm2<128>, cudaFuncAttributeMaxDynamicSharedMemorySize, MM_SMEM);
    cudaFuncSetAttribute(k_mm2<256>, cudaFuncAttributeMaxDynamicSharedMemorySize, MM_SMEM);
    cudaFuncSetAttribute((const void*)k_lstm<0, TT, NU, 64, 512>,
                         cudaFuncAttributeMaxDynamicSharedMemorySize, LS_T + 1024);
    cudaFuncSetAttribute((const void*)k_lstm<1, LPATH, NPATH, 16, 128>,
                         cudaFuncAttributeMaxDynamicSharedMemorySize, LS_P + 1024);

    // 0
    k_tok_len<<<NU / 256, 256>>>(units);
    // 1: pack Wh + permute tl biases
    k_transpose4<<<dim3((G4 * HH + 255) / 256, 5), 256>>>(tl_Whf, tl_Whb, pl_Whf, pl_Whb, tl_bf, tl_bb);
    // 2: hilo emb + tl_Wif(perm) + tl_Wib(perm) + lin_W
    {
        HiloArgs a;
        a.s[0] = emb;    a.h[0] = (__nv_bfloat16*)pEh; a.l[0] = (__nv_bfloat16*)pEl; a.n[0] = VOCAB * EE / 4; a.pm[0] = 0;
        a.s[1] = tl_Wif; a.h[1] = Wih + 0 * G4 * EE;   a.l[1] = Wil + 0 * G4 * EE;   a.n[1] = G4 * EE / 4;    a.pm[1] = 1;
        a.s[2] = tl_Wib; a.h[2] = Wih + 1 * G4 * EE;   a.l[2] = Wil + 1 * G4 * EE;   a.n[2] = G4 * EE / 4;    a.pm[2] = 1;
        a.s[3] = lin_W;  a.h[3] = W2h;                 a.l[3] = W2l;                 a.n[3] = EE * 256 / 4;   a.pm[3] = 0;
        k_hilo_multi<<<dim3((VOCAB * EE / 4 + 255) / 256, 4), 256>>>(a);
    }
    // 3: VT (both dirs, permuted cols + permuted bias)
    k_mm2<128><<<dim3(4, VOCAB / 128, 2), 256, MM_SMEM>>>(
        (const __nv_bfloat16*)pEh, (const __nv_bfloat16*)pEl,
        Wih + 0 * G4 * EE, Wil + 0 * G4 * EE, bperm, (float*)pVTf,
        Wih + 1 * G4 * EE, Wil + 1 * G4 * EE, bperm + G4, (float*)pVTb, G4);
    // 4 (PROFILED): token BiLSTM
    k_lstm<0, TT, NU, 64, 512><<<dim3(NU / 64, 2), 512, LS_T>>>(
        units, (const float*)pVTf, (const float*)pVTb, nullptr, nullptr,
        (__nv_bfloat16*)pHch, (__nv_bfloat16*)pHcl);
    // 5
    k_plen<<<NPATH / 256, 256>>>(paths, upd, ppd);
    // 6: hilo pl_Wif(perm)/pl_Wib(perm)/ul_W
    {
        HiloArgs a;
        a.s[0] = pl_Wif; a.h[0] = Wih + 2 * G4 * EE; a.l[0] = Wil + 2 * G4 * EE; a.n[0] = G4 * EE / 4;  a.pm[0] = 1;
        a.s[1] = pl_Wib; a.h[1] = Wih + 3 * G4 * EE; a.l[1] = Wil + 3 * G4 * EE; a.n[1] = G4 * EE / 4;  a.pm[1] = 1;
        a.s[2] = ul_W;   a.h[2] = W2h + EE * 256;    a.l[2] = W2l + EE * 256;    a.n[2] = EE * 256 / 4; a.pm[2] = 0;
        a.s[3] = ul_W;   a.h[3] = W2h + EE * 256;    a.l[3] = W2l + EE * 256;    a.n[3] = 0;            a.pm[3] = 0;
        k_hilo_multi<<<dim3((G4 * EE / 4 + 255) / 256, 4), 256>>>(a);
    }
    // 7: lin = Hcat @ lin_W^T + lin_b
    k_mm2<256><<<dim3(1, TT * NU / 128, 1), 256, MM_SMEM>>>(
        (const __nv_bfloat16*)pHch, (const __nv_bfloat16*)pHcl,
        W2h, W2l, lin_b, (float*)pLin, W2h, W2l, lin_b, (float*)pLin, EE);
    // 8: attention
    k_attn<<<(NU * 32) / 256, 256>>>(ln_g, ln_bv, attn_w, attn_b);
    // 9: PT (both dirs, permuted cols, zero bias)
    k_mm2<128><<<dim3(4, NU / 128, 2), 256, MM_SMEM>>>(
        (const __nv_bfloat16*)pTfh, (const __nv_bfloat16*)pTfl,
        Wih + 2 * G4 * EE, Wil + 2 * G4 * EE, (const float*)pZero, (float*)pPTf,
        Wih + 3 * G4 * EE, Wil + 3 * G4 * EE, (const float*)pZero, (float*)pPTb, G4);
    // 10: path BiLSTM
    k_lstm<1, LPATH, NPATH, 16, 128><<<dim3(NPATH / 16, 2), 128, LS_P>>>(
        paths, (const float*)pPTf, (const float*)pPTb, pl_bf, pl_bb,
        (__nv_bfloat16*)pHph, (__nv_bfloat16*)pHpl);
    // 11: out = Hp @ ul_W^T + ul_b
    k_mm2<256><<<dim3(1, LPATH * NPATH / 128, 1), 256, MM_SMEM>>>(
        (const __nv_bfloat16*)pHph, (const __nv_bfloat16*)pHpl,
        W2h + EE * 256, W2l + EE * 256, ul_b, out,
        W2h + EE * 256, W2l + EE * 256, ul_b, out, EE);
}

// round 13
// speedup vs baseline: 1.1719x; 1.1719x over previous
#include <cuda_runtime.h>
#include <cuda_bf16.h>
#include <cstdint>

#define TT 16
#define NU 4096
#define EE 128
#define HH 128
#define G4 512
#define LPATH 32
#define NPATH 1024
#define NB 8
#define VOCAB 16384

typedef unsigned long long u64;

__device__ __forceinline__ uint32_t smem_to_u32(const void* p) {
    uint32_t a;
    asm("{ .reg .u64 t; cvta.to.shared.u64 t, %1; cvt.u32.u64 %0, t; }" : "=r"(a) : "l"(p));
    return a;
}
#define LDSM_X4(r, addr) \
    asm volatile("ldmatrix.sync.aligned.m8n8.x4.shared.b16 {%0,%1,%2,%3}, [%4];" \
        : "=r"((r)[0]), "=r"((r)[1]), "=r"((r)[2]), "=r"((r)[3]) : "r"(addr))
__device__ __forceinline__ void mma16816(float* c, const uint32_t* a, uint32_t b0, uint32_t b1) {
    asm volatile("mma.sync.aligned.m16n8k16.row.col.f32.bf16.bf16.f32 "
        "{%0,%1,%2,%3}, {%4,%5,%6,%7}, {%8,%9}, {%0,%1,%2,%3};"
        : "+f"(c[0]), "+f"(c[1]), "+f"(c[2]), "+f"(c[3])
        : "r"(a[0]), "r"(a[1]), "r"(a[2]), "r"(a[3]), "r"(b0), "r"(b1));
}
__device__ __forceinline__ void ffma2(u64& d, u64 a, u64 b) {
    asm("fma.rn.f32x2 %0, %1, %2, %0;" : "+l"(d) : "l"(a), "l"(b));
}
__device__ __forceinline__ u64 dup2(float x) {
    u64 r; asm("mov.b64 %0, {%1, %1};" : "=l"(r) : "f"(x)); return r;
}
__device__ __forceinline__ float2 unpack2(u64 v) {
    float2 f; asm("mov.b64 {%0, %1}, %2;" : "=f"(f.x), "=f"(f.y) : "l"(v)); return f;
}

// fast activations (__expf ~1e-7 rel err; inf-safe)
__device__ __forceinline__ float sigm(float x) { return 1.f / (1.f + __expf(-x)); }
__device__ __forceinline__ float ftanh(float x) {
    float e = __expf(2.f * fabsf(x));
    return copysignf(1.f - 2.f / (e + 1.f), x);
}

// ============ device scratch ============
__device__ int   g_tok_len[NU];
__device__ int   g_p_len[NPATH], g_p_fe[NPATH], g_p_off[NPATH], g_p_un[NPATH];
__device__ float g_VTf[VOCAB * G4], g_VTb[VOCAB * G4];
__device__ float g_PTf[NU * G4],    g_PTb[NU * G4];
__device__ float g_lin[TT * NU * EE];
__device__ float g_WhT[4][HH * G4];
__device__ float g_zero[G4];
__device__ __nv_bfloat16 g_emb_h[VOCAB * EE],  g_emb_l[VOCAB * EE];
__device__ __nv_bfloat16 g_Hcat_h[TT * NU * 2 * HH], g_Hcat_l[TT * NU * 2 * HH];
__device__ __nv_bfloat16 g_tf_h[NU * EE], g_tf_l[NU * EE];
__device__ __nv_bfloat16 g_Hp_h[LPATH * NPATH * 2 * HH], g_Hp_l[LPATH * NPATH * 2 * HH];
__device__ __nv_bfloat16 g_Wih[4][G4 * EE], g_Wil[4][G4 * EE];
__device__ __nv_bfloat16 g_W2h[2][EE * 2 * HH], g_W2l[2][EE * 2 * HH];

// ============ fused setup: y=0 tok_len, y=1..4 transpose Wh, y=5 plen ============
__global__ void k_prep(const int* __restrict__ units,
                       const float* __restrict__ W0, const float* __restrict__ W1,
                       const float* __restrict__ W2, const float* __restrict__ W3,
                       const int* __restrict__ paths,
                       const int* __restrict__ upd, const int* __restrict__ ppd) {
    int seg = blockIdx.y;
    int idx = blockIdx.x * blockDim.x + threadIdx.x;
    if (seg == 0) {
        if (idx >= NU) return;
        int len = TT;
        for (int t = 0; t < TT; t++) if (units[t * NU + idx] == 0) { len = t; break; }
        g_tok_len[idx] = len;
    } else if (seg <= 4) {
        if (idx >= G4 * HH) return;
        const float* W = (seg == 1) ? W0 : (seg == 2) ? W1 : (seg == 3) ? W2 : W3;
        int j = idx >> 7, k = idx & 127;
        g_WhT[seg - 1][k * G4 + j] = W[idx];
    } else {
        int p = idx;
        if (p >= NPATH) return;
        int dd = NB - 1, cum = 0;
        for (int i = 0; i < NB; i++) { int nx = cum + ppd[i]; if (p >= cum && p < nx) { dd = i; break; } cum = nx; }
        int off = 0;
        for (int i = 0; i < dd; i++) off += upd[i];
        int un = upd[dd];
        int fe = LPATH;
        for (int t = 0; t < LPATH; t++) if (paths[t * NPATH + p] == -1) { fe = t; break; }
        int plen = LPATH;
        for (int t = 0; t < LPATH; t++) {
            bool msk;
            if (t >= fe) msk = true;
            else { int v = paths[t * NPATH + p]; msk = (v < 0) || (v > un); }
            if (msk) { plen = t; break; }
        }
        g_p_len[p] = plen; g_p_fe[p] = fe; g_p_off[p] = off; g_p_un[p] = un;
    }
}

__device__ __forceinline__ void hilo_one(const float* src, __nv_bfloat16* hi,
                                         __nv_bfloat16* lo, int i) {
    float4 v = reinterpret_cast<const float4*>(src)[i];
    __nv_bfloat16 h0 = __float2bfloat16(v.x), h1 = __float2bfloat16(v.y);
    __nv_bfloat16 h2 = __float2bfloat16(v.z), h3 = __float2bfloat16(v.w);
    __nv_bfloat162* H = reinterpret_cast<__nv_bfloat162*>(hi);
    __nv_bfloat162* L = reinterpret_cast<__nv_bfloat162*>(lo);
    H[2 * i] = __nv_bfloat162(h0, h1); H[2 * i + 1] = __nv_bfloat162(h2, h3);
    L[2 * i] = __nv_bfloat162(__float2bfloat16(v.x - __bfloat162float(h0)),
                              __float2bfloat16(v.y - __bfloat162float(h1)));
    L[2 * i + 1] = __nv_bfloat162(__float2bfloat16(v.z - __bfloat162float(h2)),
                                  __float2bfloat16(v.w - __bfloat162float(h3)));
}
struct HiloArgs { const float* s[4]; __nv_bfloat16* h[4]; __nv_bfloat16* l[4]; int n[4]; };
__global__ void k_hilo_multi(HiloArgs a) {
    int seg = blockIdx.y;
    int i = blockIdx.x * blockDim.x + threadIdx.x;
    if (i < a.n[seg]) hilo_one(a.s[seg], a.h[seg], a.l[seg], i);
}

// ============ warp-MMA split-bf16 GEMM (dual via gridDim.z; R10, passing) ============
template <int K>
__global__ __launch_bounds__(256) void k_mm2(
    const __nv_bfloat16* __restrict__ Ah, const __nv_bfloat16* __restrict__ Al,
    const __nv_bfloat16* __restrict__ Bh0, const __nv_bfloat16* __restrict__ Bl0,
    const float* __restrict__ bias0, float* __restrict__ C0,
    const __nv_bfloat16* __restrict__ Bh1, const __nv_bfloat16* __restrict__ Bl1,
    const float* __restrict__ bias1, float* __restrict__ C1, int Ntot)
{
    const __nv_bfloat16* __restrict__ Bh = blockIdx.z ? Bh1 : Bh0;
    const __nv_bfloat16* __restrict__ Bl = blockIdx.z ? Bl1 : Bl0;
    const float* __restrict__ bias = blockIdx.z ? bias1 : bias0;
    float* __restrict__ C = blockIdx.z ? C1 : C0;

    constexpr int LDS = 72;
    extern __shared__ __nv_bfloat16 sm[];
    __nv_bfloat16* sAh = sm;
    __nv_bfloat16* sAl = sAh + 128 * LDS;
    __nv_bfloat16* sBh = sAl + 128 * LDS;
    __nv_bfloat16* sBl = sBh + 128 * LDS;

    const int tid = threadIdx.x, lane = tid & 31, wid = tid >> 5;
    const int m0 = blockIdx.y * 128, n0 = blockIdx.x * 128;
    const int wm = (wid & 3) * 32, wn = (wid >> 2) * 64;
    const int g = lane >> 2, tg = lane & 3;
    const int seg = lane >> 3, i8 = lane & 7;
    const uint32_t sAh_b = smem_to_u32(sAh), sAl_b = smem_to_u32(sAl);
    const uint32_t sBh_b = smem_to_u32(sBh), sBl_b = smem_to_u32(sBl);

    float acc[2][8][4];
#pragma unroll
    for (int im = 0; im < 2; im++)
#pragma unroll
        for (int jn = 0; jn < 8; jn++)
#pragma unroll
            for (int q = 0; q < 4; q++) acc[im][jn][q] = 0.f;

    for (int kc = 0; kc < K; kc += 64) {
        if (kc) __syncthreads();
        {
            const __nv_bfloat16* srcs[4] = {Ah, Al, Bh, Bl};
            __nv_bfloat16* dsts[4] = {sAh, sAl, sBh, sBl};
            const int r0s[4] = {m0, m0, n0, n0};
#pragma unroll
            for (int t = 0; t < 4; t++) {
                for (int v = tid; v < 1024; v += 256) {
                    int row = v >> 3, q = (v & 7) * 8;
                    *reinterpret_cast<uint4*>(dsts[t] + row * LDS + q) =
                        *reinterpret_cast<const uint4*>(srcs[t] + (size_t)(r0s[t] + row) * K + kc + q);
                }
            }
        }
        __syncthreads();
#pragma unroll
        for (int ks = 0; ks < 4; ks++) {
            const int k0 = ks * 16;
            uint32_t ah[2][4], al[2][4];
#pragma unroll
            for (int im = 0; im < 2; im++) {
                int arow = wm + im * 16 + (seg & 1) * 8 + i8;
                int acol = k0 + (seg >> 1) * 8;
                LDSM_X4(ah[im], sAh_b + (uint32_t)(arow * LDS + acol) * 2u);
                LDSM_X4(al[im], sAl_b + (uint32_t)(arow * LDS + acol) * 2u);
            }
#pragma unroll
            for (int ip = 0; ip < 4; ip++) {
                int brow = wn + ip * 16 + (seg >> 1) * 8 + i8;
                int bcol = k0 + (seg & 1) * 8;
                uint32_t bh4[4], bl4[4];
                LDSM_X4(bh4, sBh_b + (uint32_t)(brow * LDS + bcol) * 2u);
                LDSM_X4(bl4, sBl_b + (uint32_t)(brow * LDS + bcol) * 2u);
#pragma unroll
                for (int im = 0; im < 2; im++) {
#pragma unroll
                    for (int hf = 0; hf < 2; hf++) {
                        float* c = acc[im][ip * 2 + hf];
                        mma16816(c, ah[im], bh4[2 * hf], bh4[2 * hf + 1]);
                        mma16816(c, al[im], bh4[2 * hf], bh4[2 * hf + 1]);
                        mma16816(c, ah[im], bl4[2 * hf], bl4[2 * hf + 1]);
                    }
                }
            }
        }
    }
#pragma unroll
    for (int im = 0; im < 2; im++) {
#pragma unroll
        for (int jn = 0; jn < 8; jn++) {
            int col = n0 + wn + jn * 8 + tg * 2;
            float b0v = bias[col], b1v = bias[col + 1];
            int row0 = m0 + wm + im * 16 + g;
            float2 v0 = make_float2(acc[im][jn][0] + b0v, acc[im][jn][1] + b1v);
            float2 v1 = make_float2(acc[im][jn][2] + b0v, acc[im][jn][3] + b1v);
            *reinterpret_cast<float2*>(C + (size_t)row0 * Ntot + col) = v0;
            *reinterpret_cast<float2*>(C + (size_t)(row0 + 8) * Ntot + col) = v1;
        }
    }
}

// ============ persistent BiLSTM (R7 structure, fast activations) ============
template <int MODE, int TSTEPS, int NSEQ, int ROWS, int THREADS>
__global__ __launch_bounds__(THREADS) void k_lstm(
    const int* __restrict__ idxmat,
    const float* __restrict__ tab_f, const float* __restrict__ tab_b,
    const float* __restrict__ bias_f, const float* __restrict__ bias_b,
    __nv_bfloat16* __restrict__ Hh, __nv_bfloat16* __restrict__ Hl)
{
    constexpr int NW = THREADS / 32, RPT = ROWS / NW;
    constexpr int N4 = 2048 / THREADS;
    extern __shared__ char dsm[];
    float* hs    = reinterpret_cast<float*>(dsm);       // [ROWS][HH]
    float* wst   = hs + ROWS * HH;                      // [2][16*G4]
    float* sbias = wst + 2 * 16 * G4;                   // [G4]
    int* slen = reinterpret_cast<int*>(sbias + G4);
    int* sfe = slen + ROWS; int* soff = sfe + ROWS; int* sun = soff + ROWS;

    const int dir = blockIdx.y;
    const float* __restrict__ tab = dir ? tab_b : tab_f;
    const float* __restrict__ WhT = g_WhT[2 * MODE + dir];
    const int n0 = blockIdx.x * ROWS;
    const int tid = threadIdx.x, jt = tid & 31, rt = tid >> 5;
    const int e0 = jt * 4, r0 = rt * RPT;

    if (MODE == 1) {
        const float* b = dir ? bias_b : bias_f;
        for (int i = tid; i < G4; i += THREADS) sbias[i] = b[i];
    }
    float c[RPT][4];
#pragma unroll
    for (int r = 0; r < RPT; r++) {
#pragma unroll
        for (int u = 0; u < 4; u++) c[r][u] = 0.f;
        *reinterpret_cast<float4*>(&hs[(r0 + r) * HH + e0]) = make_float4(0.f, 0.f, 0.f, 0.f);
    }
    if (tid < ROWS) {
        int n = n0 + tid;
        slen[tid] = MODE ? g_p_len[n] : g_tok_len[n];
        if (MODE) { sfe[tid] = g_p_fe[n]; soff[tid] = g_p_off[n]; sun[tid] = g_p_un[n]; }
    }
#pragma unroll
    for (int t = 0; t < N4; t++) {
        int i = tid + t * THREADS;
        reinterpret_cast<float4*>(wst)[i] = reinterpret_cast<const float4*>(WhT)[i];
    }
    __syncthreads();

    for (int s = 0; s < TSTEPS; s++) {
        u64 acc64[RPT][8];
#pragma unroll
        for (int r = 0; r < RPT; r++)
#pragma unroll
            for (int j = 0; j < 8; j++) acc64[r][j] = 0ull;

#pragma unroll
        for (int ch = 0; ch < 8; ch++) {
            const float* wcur = wst + (ch & 1) * (16 * G4);
            float* wnxt = wst + ((ch + 1) & 1) * (16 * G4);
            const int nxt = (ch + 1) & 7;
            float4 pre[N4];
#pragma unroll
            for (int t = 0; t < N4; t++)
                pre[t] = reinterpret_cast<const float4*>(WhT)[nxt * 2048 + tid + t * THREADS];

#pragma unroll
            for (int kk = 0; kk < 16; kk++) {
                ulonglong2 wA = *reinterpret_cast<const ulonglong2*>(&wcur[kk * G4 + e0]);
                ulonglong2 wB = *reinterpret_cast<const ulonglong2*>(&wcur[kk * G4 + 128 + e0]);
                ulonglong2 wC = *reinterpret_cast<const ulonglong2*>(&wcur[kk * G4 + 256 + e0]);
                ulonglong2 wD = *reinterpret_cast<const ulonglong2*>(&wcur[kk * G4 + 384 + e0]);
#pragma unroll
                for (int r = 0; r < RPT; r++) {
                    u64 h2 = dup2(hs[(r0 + r) * HH + ch * 16 + kk]);
                    ffma2(acc64[r][0], h2, wA.x); ffma2(acc64[r][1], h2, wA.y);
                    ffma2(acc64[r][2], h2, wB.x); ffma2(acc64[r][3], h2, wB.y);
                    ffma2(acc64[r][4], h2, wC.x); ffma2(acc64[r][5], h2, wC.y);
                    ffma2(acc64[r][6], h2, wD.x); ffma2(acc64[r][7], h2, wD.y);
                }
            }
#pragma unroll
            for (int t = 0; t < N4; t++)
                reinterpret_cast<float4*>(wnxt)[tid + t * THREADS] = pre[t];
            __syncthreads();
        }

        float hnew[RPT][4];
#pragma unroll
        for (int r = 0; r < RPT; r++) {
            float a16[16];
#pragma unroll
            for (int j = 0; j < 8; j++) {
                float2 v = unpack2(acc64[r][j]);
                a16[j * 2] = v.x; a16[j * 2 + 1] = v.y;
            }
            int rr = r0 + r, n = n0 + rr, len = slen[rr];
            int gi = dir ? min(max(len - 1 - s, 0), TSTEPS - 1) : s;
            float gv[16];
            if (MODE == 0) {
                int id = idxmat[(size_t)gi * NSEQ + n];
                const float* grow = tab + (size_t)id * G4;
                float4 a0 = *reinterpret_cast<const float4*>(&grow[e0]);
                float4 a1 = *reinterpret_cast<const float4*>(&grow[128 + e0]);
                float4 a2 = *reinterpret_cast<const float4*>(&grow[256 + e0]);
                float4 a3 = *reinterpret_cast<const float4*>(&grow[384 + e0]);
                gv[0]=a0.x; gv[1]=a0.y; gv[2]=a0.z; gv[3]=a0.w;
                gv[4]=a1.x; gv[5]=a1.y; gv[6]=a1.z; gv[7]=a1.w;
                gv[8]=a2.x; gv[9]=a2.y; gv[10]=a2.z; gv[11]=a2.w;
                gv[12]=a3.x; gv[13]=a3.y; gv[14]=a3.z; gv[15]=a3.w;
            } else {
                int pl = idxmat[(size_t)gi * NSEQ + n];
                bool keep = (gi < sfe[rr]) && (pl >= 0) && (pl < sun[rr]);
                float4 b0 = *reinterpret_cast<const float4*>(&sbias[e0]);
                float4 b1 = *reinterpret_cast<const float4*>(&sbias[128 + e0]);
                float4 b2 = *reinterpret_cast<const float4*>(&sbias[256 + e0]);
                float4 b3 = *reinterpret_cast<const float4*>(&sbias[384 + e0]);
                gv[0]=b0.x; gv[1]=b0.y; gv[2]=b0.z; gv[3]=b0.w;
                gv[4]=b1.x; gv[5]=b1.y; gv[6]=b1.z; gv[7]=b1.w;
                gv[8]=b2.x; gv[9]=b2.y; gv[10]=b2.z; gv[11]=b2.w;
                gv[12]=b3.x; gv[13]=b3.y; gv[14]=b3.z; gv[15]=b3.w;
                if (keep) {
                    int gidx = min(pl + soff[rr], NU - 1);
                    const float* grow = tab + (size_t)gidx * G4;
                    float4 t0 = *reinterpret_cast<const float4*>(&grow[e0]);
                    float4 t1 = *reinterpret_cast<const float4*>(&grow[128 + e0]);
                    float4 t2 = *reinterpret_cast<const float4*>(&grow[256 + e0]);
                    float4 t3 = *reinterpret_cast<const float4*>(&grow[384 + e0]);
                    gv[0]+=t0.x; gv[1]+=t0.y; gv[2]+=t0.z; gv[3]+=t0.w;
                    gv[4]+=t1.x; gv[5]+=t1.y; gv[6]+=t1.z; gv[7]+=t1.w;
                    gv[8]+=t2.x; gv[9]+=t2.y; gv[10]+=t2.z; gv[11]+=t2.w;
                    gv[12]+=t3.x; gv[13]+=t3.y; gv[14]+=t3.z; gv[15]+=t3.w;
                }
            }
#pragma unroll
            for (int u = 0; u < 4; u++) {
                float iv = a16[u]      + gv[u];
                float fv = a16[4 + u]  + gv[4 + u];
                float gg = a16[8 + u]  + gv[8 + u];
                float ov = a16[12 + u] + gv[12 + u];
                float cn = sigm(fv) * c[r][u] + sigm(iv) * ftanh(gg);
                c[r][u] = cn;
                hnew[r][u] = sigm(ov) * ftanh(cn);
            }
            if (s < len) {
                int wi = dir ? (len - 1 - s) : s;
                size_t base = ((size_t)wi * NSEQ + n) * (2 * HH) + dir * HH + e0;
                __nv_bfloat16 hb[4], lb[4];
#pragma unroll
                for (int u = 0; u < 4; u++) {
                    hb[u] = __float2bfloat16(hnew[r][u]);
                    lb[u] = __float2bfloat16(hnew[r][u] - __bfloat162float(hb[u]));
                }
                *reinterpret_cast<uint2*>(Hh + base) = *reinterpret_cast<uint2*>(hb);
                *reinterpret_cast<uint2*>(Hl + base) = *reinterpret_cast<uint2*>(lb);
            } else if (dir == 0) {
                uint2 z = make_uint2(0u, 0u);
                size_t b0 = ((size_t)s * NSEQ + n) * (2 * HH) + e0;
                *reinterpret_cast<uint2*>(Hh + b0) = z;
                *reinterpret_cast<uint2*>(Hl + b0) = z;
                *reinterpret_cast<uint2*>(Hh + b0 + HH) = z;
                *reinterpret_cast<uint2*>(Hl + b0 + HH) = z;
            }
        }
        __syncthreads();
#pragma unroll
        for (int r = 0; r < RPT; r++)
            *reinterpret_cast<float4*>(&hs[(r0 + r) * HH + e0]) =
                make_float4(hnew[r][0], hnew[r][1], hnew[r][2], hnew[r][3]);
        __syncthreads();
    }
}

// ============ attention pooling ============
__global__ void k_attn(const float* __restrict__ ln_g, const float* __restrict__ ln_b,
                       const float* __restrict__ attn_w, const float* __restrict__ attn_bp) {
    int gwarp = (blockIdx.x * blockDim.x + threadIdx.x) >> 5;
    int lane = threadIdx.x & 31;
    if (gwarp >= NU) return;
    int n = gwarp, len = g_tok_len[n];
    float gg[4], bb[4], aw[4];
#pragma unroll
    for (int q = 0; q < 4; q++) {
        int e = lane + 32 * q;
        gg[q] = ln_g[e]; bb[q] = ln_b[e]; aw[q] = attn_w[e];
    }
    float ab = attn_bp[0];
    float sc[TT], smax = -1e30f;
#pragma unroll
    for (int t = 0; t < TT; t++) {
        sc[t] = -1e30f;
        if (t < len) {
            float o[4], lsum = 0.f;
#pragma unroll
            for (int q = 0; q < 4; q++) {
                o[q] = g_lin[((size_t)t * NU + n) * EE + lane + 32 * q];
                lsum += o[q];
            }
#pragma unroll
            for (int off = 16; off; off >>= 1) lsum += __shfl_xor_sync(0xffffffffu, lsum, off);
            float mean = lsum * (1.f / 128.f);
            float vs = 0.f;
#pragma unroll
            for (int q = 0; q < 4; q++) { float d = o[q] - mean; vs += d * d; }
#pragma unroll
            for (int off = 16; off; off >>= 1) vs += __shfl_xor_sync(0xffffffffu, vs, off);
            float inv = rsqrtf(vs * (1.f / 128.f) + 1e-5f);
            float ssum = 0.f;
#pragma unroll
            for (int q = 0; q < 4; q++)
                ssum += ftanh((o[q] - mean) * inv * gg[q] + bb[q]) * aw[q];
#pragma unroll
            for (int off = 16; off; off >>= 1) ssum += __shfl_xor_sync(0xffffffffu, ssum, off);
            sc[t] = ssum + ab;
            smax = fmaxf(smax, sc[t]);
        }
    }
    float den = 0.f, wts[TT];
#pragma unroll
    for (int t = 0; t < TT; t++) {
        wts[t] = (t < len) ? __expf(sc[t] - smax) : 0.f;
        den += wts[t];
    }
    float invden = 1.f / den;
    float accq[4] = {0.f, 0.f, 0.f, 0.f};
#pragma unroll
    for (int t = 0; t < TT; t++) {
        if (t < len) {
            float wt = wts[t] * invden;
#pragma unroll
            for (int q = 0; q < 4; q++)
                accq[q] += wt * g_lin[((size_t)t * NU + n) * EE + lane + 32 * q];
        }
    }
#pragma unroll
    for (int q = 0; q < 4; q++) {
        __nv_bfloat16 h = __float2bfloat16(accq[q]);
        __nv_bfloat16 l = __float2bfloat16(accq[q] - __bfloat162float(h));
        g_tf_h[(size_t)n * EE + lane + 32 * q] = h;
        g_tf_l[(size_t)n * EE + lane + 32 * q] = l;
    }
}

// ============ host launcher ============
extern "C" void kernel_launch(void* const* d_in, const int* in_sizes, int n_in,
                              void* d_out, int out_size) {
    const int*   units  = (const int*)d_in[0];
    const int*   paths  = (const int*)d_in[1];
    const int*   upd    = (const int*)d_in[2];
    const int*   ppd    = (const int*)d_in[3];
    const float* emb    = (const float*)d_in[4];
    const float* tl_Wif = (const float*)d_in[5];
    const float* tl_Whf = (const float*)d_in[6];
    const float* tl_bf  = (const float*)d_in[7];
    const float* tl_Wib = (const float*)d_in[8];
    const float* tl_Whb = (const float*)d_in[9];
    const float* tl_bb  = (const float*)d_in[10];
    const float* lin_W  = (const float*)d_in[11];
    const float* lin_b  = (const float*)d_in[12];
    const float* ln_g   = (const float*)d_in[13];
    const float* ln_bv  = (const float*)d_in[14];
    const float* attn_w = (const float*)d_in[15];
    const float* attn_b = (const float*)d_in[16];
    const float* pl_Wif = (const float*)d_in[17];
    const float* pl_Whf = (const float*)d_in[18];
    const float* pl_bf  = (const float*)d_in[19];
    const float* pl_Wib = (const float*)d_in[20];
    const float* pl_Whb = (const float*)d_in[21];
    const float* pl_bb  = (const float*)d_in[22];
    const float* ul_W   = (const float*)d_in[23];
    const float* ul_b   = (const float*)d_in[24];
    float* out = (float*)d_out;

    void *pVTf, *pVTb, *pPTf, *pPTb, *pZero, *pLin;
    cudaGetSymbolAddress(&pVTf, g_VTf);    cudaGetSymbolAddress(&pVTb, g_VTb);
    cudaGetSymbolAddress(&pPTf, g_PTf);    cudaGetSymbolAddress(&pPTb, g_PTb);
    cudaGetSymbolAddress(&pZero, g_zero);  cudaGetSymbolAddress(&pLin, g_lin);
    void *pEh, *pEl, *pHch, *pHcl, *pTfh, *pTfl, *pHph, *pHpl, *pWih, *pWil, *pW2h, *pW2l;
    cudaGetSymbolAddress(&pEh, g_emb_h);   cudaGetSymbolAddress(&pEl, g_emb_l);
    cudaGetSymbolAddress(&pHch, g_Hcat_h); cudaGetSymbolAddress(&pHcl, g_Hcat_l);
    cudaGetSymbolAddress(&pTfh, g_tf_h);   cudaGetSymbolAddress(&pTfl, g_tf_l);
    cudaGetSymbolAddress(&pHph, g_Hp_h);   cudaGetSymbolAddress(&pHpl, g_Hp_l);
    cudaGetSymbolAddress(&pWih, g_Wih);    cudaGetSymbolAddress(&pWil, g_Wil);
    cudaGetSymbolAddress(&pW2h, g_W2h);    cudaGetSymbolAddress(&pW2l, g_W2l);
    __nv_bfloat16* Wih = (__nv_bfloat16*)pWih;  __nv_bfloat16* Wil = (__nv_bfloat16*)pWil;
    __nv_bfloat16* W2h = (__nv_bfloat16*)pW2h;  __nv_bfloat16* W2l = (__nv_bfloat16*)pW2l;

    const int MM_SMEM = 4 * 128 * 72 * 2;
    const int LS_T = 64 * HH * 4 + 2 * 16 * G4 * 4 + G4 * 4 + 4 * 64 * 4;   // 101376
    const int LS_P = 16 * HH * 4 + 2 * 16 * G4 * 4 + G4 * 4 + 4 * 16 * 4;   // 76032
    cudaFuncSetAttribute(k_mm2<128>, cudaFuncAttributeMaxDynamicSharedMemorySize, MM_SMEM);
    cudaFuncSetAttribute(k_mm2<256>, cudaFuncAttributeMaxDynamicSharedMemorySize, MM_SMEM);
    cudaFuncSetAttribute((const void*)k_lstm<0, TT, NU, 64, 512>,
                         cudaFuncAttributeMaxDynamicSharedMemorySize, LS_T + 1024);
    cudaFuncSetAttribute((const void*)k_lstm<1, LPATH, NPATH, 16, 256>,
                         cudaFuncAttributeMaxDynamicSharedMemorySize, LS_P + 1024);

    // launch 0: fused setup (tok_len + Wh transposes + plen)
    k_prep<<<dim3(256, 6), 256>>>(units, tl_Whf, tl_Whb, pl_Whf, pl_Whb, paths, upd, ppd);
    // launch 1: hilo emb + tl_Wif + tl_Wib + lin_W
    {
        HiloArgs a;
        a.s[0] = emb;    a.h[0] = (__nv_bfloat16*)pEh; a.l[0] = (__nv_bfloat16*)pEl; a.n[0] = VOCAB * EE / 4;
        a.s[1] = tl_Wif; a.h[1] = Wih + 0 * G4 * EE;   a.l[1] = Wil + 0 * G4 * EE;   a.n[1] = G4 * EE / 4;
        a.s[2] = tl_Wib; a.h[2] = Wih + 1 * G4 * EE;   a.l[2] = Wil + 1 * G4 * EE;   a.n[2] = G4 * EE / 4;
        a.s[3] = lin_W;  a.h[3] = W2h;                 a.l[3] = W2l;                 a.n[3] = EE * 256 / 4;
        k_hilo_multi<<<dim3((VOCAB * EE / 4 + 255) / 256, 4), 256>>>(a);
    }
    // launch 2: VT = emb @ Wi^T + b (both dirs)
    k_mm2<128><<<dim3(4, VOCAB / 128, 2), 256, MM_SMEM>>>(
        (const __nv_bfloat16*)pEh, (const __nv_bfloat16*)pEl,
        Wih + 0 * G4 * EE, Wil + 0 * G4 * EE, tl_bf, (float*)pVTf,
        Wih + 1 * G4 * EE, Wil + 1 * G4 * EE, tl_bb, (float*)pVTb, G4);
    // launch 3 (PROFILE TARGET): token BiLSTM
    k_lstm<0, TT, NU, 64, 512><<<dim3(NU / 64, 2), 512, LS_T>>>(
        units, (const float*)pVTf, (const float*)pVTb, nullptr, nullptr,
        (__nv_bfloat16*)pHch, (__nv_bfloat16*)pHcl);
    // launch 4: hilo pl_Wif + pl_Wib + ul_W
    {
        HiloArgs a;
        a.s[0] = pl_Wif; a.h[0] = Wih + 2 * G4 * EE; a.l[0] = Wil + 2 * G4 * EE; a.n[0] = G4 * EE / 4;
        a.s[1] = pl_Wib; a.h[1] = Wih + 3 * G4 * EE; a.l[1] = Wil + 3 * G4 * EE; a.n[1] = G4 * EE / 4;
        a.s[2] = ul_W;   a.h[2] = W2h + EE * 256;    a.l[2] = W2l + EE * 256;    a.n[2] = EE * 256 / 4;
        a.s[3] = ul_W;   a.h[3] = W2h + EE * 256;    a.l[3] = W2l + EE * 256;    a.n[3] = 0;
        k_hilo_multi<<<dim3((G4 * EE / 4 + 255) / 256, 4), 256>>>(a);
    }
    // launch 5: lin = Hcat @ lin_W^T + lin_b
    k_mm2<256><<<dim3(1, TT * NU / 128, 1), 256, MM_SMEM>>>(
        (const __nv_bfloat16*)pHch, (const __nv_bfloat16*)pHcl,
        W2h, W2l, lin_b, (float*)pLin, W2h, W2l, lin_b, (float*)pLin, EE);
    // launch 6: attention -> tf hi/lo
    k_attn<<<(NU * 32) / 256, 256>>>(ln_g, ln_bv, attn_w, attn_b);
    // launch 7: PT (both dirs)
    k_mm2<128><<<dim3(4, NU / 128, 2), 256, MM_SMEM>>>(
        (const __nv_bfloat16*)pTfh, (const __nv_bfloat16*)pTfl,
        Wih + 2 * G4 * EE, Wil + 2 * G4 * EE, (const float*)pZero, (float*)pPTf,
        Wih + 3 * G4 * EE, Wil + 3 * G4 * EE, (const float*)pZero, (float*)pPTb, G4);
    // launch 8: path BiLSTM
    k_lstm<1, LPATH, NPATH, 16, 256><<<dim3(NPATH / 16, 2), 256, LS_P>>>(
        paths, (const float*)pPTf, (const float*)pPTb, pl_bf, pl_bb,
        (__nv_bfloat16*)pHph, (__nv_bfloat16*)pHpl);
    // launch 9: out = Hp @ ul_W^T + ul_b
    k_mm2<256><<<dim3(1, LPATH * NPATH / 128, 1), 256, MM_SMEM>>>(
        (const __nv_bfloat16*)pHph, (const __nv_bfloat16*)pHpl,
        W2h + EE * 256, W2l + EE * 256, ul_b, out,
        W2h + EE * 256, W2l + EE * 256, ul_b, out, EE);
}

// round 14
// speedup vs baseline: 1.4702x; 1.2545x over previous
#include <cuda_runtime.h>
#include <cuda_bf16.h>
#include <cstdint>

#define TT 16
#define NU 4096
#define EE 128
#define HH 128
#define G4 512
#define LPATH 32
#define NPATH 1024
#define NB 8
#define VOCAB 16384

typedef unsigned long long u64;

__device__ __forceinline__ uint32_t smem_to_u32(const void* p) {
    uint32_t a;
    asm("{ .reg .u64 t; cvta.to.shared.u64 t, %1; cvt.u32.u64 %0, t; }" : "=r"(a) : "l"(p));
    return a;
}
#define LDSM_X4(r, addr) \
    asm volatile("ldmatrix.sync.aligned.m8n8.x4.shared.b16 {%0,%1,%2,%3}, [%4];" \
        : "=r"((r)[0]), "=r"((r)[1]), "=r"((r)[2]), "=r"((r)[3]) : "r"(addr))
__device__ __forceinline__ void mma16816(float* c, const uint32_t* a, uint32_t b0, uint32_t b1) {
    asm volatile("mma.sync.aligned.m16n8k16.row.col.f32.bf16.bf16.f32 "
        "{%0,%1,%2,%3}, {%4,%5,%6,%7}, {%8,%9}, {%0,%1,%2,%3};"
        : "+f"(c[0]), "+f"(c[1]), "+f"(c[2]), "+f"(c[3])
        : "r"(a[0]), "r"(a[1]), "r"(a[2]), "r"(a[3]), "r"(b0), "r"(b1));
}
__device__ __forceinline__ void ffma2(u64& d, u64 a, u64 b) {
    asm("fma.rn.f32x2 %0, %1, %2, %0;" : "+l"(d) : "l"(a), "l"(b));
}
__device__ __forceinline__ u64 dup2(float x) {
    u64 r; asm("mov.b64 %0, {%1, %1};" : "=l"(r) : "f"(x)); return r;
}
__device__ __forceinline__ float2 unpack2(u64 v) {
    float2 f; asm("mov.b64 {%0, %1}, %2;" : "=f"(f.x), "=f"(f.y) : "l"(v)); return f;
}
#define CP_ASYNC16(dst_u32, src_ptr) \
    asm volatile("cp.async.cg.shared.global [%0], [%1], 16;" :: "r"(dst_u32), "l"(src_ptr))
#define CP_COMMIT asm volatile("cp.async.commit_group;" ::: "memory")
#define CP_WAIT0  asm volatile("cp.async.wait_group 0;" ::: "memory")

// fast activations
__device__ __forceinline__ float sigm(float x) {
    return __fdividef(1.f, 1.f + __expf(-x));
}
__device__ __forceinline__ float ftanh(float x) {
    float e = __expf(2.f * fabsf(x));
    return copysignf(1.f - __fdividef(2.f, e + 1.f), x);
}

// ============ device scratch ============
__device__ int   g_tok_len[NU];
__device__ int   g_p_len[NPATH], g_p_fe[NPATH], g_p_off[NPATH], g_p_un[NPATH];
__device__ float g_VTf[VOCAB * G4], g_VTb[VOCAB * G4];
__device__ float g_PTf[NU * G4],    g_PTb[NU * G4];
__device__ float g_lin[TT * NU * EE];
__device__ float g_WhT[4][HH * G4];
__device__ float g_zero[G4];
__device__ __nv_bfloat16 g_emb_h[VOCAB * EE],  g_emb_l[VOCAB * EE];
__device__ __nv_bfloat16 g_Hcat_h[TT * NU * 2 * HH], g_Hcat_l[TT * NU * 2 * HH];
__device__ __nv_bfloat16 g_tf_h[NU * EE], g_tf_l[NU * EE];
__device__ __nv_bfloat16 g_Hp_h[LPATH * NPATH * 2 * HH], g_Hp_l[LPATH * NPATH * 2 * HH];
__device__ __nv_bfloat16 g_Wih[4][G4 * EE], g_Wil[4][G4 * EE];
__device__ __nv_bfloat16 g_W2h[2][EE * 2 * HH], g_W2l[2][EE * 2 * HH];

// ============ fused setup ============
__global__ void k_prep(const int* __restrict__ units,
                       const float* __restrict__ W0, const float* __restrict__ W1,
                       const float* __restrict__ W2, const float* __restrict__ W3,
                       const int* __restrict__ paths,
                       const int* __restrict__ upd, const int* __restrict__ ppd) {
    int seg = blockIdx.y;
    int idx = blockIdx.x * blockDim.x + threadIdx.x;
    if (seg == 0) {
        if (idx >= NU) return;
        int len = TT;
        for (int t = 0; t < TT; t++) if (units[t * NU + idx] == 0) { len = t; break; }
        g_tok_len[idx] = len;
    } else if (seg <= 4) {
        if (idx >= G4 * HH) return;
        const float* W = (seg == 1) ? W0 : (seg == 2) ? W1 : (seg == 3) ? W2 : W3;
        int j = idx >> 7, k = idx & 127;
        g_WhT[seg - 1][k * G4 + j] = W[idx];
    } else {
        int p = idx;
        if (p >= NPATH) return;
        int dd = NB - 1, cum = 0;
        for (int i = 0; i < NB; i++) { int nx = cum + ppd[i]; if (p >= cum && p < nx) { dd = i; break; } cum = nx; }
        int off = 0;
        for (int i = 0; i < dd; i++) off += upd[i];
        int un = upd[dd];
        int fe = LPATH;
        for (int t = 0; t < LPATH; t++) if (paths[t * NPATH + p] == -1) { fe = t; break; }
        int plen = LPATH;
        for (int t = 0; t < LPATH; t++) {
            bool msk;
            if (t >= fe) msk = true;
            else { int v = paths[t * NPATH + p]; msk = (v < 0) || (v > un); }
            if (msk) { plen = t; break; }
        }
        g_p_len[p] = plen; g_p_fe[p] = fe; g_p_off[p] = off; g_p_un[p] = un;
    }
}

__device__ __forceinline__ void hilo_one(const float* src, __nv_bfloat16* hi,
                                         __nv_bfloat16* lo, int i) {
    float4 v = reinterpret_cast<const float4*>(src)[i];
    __nv_bfloat16 h0 = __float2bfloat16(v.x), h1 = __float2bfloat16(v.y);
    __nv_bfloat16 h2 = __float2bfloat16(v.z), h3 = __float2bfloat16(v.w);
    __nv_bfloat162* H = reinterpret_cast<__nv_bfloat162*>(hi);
    __nv_bfloat162* L = reinterpret_cast<__nv_bfloat162*>(lo);
    H[2 * i] = __nv_bfloat162(h0, h1); H[2 * i + 1] = __nv_bfloat162(h2, h3);
    L[2 * i] = __nv_bfloat162(__float2bfloat16(v.x - __bfloat162float(h0)),
                              __float2bfloat16(v.y - __bfloat162float(h1)));
    L[2 * i + 1] = __nv_bfloat162(__float2bfloat16(v.z - __bfloat162float(h2)),
                                  __float2bfloat16(v.w - __bfloat162float(h3)));
}
struct HiloArgs { const float* s[4]; __nv_bfloat16* h[4]; __nv_bfloat16* l[4]; int n[4]; };
__global__ void k_hilo_multi(HiloArgs a) {
    int seg = blockIdx.y;
    int i = blockIdx.x * blockDim.x + threadIdx.x;
    if (i < a.n[seg]) hilo_one(a.s[seg], a.h[seg], a.l[seg], i);
}

// ============ warp-MMA split-bf16 GEMM (dual via gridDim.z; passing) ============
template <int K>
__global__ __launch_bounds__(256) void k_mm2(
    const __nv_bfloat16* __restrict__ Ah, const __nv_bfloat16* __restrict__ Al,
    const __nv_bfloat16* __restrict__ Bh0, const __nv_bfloat16* __restrict__ Bl0,
    const float* __restrict__ bias0, float* __restrict__ C0,
    const __nv_bfloat16* __restrict__ Bh1, const __nv_bfloat16* __restrict__ Bl1,
    const float* __restrict__ bias1, float* __restrict__ C1, int Ntot)
{
    const __nv_bfloat16* __restrict__ Bh = blockIdx.z ? Bh1 : Bh0;
    const __nv_bfloat16* __restrict__ Bl = blockIdx.z ? Bl1 : Bl0;
    const float* __restrict__ bias = blockIdx.z ? bias1 : bias0;
    float* __restrict__ C = blockIdx.z ? C1 : C0;

    constexpr int LDS = 72;
    extern __shared__ __nv_bfloat16 sm[];
    __nv_bfloat16* sAh = sm;
    __nv_bfloat16* sAl = sAh + 128 * LDS;
    __nv_bfloat16* sBh = sAl + 128 * LDS;
    __nv_bfloat16* sBl = sBh + 128 * LDS;

    const int tid = threadIdx.x, lane = tid & 31, wid = tid >> 5;
    const int m0 = blockIdx.y * 128, n0 = blockIdx.x * 128;
    const int wm = (wid & 3) * 32, wn = (wid >> 2) * 64;
    const int g = lane >> 2, tg = lane & 3;
    const int seg = lane >> 3, i8 = lane & 7;
    const uint32_t sAh_b = smem_to_u32(sAh), sAl_b = smem_to_u32(sAl);
    const uint32_t sBh_b = smem_to_u32(sBh), sBl_b = smem_to_u32(sBl);

    float acc[2][8][4];
#pragma unroll
    for (int im = 0; im < 2; im++)
#pragma unroll
        for (int jn = 0; jn < 8; jn++)
#pragma unroll
            for (int q = 0; q < 4; q++) acc[im][jn][q] = 0.f;

    for (int kc = 0; kc < K; kc += 64) {
        if (kc) __syncthreads();
        {
            const __nv_bfloat16* srcs[4] = {Ah, Al, Bh, Bl};
            __nv_bfloat16* dsts[4] = {sAh, sAl, sBh, sBl};
            const int r0s[4] = {m0, m0, n0, n0};
#pragma unroll
            for (int t = 0; t < 4; t++) {
                for (int v = tid; v < 1024; v += 256) {
                    int row = v >> 3, q = (v & 7) * 8;
                    *reinterpret_cast<uint4*>(dsts[t] + row * LDS + q) =
                        *reinterpret_cast<const uint4*>(srcs[t] + (size_t)(r0s[t] + row) * K + kc + q);
                }
            }
        }
        __syncthreads();
#pragma unroll
        for (int ks = 0; ks < 4; ks++) {
            const int k0 = ks * 16;
            uint32_t ah[2][4], al[2][4];
#pragma unroll
            for (int im = 0; im < 2; im++) {
                int arow = wm + im * 16 + (seg & 1) * 8 + i8;
                int acol = k0 + (seg >> 1) * 8;
                LDSM_X4(ah[im], sAh_b + (uint32_t)(arow * LDS + acol) * 2u);
                LDSM_X4(al[im], sAl_b + (uint32_t)(arow * LDS + acol) * 2u);
            }
#pragma unroll
            for (int ip = 0; ip < 4; ip++) {
                int brow = wn + ip * 16 + (seg >> 1) * 8 + i8;
                int bcol = k0 + (seg & 1) * 8;
                uint32_t bh4[4], bl4[4];
                LDSM_X4(bh4, sBh_b + (uint32_t)(brow * LDS + bcol) * 2u);
                LDSM_X4(bl4, sBl_b + (uint32_t)(brow * LDS + bcol) * 2u);
#pragma unroll
                for (int im = 0; im < 2; im++) {
#pragma unroll
                    for (int hf = 0; hf < 2; hf++) {
                        float* c = acc[im][ip * 2 + hf];
                        mma16816(c, ah[im], bh4[2 * hf], bh4[2 * hf + 1]);
                        mma16816(c, al[im], bh4[2 * hf], bh4[2 * hf + 1]);
                        mma16816(c, ah[im], bl4[2 * hf], bl4[2 * hf + 1]);
                    }
                }
            }
        }
    }
#pragma unroll
    for (int im = 0; im < 2; im++) {
#pragma unroll
        for (int jn = 0; jn < 8; jn++) {
            int col = n0 + wn + jn * 8 + tg * 2;
            float b0v = bias[col], b1v = bias[col + 1];
            int row0 = m0 + wm + im * 16 + g;
            float2 v0 = make_float2(acc[im][jn][0] + b0v, acc[im][jn][1] + b1v);
            float2 v1 = make_float2(acc[im][jn][2] + b0v, acc[im][jn][3] + b1v);
            *reinterpret_cast<float2*>(C + (size_t)row0 * Ntot + col) = v0;
            *reinterpret_cast<float2*>(C + (size_t)(row0 + 8) * Ntot + col) = v1;
        }
    }
}

// ============ persistent BiLSTM: 32k chunks, cp.async prefetch, fewer syncs ============
template <int MODE, int TSTEPS, int NSEQ, int ROWS, int THREADS>
__global__ __launch_bounds__(THREADS) void k_lstm(
    const int* __restrict__ idxmat,
    const float* __restrict__ tab_f, const float* __restrict__ tab_b,
    const float* __restrict__ bias_f, const float* __restrict__ bias_b,
    __nv_bfloat16* __restrict__ Hh, __nv_bfloat16* __restrict__ Hl)
{
    constexpr int NW = THREADS / 32, RPT = ROWS / NW;
    constexpr int CHF = 32 * G4;              // floats per 32-k chunk = 16384
    constexpr int NCP = (CHF / 4) / THREADS;  // float4 per thread per chunk
    extern __shared__ char dsm[];
    float* hs    = reinterpret_cast<float*>(dsm);       // [ROWS][HH]
    float* wst   = hs + ROWS * HH;                      // [2][CHF]
    float* sbias = wst + 2 * CHF;                       // [G4]
    int* slen = reinterpret_cast<int*>(sbias + G4);
    int* sfe = slen + ROWS; int* soff = sfe + ROWS; int* sun = soff + ROWS;

    const int dir = blockIdx.y;
    const float* __restrict__ tab = dir ? tab_b : tab_f;
    const float* __restrict__ WhT = g_WhT[2 * MODE + dir];
    const int n0 = blockIdx.x * ROWS;
    const int tid = threadIdx.x, jt = tid & 31, rt = tid >> 5;
    const int e0 = jt * 4, r0 = rt * RPT;
    const uint32_t wst_a = smem_to_u32(wst);

    if (MODE == 1) {
        const float* b = dir ? bias_b : bias_f;
        for (int i = tid; i < G4; i += THREADS) sbias[i] = b[i];
    }
    float c[RPT][4];
#pragma unroll
    for (int r = 0; r < RPT; r++) {
#pragma unroll
        for (int u = 0; u < 4; u++) c[r][u] = 0.f;
        *reinterpret_cast<float4*>(&hs[(r0 + r) * HH + e0]) = make_float4(0.f, 0.f, 0.f, 0.f);
    }
    if (tid < ROWS) {
        int n = n0 + tid;
        slen[tid] = MODE ? g_p_len[n] : g_tok_len[n];
        if (MODE) { sfe[tid] = g_p_fe[n]; soff[tid] = g_p_off[n]; sun[tid] = g_p_un[n]; }
    }
    for (int i = tid; i < CHF / 4; i += THREADS)
        reinterpret_cast<float4*>(wst)[i] = reinterpret_cast<const float4*>(WhT)[i];
    __syncthreads();

    for (int s = 0; s < TSTEPS; s++) {
        u64 acc64[RPT][8];
#pragma unroll
        for (int r = 0; r < RPT; r++)
#pragma unroll
            for (int j = 0; j < 8; j++) acc64[r][j] = 0ull;

#pragma unroll
        for (int ch = 0; ch < 4; ch++) {
            {   // async-prefetch next 32-k chunk into the other buffer
                const int nxt = (ch + 1) & 3;
                const float4* src = reinterpret_cast<const float4*>(WhT + nxt * CHF);
                uint32_t dsta = wst_a + (uint32_t)(((ch + 1) & 1) * CHF) * 4u;
#pragma unroll
                for (int t = 0; t < NCP; t++)
                    CP_ASYNC16(dsta + (uint32_t)(tid + t * THREADS) * 16u, src + tid + t * THREADS);
                CP_COMMIT;
            }
            const float* wcur = wst + (ch & 1) * CHF;
#pragma unroll
            for (int kk = 0; kk < 32; kk++) {
                ulonglong2 wA = *reinterpret_cast<const ulonglong2*>(&wcur[kk * G4 + e0]);
                ulonglong2 wB = *reinterpret_cast<const ulonglong2*>(&wcur[kk * G4 + 128 + e0]);
                ulonglong2 wC = *reinterpret_cast<const ulonglong2*>(&wcur[kk * G4 + 256 + e0]);
                ulonglong2 wD = *reinterpret_cast<const ulonglong2*>(&wcur[kk * G4 + 384 + e0]);
#pragma unroll
                for (int r = 0; r < RPT; r++) {
                    u64 h2 = dup2(hs[(r0 + r) * HH + ch * 32 + kk]);
                    ffma2(acc64[r][0], h2, wA.x); ffma2(acc64[r][1], h2, wA.y);
                    ffma2(acc64[r][2], h2, wB.x); ffma2(acc64[r][3], h2, wB.y);
                    ffma2(acc64[r][4], h2, wC.x); ffma2(acc64[r][5], h2, wC.y);
                    ffma2(acc64[r][6], h2, wD.x); ffma2(acc64[r][7], h2, wD.y);
                }
            }
            CP_WAIT0;
            __syncthreads();
        }

        float hnew[RPT][4];
#pragma unroll
        for (int r = 0; r < RPT; r++) {
            float a16[16];
#pragma unroll
            for (int j = 0; j < 8; j++) {
                float2 v = unpack2(acc64[r][j]);
                a16[j * 2] = v.x; a16[j * 2 + 1] = v.y;
            }
            int rr = r0 + r, n = n0 + rr, len = slen[rr];
            int gi = dir ? min(max(len - 1 - s, 0), TSTEPS - 1) : s;
            float gv[16];
            if (MODE == 0) {
                int id = idxmat[(size_t)gi * NSEQ + n];
                const float* grow = tab + (size_t)id * G4;
                float4 a0 = *reinterpret_cast<const float4*>(&grow[e0]);
                float4 a1 = *reinterpret_cast<const float4*>(&grow[128 + e0]);
                float4 a2 = *reinterpret_cast<const float4*>(&grow[256 + e0]);
                float4 a3 = *reinterpret_cast<const float4*>(&grow[384 + e0]);
                gv[0]=a0.x; gv[1]=a0.y; gv[2]=a0.z; gv[3]=a0.w;
                gv[4]=a1.x; gv[5]=a1.y; gv[6]=a1.z; gv[7]=a1.w;
                gv[8]=a2.x; gv[9]=a2.y; gv[10]=a2.z; gv[11]=a2.w;
                gv[12]=a3.x; gv[13]=a3.y; gv[14]=a3.z; gv[15]=a3.w;
            } else {
                int pl = idxmat[(size_t)gi * NSEQ + n];
                bool keep = (gi < sfe[rr]) && (pl >= 0) && (pl < sun[rr]);
                float4 b0 = *reinterpret_cast<const float4*>(&sbias[e0]);
                float4 b1 = *reinterpret_cast<const float4*>(&sbias[128 + e0]);
                float4 b2 = *reinterpret_cast<const float4*>(&sbias[256 + e0]);
                float4 b3 = *reinterpret_cast<const float4*>(&sbias[384 + e0]);
                gv[0]=b0.x; gv[1]=b0.y; gv[2]=b0.z; gv[3]=b0.w;
                gv[4]=b1.x; gv[5]=b1.y; gv[6]=b1.z; gv[7]=b1.w;
                gv[8]=b2.x; gv[9]=b2.y; gv[10]=b2.z; gv[11]=b2.w;
                gv[12]=b3.x; gv[13]=b3.y; gv[14]=b3.z; gv[15]=b3.w;
                if (keep) {
                    int gidx = min(pl + soff[rr], NU - 1);
                    const float* grow = tab + (size_t)gidx * G4;
                    float4 t0 = *reinterpret_cast<const float4*>(&grow[e0]);
                    float4 t1 = *reinterpret_cast<const float4*>(&grow[128 + e0]);
                    float4 t2 = *reinterpret_cast<const float4*>(&grow[256 + e0]);
                    float4 t3 = *reinterpret_cast<const float4*>(&grow[384 + e0]);
                    gv[0]+=t0.x; gv[1]+=t0.y; gv[2]+=t0.z; gv[3]+=t0.w;
                    gv[4]+=t1.x; gv[5]+=t1.y; gv[6]+=t1.z; gv[7]+=t1.w;
                    gv[8]+=t2.x; gv[9]+=t2.y; gv[10]+=t2.z; gv[11]+=t2.w;
                    gv[12]+=t3.x; gv[13]+=t3.y; gv[14]+=t3.z; gv[15]+=t3.w;
                }
            }
#pragma unroll
            for (int u = 0; u < 4; u++) {
                float iv = a16[u]      + gv[u];
                float fv = a16[4 + u]  + gv[4 + u];
                float gg = a16[8 + u]  + gv[8 + u];
                float ov = a16[12 + u] + gv[12 + u];
                float cn = sigm(fv) * c[r][u] + sigm(iv) * ftanh(gg);
                c[r][u] = cn;
                hnew[r][u] = sigm(ov) * ftanh(cn);
            }
            if (s < len) {
                int wi = dir ? (len - 1 - s) : s;
                size_t base = ((size_t)wi * NSEQ + n) * (2 * HH) + dir * HH + e0;
                __nv_bfloat16 hb[4], lb[4];
#pragma unroll
                for (int u = 0; u < 4; u++) {
                    hb[u] = __float2bfloat16(hnew[r][u]);
                    lb[u] = __float2bfloat16(hnew[r][u] - __bfloat162float(hb[u]));
                }
                *reinterpret_cast<uint2*>(Hh + base) = *reinterpret_cast<uint2*>(hb);
                *reinterpret_cast<uint2*>(Hl + base) = *reinterpret_cast<uint2*>(lb);
            } else if (dir == 0) {
                uint2 z = make_uint2(0u, 0u);
                size_t b0 = ((size_t)s * NSEQ + n) * (2 * HH) + e0;
                *reinterpret_cast<uint2*>(Hh + b0) = z;
                *reinterpret_cast<uint2*>(Hl + b0) = z;
                *reinterpret_cast<uint2*>(Hh + b0 + HH) = z;
                *reinterpret_cast<uint2*>(Hl + b0 + HH) = z;
            }
        }
        // hs reads all completed at last chunk-sync; pointwise touches no hs.
#pragma unroll
        for (int r = 0; r < RPT; r++)
            *reinterpret_cast<float4*>(&hs[(r0 + r) * HH + e0]) =
                make_float4(hnew[r][0], hnew[r][1], hnew[r][2], hnew[r][3]);
        __syncthreads();
    }
}

// ============ attention pooling ============
__global__ void k_attn(const float* __restrict__ ln_g, const float* __restrict__ ln_b,
                       const float* __restrict__ attn_w, const float* __restrict__ attn_bp) {
    int gwarp = (blockIdx.x * blockDim.x + threadIdx.x) >> 5;
    int lane = threadIdx.x & 31;
    if (gwarp >= NU) return;
    int n = gwarp, len = g_tok_len[n];
    float gg[4], bb[4], aw[4];
#pragma unroll
    for (int q = 0; q < 4; q++) {
        int e = lane + 32 * q;
        gg[q] = ln_g[e]; bb[q] = ln_b[e]; aw[q] = attn_w[e];
    }
    float ab = attn_bp[0];
    float sc[TT], smax = -1e30f;
#pragma unroll
    for (int t = 0; t < TT; t++) {
        sc[t] = -1e30f;
        if (t < len) {
            float o[4], lsum = 0.f;
#pragma unroll
            for (int q = 0; q < 4; q++) {
                o[q] = g_lin[((size_t)t * NU + n) * EE + lane + 32 * q];
                lsum += o[q];
            }
#pragma unroll
            for (int off = 16; off; off >>= 1) lsum += __shfl_xor_sync(0xffffffffu, lsum, off);
            float mean = lsum * (1.f / 128.f);
            float vs = 0.f;
#pragma unroll
            for (int q = 0; q < 4; q++) { float d = o[q] - mean; vs += d * d; }
#pragma unroll
            for (int off = 16; off; off >>= 1) vs += __shfl_xor_sync(0xffffffffu, vs, off);
            float inv = rsqrtf(vs * (1.f / 128.f) + 1e-5f);
            float ssum = 0.f;
#pragma unroll
            for (int q = 0; q < 4; q++)
                ssum += ftanh((o[q] - mean) * inv * gg[q] + bb[q]) * aw[q];
#pragma unroll
            for (int off = 16; off; off >>= 1) ssum += __shfl_xor_sync(0xffffffffu, ssum, off);
            sc[t] = ssum + ab;
            smax = fmaxf(smax, sc[t]);
        }
    }
    float den = 0.f, wts[TT];
#pragma unroll
    for (int t = 0; t < TT; t++) {
        wts[t] = (t < len) ? __expf(sc[t] - smax) : 0.f;
        den += wts[t];
    }
    float invden = 1.f / den;
    float accq[4] = {0.f, 0.f, 0.f, 0.f};
#pragma unroll
    for (int t = 0; t < TT; t++) {
        if (t < len) {
            float wt = wts[t] * invden;
#pragma unroll
            for (int q = 0; q < 4; q++)
                accq[q] += wt * g_lin[((size_t)t * NU + n) * EE + lane + 32 * q];
        }
    }
#pragma unroll
    for (int q = 0; q < 4; q++) {
        __nv_bfloat16 h = __float2bfloat16(accq[q]);
        __nv_bfloat16 l = __float2bfloat16(accq[q] - __bfloat162float(h));
        g_tf_h[(size_t)n * EE + lane + 32 * q] = h;
        g_tf_l[(size_t)n * EE + lane + 32 * q] = l;
    }
}

// ============ host launcher ============
extern "C" void kernel_launch(void* const* d_in, const int* in_sizes, int n_in,
                              void* d_out, int out_size) {
    const int*   units  = (const int*)d_in[0];
    const int*   paths  = (const int*)d_in[1];
    const int*   upd    = (const int*)d_in[2];
    const int*   ppd    = (const int*)d_in[3];
    const float* emb    = (const float*)d_in[4];
    const float* tl_Wif = (const float*)d_in[5];
    const float* tl_Whf = (const float*)d_in[6];
    const float* tl_bf  = (const float*)d_in[7];
    const float* tl_Wib = (const float*)d_in[8];
    const float* tl_Whb = (const float*)d_in[9];
    const float* tl_bb  = (const float*)d_in[10];
    const float* lin_W  = (const float*)d_in[11];
    const float* lin_b  = (const float*)d_in[12];
    const float* ln_g   = (const float*)d_in[13];
    const float* ln_bv  = (const float*)d_in[14];
    const float* attn_w = (const float*)d_in[15];
    const float* attn_b = (const float*)d_in[16];
    const float* pl_Wif = (const float*)d_in[17];
    const float* pl_Whf = (const float*)d_in[18];
    const float* pl_bf  = (const float*)d_in[19];
    const float* pl_Wib = (const float*)d_in[20];
    const float* pl_Whb = (const float*)d_in[21];
    const float* pl_bb  = (const float*)d_in[22];
    const float* ul_W   = (const float*)d_in[23];
    const float* ul_b   = (const float*)d_in[24];
    float* out = (float*)d_out;

    void *pVTf, *pVTb, *pPTf, *pPTb, *pZero, *pLin;
    cudaGetSymbolAddress(&pVTf, g_VTf);    cudaGetSymbolAddress(&pVTb, g_VTb);
    cudaGetSymbolAddress(&pPTf, g_PTf);    cudaGetSymbolAddress(&pPTb, g_PTb);
    cudaGetSymbolAddress(&pZero, g_zero);  cudaGetSymbolAddress(&pLin, g_lin);
    void *pEh, *pEl, *pHch, *pHcl, *pTfh, *pTfl, *pHph, *pHpl, *pWih, *pWil, *pW2h, *pW2l;
    cudaGetSymbolAddress(&pEh, g_emb_h);   cudaGetSymbolAddress(&pEl, g_emb_l);
    cudaGetSymbolAddress(&pHch, g_Hcat_h); cudaGetSymbolAddress(&pHcl, g_Hcat_l);
    cudaGetSymbolAddress(&pTfh, g_tf_h);   cudaGetSymbolAddress(&pTfl, g_tf_l);
    cudaGetSymbolAddress(&pHph, g_Hp_h);   cudaGetSymbolAddress(&pHpl, g_Hp_l);
    cudaGetSymbolAddress(&pWih, g_Wih);    cudaGetSymbolAddress(&pWil, g_Wil);
    cudaGetSymbolAddress(&pW2h, g_W2h);    cudaGetSymbolAddress(&pW2l, g_W2l);
    __nv_bfloat16* Wih = (__nv_bfloat16*)pWih;  __nv_bfloat16* Wil = (__nv_bfloat16*)pWil;
    __nv_bfloat16* W2h = (__nv_bfloat16*)pW2h;  __nv_bfloat16* W2l = (__nv_bfloat16*)pW2l;

    const int MM_SMEM = 4 * 128 * 72 * 2;
    const int LS_T = 64 * HH * 4 + 2 * 32 * G4 * 4 + G4 * 4 + 4 * 64 * 4;   // 167936
    const int LS_P = 16 * HH * 4 + 2 * 32 * G4 * 4 + G4 * 4 + 4 * 16 * 4;   // 141568
    cudaFuncSetAttribute(k_mm2<128>, cudaFuncAttributeMaxDynamicSharedMemorySize, MM_SMEM);
    cudaFuncSetAttribute(k_mm2<256>, cudaFuncAttributeMaxDynamicSharedMemorySize, MM_SMEM);
    cudaFuncSetAttribute((const void*)k_lstm<0, TT, NU, 64, 512>,
                         cudaFuncAttributeMaxDynamicSharedMemorySize, LS_T + 1024);
    cudaFuncSetAttribute((const void*)k_lstm<1, LPATH, NPATH, 16, 256>,
                         cudaFuncAttributeMaxDynamicSharedMemorySize, LS_P + 1024);

    // launch 0: fused setup
    k_prep<<<dim3(256, 6), 256>>>(units, tl_Whf, tl_Whb, pl_Whf, pl_Whb, paths, upd, ppd);
    // launch 1: hilo emb + tl_Wif + tl_Wib + lin_W
    {
        HiloArgs a;
        a.s[0] = emb;    a.h[0] = (__nv_bfloat16*)pEh; a.l[0] = (__nv_bfloat16*)pEl; a.n[0] = VOCAB * EE / 4;
        a.s[1] = tl_Wif; a.h[1] = Wih + 0 * G4 * EE;   a.l[1] = Wil + 0 * G4 * EE;   a.n[1] = G4 * EE / 4;
        a.s[2] = tl_Wib; a.h[2] = Wih + 1 * G4 * EE;   a.l[2] = Wil + 1 * G4 * EE;   a.n[2] = G4 * EE / 4;
        a.s[3] = lin_W;  a.h[3] = W2h;                 a.l[3] = W2l;                 a.n[3] = EE * 256 / 4;
        k_hilo_multi<<<dim3((VOCAB * EE / 4 + 255) / 256, 4), 256>>>(a);
    }
    // launch 2: VT (both dirs)
    k_mm2<128><<<dim3(4, VOCAB / 128, 2), 256, MM_SMEM>>>(
        (const __nv_bfloat16*)pEh, (const __nv_bfloat16*)pEl,
        Wih + 0 * G4 * EE, Wil + 0 * G4 * EE, tl_bf, (float*)pVTf,
        Wih + 1 * G4 * EE, Wil + 1 * G4 * EE, tl_bb, (float*)pVTb, G4);
    // launch 3 (PROFILE TARGET): token BiLSTM
    k_lstm<0, TT, NU, 64, 512><<<dim3(NU / 64, 2), 512, LS_T>>>(
        units, (const float*)pVTf, (const float*)pVTb, nullptr, nullptr,
        (__nv_bfloat16*)pHch, (__nv_bfloat16*)pHcl);
    // launch 4: hilo pl weights + ul_W
    {
        HiloArgs a;
        a.s[0] = pl_Wif; a.h[0] = Wih + 2 * G4 * EE; a.l[0] = Wil + 2 * G4 * EE; a.n[0] = G4 * EE / 4;
        a.s[1] = pl_Wib; a.h[1] = Wih + 3 * G4 * EE; a.l[1] = Wil + 3 * G4 * EE; a.n[1] = G4 * EE / 4;
        a.s[2] = ul_W;   a.h[2] = W2h + EE * 256;    a.l[2] = W2l + EE * 256;    a.n[2] = EE * 256 / 4;
        a.s[3] = ul_W;   a.h[3] = W2h + EE * 256;    a.l[3] = W2l + EE * 256;    a.n[3] = 0;
        k_hilo_multi<<<dim3((G4 * EE / 4 + 255) / 256, 4), 256>>>(a);
    }
    // launch 5: lin
    k_mm2<256><<<dim3(1, TT * NU / 128, 1), 256, MM_SMEM>>>(
        (const __nv_bfloat16*)pHch, (const __nv_bfloat16*)pHcl,
        W2h, W2l, lin_b, (float*)pLin, W2h, W2l, lin_b, (float*)pLin, EE);
    // launch 6: attention
    k_attn<<<(NU * 32) / 256, 256>>>(ln_g, ln_bv, attn_w, attn_b);
    // launch 7: PT (both dirs)
    k_mm2<128><<<dim3(4, NU / 128, 2), 256, MM_SMEM>>>(
        (const __nv_bfloat16*)pTfh, (const __nv_bfloat16*)pTfl,
        Wih + 2 * G4 * EE, Wil + 2 * G4 * EE, (const float*)pZero, (float*)pPTf,
        Wih + 3 * G4 * EE, Wil + 3 * G4 * EE, (const float*)pZero, (float*)pPTb, G4);
    // launch 8: path BiLSTM
    k_lstm<1, LPATH, NPATH, 16, 256><<<dim3(NPATH / 16, 2), 256, LS_P>>>(
        paths, (const float*)pPTf, (const float*)pPTb, pl_bf, pl_bb,
        (__nv_bfloat16*)pHph, (__nv_bfloat16*)pHpl);
    // launch 9: out
    k_mm2<256><<<dim3(1, LPATH * NPATH / 128, 1), 256, MM_SMEM>>>(
        (const __nv_bfloat16*)pHph, (const __nv_bfloat16*)pHpl,
        W2h + EE * 256, W2l + EE * 256, ul_b, out,
        W2h + EE * 256, W2l + EE * 256, ul_b, out, EE);
}

// round 15
// speedup vs baseline: 1.5304x; 1.0409x over previous
#include <cuda_runtime.h>
#include <cuda_bf16.h>
#include <cstdint>

#define TT 16
#define NU 4096
#define EE 128
#define HH 128
#define G4 512
#define LPATH 32
#define NPATH 1024
#define NB 8
#define VOCAB 16384

typedef unsigned long long u64;

__device__ __forceinline__ uint32_t smem_to_u32(const void* p) {
    uint32_t a;
    asm("{ .reg .u64 t; cvta.to.shared.u64 t, %1; cvt.u32.u64 %0, t; }" : "=r"(a) : "l"(p));
    return a;
}
#define LDSM_X4(r, addr) \
    asm volatile("ldmatrix.sync.aligned.m8n8.x4.shared.b16 {%0,%1,%2,%3}, [%4];" \
        : "=r"((r)[0]), "=r"((r)[1]), "=r"((r)[2]), "=r"((r)[3]) : "r"(addr))
__device__ __forceinline__ void mma16816(float* c, const uint32_t* a, uint32_t b0, uint32_t b1) {
    asm volatile("mma.sync.aligned.m16n8k16.row.col.f32.bf16.bf16.f32 "
        "{%0,%1,%2,%3}, {%4,%5,%6,%7}, {%8,%9}, {%0,%1,%2,%3};"
        : "+f"(c[0]), "+f"(c[1]), "+f"(c[2]), "+f"(c[3])
        : "r"(a[0]), "r"(a[1]), "r"(a[2]), "r"(a[3]), "r"(b0), "r"(b1));
}
__device__ __forceinline__ void ffma2(u64& d, u64 a, u64 b) {
    asm("fma.rn.f32x2 %0, %1, %2, %0;" : "+l"(d) : "l"(a), "l"(b));
}
__device__ __forceinline__ u64 dup2(float x) {
    u64 r; asm("mov.b64 %0, {%1, %1};" : "=l"(r) : "f"(x)); return r;
}
__device__ __forceinline__ float2 unpack2(u64 v) {
    float2 f; asm("mov.b64 {%0, %1}, %2;" : "=f"(f.x), "=f"(f.y) : "l"(v)); return f;
}
#define CP_ASYNC16(dst_u32, src_ptr) \
    asm volatile("cp.async.cg.shared.global [%0], [%1], 16;" :: "r"(dst_u32), "l"(src_ptr))
#define CP_COMMIT asm volatile("cp.async.commit_group;" ::: "memory")
#define CP_WAIT0  asm volatile("cp.async.wait_group 0;" ::: "memory")

__device__ __forceinline__ float sigm(float x) {
    return __fdividef(1.f, 1.f + __expf(-x));
}
__device__ __forceinline__ float ftanh(float x) {
    float e = __expf(2.f * fabsf(x));
    return copysignf(1.f - __fdividef(2.f, e + 1.f), x);
}

// ============ device scratch ============
__device__ int   g_tok_len[NU];
__device__ int   g_p_len[NPATH], g_p_fe[NPATH], g_p_off[NPATH], g_p_un[NPATH];
__device__ float g_VTf[VOCAB * G4], g_VTb[VOCAB * G4];
__device__ float g_PTf[NU * G4],    g_PTb[NU * G4];
__device__ float g_lin[TT * NU * EE];
__device__ float g_WhT[4][HH * G4];
__device__ float g_zero[G4];
__device__ __nv_bfloat16 g_emb_h[VOCAB * EE],  g_emb_l[VOCAB * EE];
__device__ __nv_bfloat16 g_Hcat_h[TT * NU * 2 * HH], g_Hcat_l[TT * NU * 2 * HH];
__device__ __nv_bfloat16 g_tf_h[NU * EE], g_tf_l[NU * EE];
__device__ __nv_bfloat16 g_Hp_h[LPATH * NPATH * 2 * HH], g_Hp_l[LPATH * NPATH * 2 * HH];
__device__ __nv_bfloat16 g_Wih[4][G4 * EE], g_Wil[4][G4 * EE];
__device__ __nv_bfloat16 g_W2h[2][EE * 2 * HH], g_W2l[2][EE * 2 * HH];

// ============ fused setup ============
__global__ void k_prep(const int* __restrict__ units,
                       const float* __restrict__ W0, const float* __restrict__ W1,
                       const float* __restrict__ W2, const float* __restrict__ W3,
                       const int* __restrict__ paths,
                       const int* __restrict__ upd, const int* __restrict__ ppd) {
    int seg = blockIdx.y;
    int idx = blockIdx.x * blockDim.x + threadIdx.x;
    if (seg == 0) {
        if (idx >= NU) return;
        int len = TT;
        for (int t = 0; t < TT; t++) if (units[t * NU + idx] == 0) { len = t; break; }
        g_tok_len[idx] = len;
    } else if (seg <= 4) {
        if (idx >= G4 * HH) return;
        const float* W = (seg == 1) ? W0 : (seg == 2) ? W1 : (seg == 3) ? W2 : W3;
        int j = idx >> 7, k = idx & 127;
        g_WhT[seg - 1][k * G4 + j] = W[idx];
    } else {
        int p = idx;
        if (p >= NPATH) return;
        int dd = NB - 1, cum = 0;
        for (int i = 0; i < NB; i++) { int nx = cum + ppd[i]; if (p >= cum && p < nx) { dd = i; break; } cum = nx; }
        int off = 0;
        for (int i = 0; i < dd; i++) off += upd[i];
        int un = upd[dd];
        int fe = LPATH;
        for (int t = 0; t < LPATH; t++) if (paths[t * NPATH + p] == -1) { fe = t; break; }
        int plen = LPATH;
        for (int t = 0; t < LPATH; t++) {
            bool msk;
            if (t >= fe) msk = true;
            else { int v = paths[t * NPATH + p]; msk = (v < 0) || (v > un); }
            if (msk) { plen = t; break; }
        }
        g_p_len[p] = plen; g_p_fe[p] = fe; g_p_off[p] = off; g_p_un[p] = un;
    }
}

__device__ __forceinline__ void hilo_one(const float* src, __nv_bfloat16* hi,
                                         __nv_bfloat16* lo, int i) {
    float4 v = reinterpret_cast<const float4*>(src)[i];
    __nv_bfloat16 h0 = __float2bfloat16(v.x), h1 = __float2bfloat16(v.y);
    __nv_bfloat16 h2 = __float2bfloat16(v.z), h3 = __float2bfloat16(v.w);
    __nv_bfloat162* H = reinterpret_cast<__nv_bfloat162*>(hi);
    __nv_bfloat162* L = reinterpret_cast<__nv_bfloat162*>(lo);
    H[2 * i] = __nv_bfloat162(h0, h1); H[2 * i + 1] = __nv_bfloat162(h2, h3);
    L[2 * i] = __nv_bfloat162(__float2bfloat16(v.x - __bfloat162float(h0)),
                              __float2bfloat16(v.y - __bfloat162float(h1)));
    L[2 * i + 1] = __nv_bfloat162(__float2bfloat16(v.z - __bfloat162float(h2)),
                                  __float2bfloat16(v.w - __bfloat162float(h3)));
}
struct HiloArgs { const float* s[4]; __nv_bfloat16* h[4]; __nv_bfloat16* l[4]; int n[4]; };
__global__ void k_hilo_multi(HiloArgs a) {
    int seg = blockIdx.y;
    int i = blockIdx.x * blockDim.x + threadIdx.x;
    if (i < a.n[seg]) hilo_one(a.s[seg], a.h[seg], a.l[seg], i);
}

// ============ warp-MMA split-bf16 GEMM (dual via gridDim.z; passing) ============
template <int K>
__global__ __launch_bounds__(256) void k_mm2(
    const __nv_bfloat16* __restrict__ Ah, const __nv_bfloat16* __restrict__ Al,
    const __nv_bfloat16* __restrict__ Bh0, const __nv_bfloat16* __restrict__ Bl0,
    const float* __restrict__ bias0, float* __restrict__ C0,
    const __nv_bfloat16* __restrict__ Bh1, const __nv_bfloat16* __restrict__ Bl1,
    const float* __restrict__ bias1, float* __restrict__ C1, int Ntot)
{
    const __nv_bfloat16* __restrict__ Bh = blockIdx.z ? Bh1 : Bh0;
    const __nv_bfloat16* __restrict__ Bl = blockIdx.z ? Bl1 : Bl0;
    const float* __restrict__ bias = blockIdx.z ? bias1 : bias0;
    float* __restrict__ C = blockIdx.z ? C1 : C0;

    constexpr int LDS = 72;
    extern __shared__ __nv_bfloat16 sm[];
    __nv_bfloat16* sAh = sm;
    __nv_bfloat16* sAl = sAh + 128 * LDS;
    __nv_bfloat16* sBh = sAl + 128 * LDS;
    __nv_bfloat16* sBl = sBh + 128 * LDS;

    const int tid = threadIdx.x, lane = tid & 31, wid = tid >> 5;
    const int m0 = blockIdx.y * 128, n0 = blockIdx.x * 128;
    const int wm = (wid & 3) * 32, wn = (wid >> 2) * 64;
    const int g = lane >> 2, tg = lane & 3;
    const int seg = lane >> 3, i8 = lane & 7;
    const uint32_t sAh_b = smem_to_u32(sAh), sAl_b = smem_to_u32(sAl);
    const uint32_t sBh_b = smem_to_u32(sBh), sBl_b = smem_to_u32(sBl);

    float acc[2][8][4];
#pragma unroll
    for (int im = 0; im < 2; im++)
#pragma unroll
        for (int jn = 0; jn < 8; jn++)
#pragma unroll
            for (int q = 0; q < 4; q++) acc[im][jn][q] = 0.f;

    for (int kc = 0; kc < K; kc += 64) {
        if (kc) __syncthreads();
        {
            const __nv_bfloat16* srcs[4] = {Ah, Al, Bh, Bl};
            __nv_bfloat16* dsts[4] = {sAh, sAl, sBh, sBl};
            const int r0s[4] = {m0, m0, n0, n0};
#pragma unroll
            for (int t = 0; t < 4; t++) {
                for (int v = tid; v < 1024; v += 256) {
                    int row = v >> 3, q = (v & 7) * 8;
                    *reinterpret_cast<uint4*>(dsts[t] + row * LDS + q) =
                        *reinterpret_cast<const uint4*>(srcs[t] + (size_t)(r0s[t] + row) * K + kc + q);
                }
            }
        }
        __syncthreads();
#pragma unroll
        for (int ks = 0; ks < 4; ks++) {
            const int k0 = ks * 16;
            uint32_t ah[2][4], al[2][4];
#pragma unroll
            for (int im = 0; im < 2; im++) {
                int arow = wm + im * 16 + (seg & 1) * 8 + i8;
                int acol = k0 + (seg >> 1) * 8;
                LDSM_X4(ah[im], sAh_b + (uint32_t)(arow * LDS + acol) * 2u);
                LDSM_X4(al[im], sAl_b + (uint32_t)(arow * LDS + acol) * 2u);
            }
#pragma unroll
            for (int ip = 0; ip < 4; ip++) {
                int brow = wn + ip * 16 + (seg >> 1) * 8 + i8;
                int bcol = k0 + (seg & 1) * 8;
                uint32_t bh4[4], bl4[4];
                LDSM_X4(bh4, sBh_b + (uint32_t)(brow * LDS + bcol) * 2u);
                LDSM_X4(bl4, sBl_b + (uint32_t)(brow * LDS + bcol) * 2u);
#pragma unroll
                for (int im = 0; im < 2; im++) {
#pragma unroll
                    for (int hf = 0; hf < 2; hf++) {
                        float* c = acc[im][ip * 2 + hf];
                        mma16816(c, ah[im], bh4[2 * hf], bh4[2 * hf + 1]);
                        mma16816(c, al[im], bh4[2 * hf], bh4[2 * hf + 1]);
                        mma16816(c, ah[im], bl4[2 * hf], bl4[2 * hf + 1]);
                    }
                }
            }
        }
    }
#pragma unroll
    for (int im = 0; im < 2; im++) {
#pragma unroll
        for (int jn = 0; jn < 8; jn++) {
            int col = n0 + wn + jn * 8 + tg * 2;
            float b0v = bias[col], b1v = bias[col + 1];
            int row0 = m0 + wm + im * 16 + g;
            float2 v0 = make_float2(acc[im][jn][0] + b0v, acc[im][jn][1] + b1v);
            float2 v1 = make_float2(acc[im][jn][2] + b0v, acc[im][jn][3] + b1v);
            *reinterpret_cast<float2*>(C + (size_t)row0 * Ntot + col) = v0;
            *reinterpret_cast<float2*>(C + (size_t)(row0 + 8) * Ntot + col) = v1;
        }
    }
}

// ============ persistent BiLSTM: col-split warps (2 cols/thread), 32k chunks ============
// Warp wid: ch = wid&1 (column half), rg = wid>>1 (row group of RPT rows).
// Thread owns cols e0,e0+1 (e0 = ch*64 + lane*2) of each of the 4 gate blocks,
// for RPT rows -> complete gate sets per cell; weights 32B/thread/k (4x LDS.64).
template <int MODE, int TSTEPS, int NSEQ, int ROWS, int THREADS>
__global__ __launch_bounds__(THREADS) void k_lstm(
    const int* __restrict__ idxmat,
    const float* __restrict__ tab_f, const float* __restrict__ tab_b,
    const float* __restrict__ bias_f, const float* __restrict__ bias_b,
    __nv_bfloat16* __restrict__ Hh, __nv_bfloat16* __restrict__ Hl)
{
    constexpr int NW = THREADS / 32, RG = NW / 2, RPT = ROWS / RG;
    constexpr int CHF = 32 * G4;
    constexpr int NCP = (CHF / 4) / THREADS;
    extern __shared__ char dsm[];
    float* hs    = reinterpret_cast<float*>(dsm);       // [ROWS][HH]
    float* wst   = hs + ROWS * HH;                      // [2][CHF]
    float* sbias = wst + 2 * CHF;                       // [G4]
    int* slen = reinterpret_cast<int*>(sbias + G4);
    int* sfe = slen + ROWS; int* soff = sfe + ROWS; int* sun = soff + ROWS;

    const int dir = blockIdx.y;
    const float* __restrict__ tab = dir ? tab_b : tab_f;
    const float* __restrict__ WhT = g_WhT[2 * MODE + dir];
    const int n0 = blockIdx.x * ROWS;
    const int tid = threadIdx.x, lane = tid & 31, wid = tid >> 5;
    const int ch = wid & 1, rg = wid >> 1;
    const int e0 = ch * 64 + lane * 2;
    const int r0 = rg * RPT;
    const uint32_t wst_a = smem_to_u32(wst);

    if (MODE == 1) {
        const float* b = dir ? bias_b : bias_f;
        for (int i = tid; i < G4; i += THREADS) sbias[i] = b[i];
    }
    float cst[RPT][2];
#pragma unroll
    for (int r = 0; r < RPT; r++) { cst[r][0] = 0.f; cst[r][1] = 0.f; }
    for (int i = tid; i < ROWS * HH / 4; i += THREADS)
        reinterpret_cast<float4*>(hs)[i] = make_float4(0.f, 0.f, 0.f, 0.f);
    if (tid < ROWS) {
        int n = n0 + tid;
        slen[tid] = MODE ? g_p_len[n] : g_tok_len[n];
        if (MODE) { sfe[tid] = g_p_fe[n]; soff[tid] = g_p_off[n]; sun[tid] = g_p_un[n]; }
    }
    for (int i = tid; i < CHF / 4; i += THREADS)
        reinterpret_cast<float4*>(wst)[i] = reinterpret_cast<const float4*>(WhT)[i];
    __syncthreads();

    for (int s = 0; s < TSTEPS; s++) {
        u64 acc[RPT][4];
#pragma unroll
        for (int r = 0; r < RPT; r++)
#pragma unroll
            for (int g = 0; g < 4; g++) acc[r][g] = 0ull;

#pragma unroll
        for (int cno = 0; cno < 4; cno++) {
            {   // async-prefetch next 32-k chunk
                const int nxt = (cno + 1) & 3;
                const float4* src = reinterpret_cast<const float4*>(WhT + nxt * CHF);
                uint32_t dsta = wst_a + (uint32_t)(((cno + 1) & 1) * CHF) * 4u;
#pragma unroll
                for (int t = 0; t < NCP; t++)
                    CP_ASYNC16(dsta + (uint32_t)(tid + t * THREADS) * 16u, src + tid + t * THREADS);
                CP_COMMIT;
            }
            const float* wcur = wst + (cno & 1) * CHF;
#pragma unroll
            for (int kp = 0; kp < 16; kp++) {
                const int kk = kp * 2;
                u64 w0i = *reinterpret_cast<const u64*>(&wcur[kk * G4 + e0]);
                u64 w0f = *reinterpret_cast<const u64*>(&wcur[kk * G4 + 128 + e0]);
                u64 w0g = *reinterpret_cast<const u64*>(&wcur[kk * G4 + 256 + e0]);
                u64 w0o = *reinterpret_cast<const u64*>(&wcur[kk * G4 + 384 + e0]);
                u64 w1i = *reinterpret_cast<const u64*>(&wcur[(kk + 1) * G4 + e0]);
                u64 w1f = *reinterpret_cast<const u64*>(&wcur[(kk + 1) * G4 + 128 + e0]);
                u64 w1g = *reinterpret_cast<const u64*>(&wcur[(kk + 1) * G4 + 256 + e0]);
                u64 w1o = *reinterpret_cast<const u64*>(&wcur[(kk + 1) * G4 + 384 + e0]);
#pragma unroll
                for (int r = 0; r < RPT; r++) {
                    float2 hp = *reinterpret_cast<const float2*>(&hs[(r0 + r) * HH + cno * 32 + kk]);
                    u64 ha = dup2(hp.x), hb = dup2(hp.y);
                    ffma2(acc[r][0], ha, w0i); ffma2(acc[r][1], ha, w0f);
                    ffma2(acc[r][2], ha, w0g); ffma2(acc[r][3], ha, w0o);
                    ffma2(acc[r][0], hb, w1i); ffma2(acc[r][1], hb, w1f);
                    ffma2(acc[r][2], hb, w1g); ffma2(acc[r][3], hb, w1o);
                }
            }
            CP_WAIT0;
            __syncthreads();
        }

        // pointwise: thread owns cells (e0, e0+1) for rows r0..r0+RPT-1
#pragma unroll
        for (int r = 0; r < RPT; r++) {
            const int row = r0 + r, n = n0 + row, len = slen[row];
            const int gi = dir ? min(max(len - 1 - s, 0), TSTEPS - 1) : s;
            float2 ai = unpack2(acc[r][0]), af = unpack2(acc[r][1]);
            float2 ag = unpack2(acc[r][2]), ao = unpack2(acc[r][3]);
            float2 gvi, gvf, gvg, gvo;
            if (MODE == 0) {
                int id = idxmat[(size_t)gi * NSEQ + n];
                const float* grow = tab + (size_t)id * G4;
                gvi = *reinterpret_cast<const float2*>(&grow[e0]);
                gvf = *reinterpret_cast<const float2*>(&grow[128 + e0]);
                gvg = *reinterpret_cast<const float2*>(&grow[256 + e0]);
                gvo = *reinterpret_cast<const float2*>(&grow[384 + e0]);
            } else {
                int pl = idxmat[(size_t)gi * NSEQ + n];
                bool keep = (gi < sfe[row]) && (pl >= 0) && (pl < sun[row]);
                gvi = *reinterpret_cast<const float2*>(&sbias[e0]);
                gvf = *reinterpret_cast<const float2*>(&sbias[128 + e0]);
                gvg = *reinterpret_cast<const float2*>(&sbias[256 + e0]);
                gvo = *reinterpret_cast<const float2*>(&sbias[384 + e0]);
                if (keep) {
                    int gidx = min(pl + soff[row], NU - 1);
                    const float* grow = tab + (size_t)gidx * G4;
                    float2 t0 = *reinterpret_cast<const float2*>(&grow[e0]);
                    float2 t1 = *reinterpret_cast<const float2*>(&grow[128 + e0]);
                    float2 t2 = *reinterpret_cast<const float2*>(&grow[256 + e0]);
                    float2 t3 = *reinterpret_cast<const float2*>(&grow[384 + e0]);
                    gvi.x += t0.x; gvi.y += t0.y; gvf.x += t1.x; gvf.y += t1.y;
                    gvg.x += t2.x; gvg.y += t2.y; gvo.x += t3.x; gvo.y += t3.y;
                }
            }
            float h0, h1;
            {
                float iv = ai.x + gvi.x, fv = af.x + gvf.x, gg = ag.x + gvg.x, ov = ao.x + gvo.x;
                float cn = sigm(fv) * cst[r][0] + sigm(iv) * ftanh(gg);
                cst[r][0] = cn; h0 = sigm(ov) * ftanh(cn);
            }
            {
                float iv = ai.y + gvi.y, fv = af.y + gvf.y, gg = ag.y + gvg.y, ov = ao.y + gvo.y;
                float cn = sigm(fv) * cst[r][1] + sigm(iv) * ftanh(gg);
                cst[r][1] = cn; h1 = sigm(ov) * ftanh(cn);
            }
            *reinterpret_cast<float2*>(&hs[row * HH + e0]) = make_float2(h0, h1);
            __nv_bfloat16 hb0 = __float2bfloat16(h0), hb1 = __float2bfloat16(h1);
            __nv_bfloat162 hb(hb0, hb1);
            __nv_bfloat162 lb(__float2bfloat16(h0 - __bfloat162float(hb0)),
                              __float2bfloat16(h1 - __bfloat162float(hb1)));
            if (s < len) {
                int wi = dir ? (len - 1 - s) : s;
                size_t base = ((size_t)wi * NSEQ + n) * (2 * HH) + dir * HH + e0;
                *reinterpret_cast<__nv_bfloat162*>(Hh + base) = hb;
                *reinterpret_cast<__nv_bfloat162*>(Hl + base) = lb;
            } else if (dir == 0) {
                __nv_bfloat162 z(__float2bfloat16(0.f), __float2bfloat16(0.f));
                size_t b0 = ((size_t)s * NSEQ + n) * (2 * HH) + e0;
                *reinterpret_cast<__nv_bfloat162*>(Hh + b0) = z;
                *reinterpret_cast<__nv_bfloat162*>(Hl + b0) = z;
                *reinterpret_cast<__nv_bfloat162*>(Hh + b0 + HH) = z;
                *reinterpret_cast<__nv_bfloat162*>(Hl + b0 + HH) = z;
            }
        }
        __syncthreads();
    }
}

// ============ attention pooling ============
__global__ void k_attn(const float* __restrict__ ln_g, const float* __restrict__ ln_b,
                       const float* __restrict__ attn_w, const float* __restrict__ attn_bp) {
    int gwarp = (blockIdx.x * blockDim.x + threadIdx.x) >> 5;
    int lane = threadIdx.x & 31;
    if (gwarp >= NU) return;
    int n = gwarp, len = g_tok_len[n];
    float gg[4], bb[4], aw[4];
#pragma unroll
    for (int q = 0; q < 4; q++) {
        int e = lane + 32 * q;
        gg[q] = ln_g[e]; bb[q] = ln_b[e]; aw[q] = attn_w[e];
    }
    float ab = attn_bp[0];
    float sc[TT], smax = -1e30f;
#pragma unroll
    for (int t = 0; t < TT; t++) {
        sc[t] = -1e30f;
        if (t < len) {
            float o[4], lsum = 0.f;
#pragma unroll
            for (int q = 0; q < 4; q++) {
                o[q] = g_lin[((size_t)t * NU + n) * EE + lane + 32 * q];
                lsum += o[q];
            }
#pragma unroll
            for (int off = 16; off; off >>= 1) lsum += __shfl_xor_sync(0xffffffffu, lsum, off);
            float mean = lsum * (1.f / 128.f);
            float vs = 0.f;
#pragma unroll
            for (int q = 0; q < 4; q++) { float d = o[q] - mean; vs += d * d; }
#pragma unroll
            for (int off = 16; off; off >>= 1) vs += __shfl_xor_sync(0xffffffffu, vs, off);
            float inv = rsqrtf(vs * (1.f / 128.f) + 1e-5f);
            float ssum = 0.f;
#pragma unroll
            for (int q = 0; q < 4; q++)
                ssum += ftanh((o[q] - mean) * inv * gg[q] + bb[q]) * aw[q];
#pragma unroll
            for (int off = 16; off; off >>= 1) ssum += __shfl_xor_sync(0xffffffffu, ssum, off);
            sc[t] = ssum + ab;
            smax = fmaxf(smax, sc[t]);
        }
    }
    float den = 0.f, wts[TT];
#pragma unroll
    for (int t = 0; t < TT; t++) {
        wts[t] = (t < len) ? __expf(sc[t] - smax) : 0.f;
        den += wts[t];
    }
    float invden = 1.f / den;
    float accq[4] = {0.f, 0.f, 0.f, 0.f};
#pragma unroll
    for (int t = 0; t < TT; t++) {
        if (t < len) {
            float wt = wts[t] * invden;
#pragma unroll
            for (int q = 0; q < 4; q++)
                accq[q] += wt * g_lin[((size_t)t * NU + n) * EE + lane + 32 * q];
        }
    }
#pragma unroll
    for (int q = 0; q < 4; q++) {
        __nv_bfloat16 h = __float2bfloat16(accq[q]);
        __nv_bfloat16 l = __float2bfloat16(accq[q] - __bfloat162float(h));
        g_tf_h[(size_t)n * EE + lane + 32 * q] = h;
        g_tf_l[(size_t)n * EE + lane + 32 * q] = l;
    }
}

// ============ host launcher ============
extern "C" void kernel_launch(void* const* d_in, const int* in_sizes, int n_in,
                              void* d_out, int out_size) {
    const int*   units  = (const int*)d_in[0];
    const int*   paths  = (const int*)d_in[1];
    const int*   upd    = (const int*)d_in[2];
    const int*   ppd    = (const int*)d_in[3];
    const float* emb    = (const float*)d_in[4];
    const float* tl_Wif = (const float*)d_in[5];
    const float* tl_Whf = (const float*)d_in[6];
    const float* tl_bf  = (const float*)d_in[7];
    const float* tl_Wib = (const float*)d_in[8];
    const float* tl_Whb = (const float*)d_in[9];
    const float* tl_bb  = (const float*)d_in[10];
    const float* lin_W  = (const float*)d_in[11];
    const float* lin_b  = (const float*)d_in[12];
    const float* ln_g   = (const float*)d_in[13];
    const float* ln_bv  = (const float*)d_in[14];
    const float* attn_w = (const float*)d_in[15];
    const float* attn_b = (const float*)d_in[16];
    const float* pl_Wif = (const float*)d_in[17];
    const float* pl_Whf = (const float*)d_in[18];
    const float* pl_bf  = (const float*)d_in[19];
    const float* pl_Wib = (const float*)d_in[20];
    const float* pl_Whb = (const float*)d_in[21];
    const float* pl_bb  = (const float*)d_in[22];
    const float* ul_W   = (const float*)d_in[23];
    const float* ul_b   = (const float*)d_in[24];
    float* out = (float*)d_out;

    void *pVTf, *pVTb, *pPTf, *pPTb, *pZero, *pLin;
    cudaGetSymbolAddress(&pVTf, g_VTf);    cudaGetSymbolAddress(&pVTb, g_VTb);
    cudaGetSymbolAddress(&pPTf, g_PTf);    cudaGetSymbolAddress(&pPTb, g_PTb);
    cudaGetSymbolAddress(&pZero, g_zero);  cudaGetSymbolAddress(&pLin, g_lin);
    void *pEh, *pEl, *pHch, *pHcl, *pTfh, *pTfl, *pHph, *pHpl, *pWih, *pWil, *pW2h, *pW2l;
    cudaGetSymbolAddress(&pEh, g_emb_h);   cudaGetSymbolAddress(&pEl, g_emb_l);
    cudaGetSymbolAddress(&pHch, g_Hcat_h); cudaGetSymbolAddress(&pHcl, g_Hcat_l);
    cudaGetSymbolAddress(&pTfh, g_tf_h);   cudaGetSymbolAddress(&pTfl, g_tf_l);
    cudaGetSymbolAddress(&pHph, g_Hp_h);   cudaGetSymbolAddress(&pHpl, g_Hp_l);
    cudaGetSymbolAddress(&pWih, g_Wih);    cudaGetSymbolAddress(&pWil, g_Wil);
    cudaGetSymbolAddress(&pW2h, g_W2h);    cudaGetSymbolAddress(&pW2l, g_W2l);
    __nv_bfloat16* Wih = (__nv_bfloat16*)pWih;  __nv_bfloat16* Wil = (__nv_bfloat16*)pWil;
    __nv_bfloat16* W2h = (__nv_bfloat16*)pW2h;  __nv_bfloat16* W2l = (__nv_bfloat16*)pW2l;

    const int MM_SMEM = 4 * 128 * 72 * 2;
    const int LS_T = 64 * HH * 4 + 2 * 32 * G4 * 4 + G4 * 4 + 4 * 64 * 4;   // 167936
    const int LS_P = 16 * HH * 4 + 2 * 32 * G4 * 4 + G4 * 4 + 4 * 16 * 4;   // 141568
    cudaFuncSetAttribute(k_mm2<128>, cudaFuncAttributeMaxDynamicSharedMemorySize, MM_SMEM);
    cudaFuncSetAttribute(k_mm2<256>, cudaFuncAttributeMaxDynamicSharedMemorySize, MM_SMEM);
    cudaFuncSetAttribute((const void*)k_lstm<0, TT, NU, 64, 512>,
                         cudaFuncAttributeMaxDynamicSharedMemorySize, LS_T + 1024);
    cudaFuncSetAttribute((const void*)k_lstm<1, LPATH, NPATH, 16, 256>,
                         cudaFuncAttributeMaxDynamicSharedMemorySize, LS_P + 1024);

    k_prep<<<dim3(256, 6), 256>>>(units, tl_Whf, tl_Whb, pl_Whf, pl_Whb, paths, upd, ppd);
    {
        HiloArgs a;
        a.s[0] = emb;    a.h[0] = (__nv_bfloat16*)pEh; a.l[0] = (__nv_bfloat16*)pEl; a.n[0] = VOCAB * EE / 4;
        a.s[1] = tl_Wif; a.h[1] = Wih + 0 * G4 * EE;   a.l[1] = Wil + 0 * G4 * EE;   a.n[1] = G4 * EE / 4;
        a.s[2] = tl_Wib; a.h[2] = Wih + 1 * G4 * EE;   a.l[2] = Wil + 1 * G4 * EE;   a.n[2] = G4 * EE / 4;
        a.s[3] = lin_W;  a.h[3] = W2h;                 a.l[3] = W2l;                 a.n[3] = EE * 256 / 4;
        k_hilo_multi<<<dim3((VOCAB * EE / 4 + 255) / 256, 4), 256>>>(a);
    }
    k_mm2<128><<<dim3(4, VOCAB / 128, 2), 256, MM_SMEM>>>(
        (const __nv_bfloat16*)pEh, (const __nv_bfloat16*)pEl,
        Wih + 0 * G4 * EE, Wil + 0 * G4 * EE, tl_bf, (float*)pVTf,
        Wih + 1 * G4 * EE, Wil + 1 * G4 * EE, tl_bb, (float*)pVTb, G4);
    // launch 3 (PROFILE TARGET): token BiLSTM
    k_lstm<0, TT, NU, 64, 512><<<dim3(NU / 64, 2), 512, LS_T>>>(
        units, (const float*)pVTf, (const float*)pVTb, nullptr, nullptr,
        (__nv_bfloat16*)pHch, (__nv_bfloat16*)pHcl);
    {
        HiloArgs a;
        a.s[0] = pl_Wif; a.h[0] = Wih + 2 * G4 * EE; a.l[0] = Wil + 2 * G4 * EE; a.n[0] = G4 * EE / 4;
        a.s[1] = pl_Wib; a.h[1] = Wih + 3 * G4 * EE; a.l[1] = Wil + 3 * G4 * EE; a.n[1] = G4 * EE / 4;
        a.s[2] = ul_W;   a.h[2] = W2h + EE * 256;    a.l[2] = W2l + EE * 256;    a.n[2] = EE * 256 / 4;
        a.s[3] = ul_W;   a.h[3] = W2h + EE * 256;    a.l[3] = W2l + EE * 256;    a.n[3] = 0;
        k_hilo_multi<<<dim3((G4 * EE / 4 + 255) / 256, 4), 256>>>(a);
    }
    k_mm2<256><<<dim3(1, TT * NU / 128, 1), 256, MM_SMEM>>>(
        (const __nv_bfloat16*)pHch, (const __nv_bfloat16*)pHcl,
        W2h, W2l, lin_b, (float*)pLin, W2h, W2l, lin_b, (float*)pLin, EE);
    k_attn<<<(NU * 32) / 256, 256>>>(ln_g, ln_bv, attn_w, attn_b);
    k_mm2<128><<<dim3(4, NU / 128, 2), 256, MM_SMEM>>>(
        (const __nv_bfloat16*)pTfh, (const __nv_bfloat16*)pTfl,
        Wih + 2 * G4 * EE, Wil + 2 * G4 * EE, (const float*)pZero, (float*)pPTf,
        Wih + 3 * G4 * EE, Wil + 3 * G4 * EE, (const float*)pZero, (float*)pPTb, G4);
    k_lstm<1, LPATH, NPATH, 16, 256><<<dim3(NPATH / 16, 2), 256, LS_P>>>(
        paths, (const float*)pPTf, (const float*)pPTb, pl_bf, pl_bb,
        (__nv_bfloat16*)pHph, (__nv_bfloat16*)pHpl);
    k_mm2<256><<<dim3(1, LPATH * NPATH / 128, 1), 256, MM_SMEM>>>(
        (const __nv_bfloat16*)pHph, (const __nv_bfloat16*)pHpl,
        W2h + EE * 256, W2l + EE * 256, ul_b, out,
        W2h + EE * 256, W2l + EE * 256, ul_b, out, EE);
}

// round 16
// speedup vs baseline: 1.5467x; 1.0107x over previous
#include <cuda_runtime.h>
#include <cuda_bf16.h>
#include <cstdint>

#define TT 16
#define NU 4096
#define EE 128
#define HH 128
#define G4 512
#define LPATH 32
#define NPATH 1024
#define NB 8
#define VOCAB 16384

typedef unsigned long long u64;

__device__ __forceinline__ uint32_t smem_to_u32(const void* p) {
    uint32_t a;
    asm("{ .reg .u64 t; cvta.to.shared.u64 t, %1; cvt.u32.u64 %0, t; }" : "=r"(a) : "l"(p));
    return a;
}
#define LDSM_X4(r, addr) \
    asm volatile("ldmatrix.sync.aligned.m8n8.x4.shared.b16 {%0,%1,%2,%3}, [%4];" \
        : "=r"((r)[0]), "=r"((r)[1]), "=r"((r)[2]), "=r"((r)[3]) : "r"(addr))
__device__ __forceinline__ void mma16816(float* c, const uint32_t* a, uint32_t b0, uint32_t b1) {
    asm volatile("mma.sync.aligned.m16n8k16.row.col.f32.bf16.bf16.f32 "
        "{%0,%1,%2,%3}, {%4,%5,%6,%7}, {%8,%9}, {%0,%1,%2,%3};"
        : "+f"(c[0]), "+f"(c[1]), "+f"(c[2]), "+f"(c[3])
        : "r"(a[0]), "r"(a[1]), "r"(a[2]), "r"(a[3]), "r"(b0), "r"(b1));
}
__device__ __forceinline__ void ffma2(u64& d, u64 a, u64 b) {
    asm("fma.rn.f32x2 %0, %1, %2, %0;" : "+l"(d) : "l"(a), "l"(b));
}
__device__ __forceinline__ u64 dup2(float x) {
    u64 r; asm("mov.b64 %0, {%1, %1};" : "=l"(r) : "f"(x)); return r;
}
__device__ __forceinline__ float2 unpack2(u64 v) {
    float2 f; asm("mov.b64 {%0, %1}, %2;" : "=f"(f.x), "=f"(f.y) : "l"(v)); return f;
}
#define CP_ASYNC16(dst_u32, src_ptr) \
    asm volatile("cp.async.cg.shared.global [%0], [%1], 16;" :: "r"(dst_u32), "l"(src_ptr))
#define CP_COMMIT asm volatile("cp.async.commit_group;" ::: "memory")
#define CP_WAIT0  asm volatile("cp.async.wait_group 0;" ::: "memory")
#define BAR_HALF(id, cnt) asm volatile("bar.sync %0, %1;" :: "r"(id), "r"(cnt) : "memory")

__device__ __forceinline__ float sigm(float x) {
    return __fdividef(1.f, 1.f + __expf(-x));
}
__device__ __forceinline__ float ftanh(float x) {
    float e = __expf(2.f * fabsf(x));
    return copysignf(1.f - __fdividef(2.f, e + 1.f), x);
}

// ============ device scratch ============
__device__ int   g_tok_len[NU];
__device__ int   g_p_len[NPATH], g_p_fe[NPATH], g_p_off[NPATH], g_p_un[NPATH];
__device__ float g_VTf[VOCAB * G4], g_VTb[VOCAB * G4];
__device__ float g_PTf[NU * G4],    g_PTb[NU * G4];
__device__ float g_lin[TT * NU * EE];
__device__ float g_WhT[4][HH * G4];
__device__ float g_zero[G4];
__device__ __nv_bfloat16 g_emb_h[VOCAB * EE],  g_emb_l[VOCAB * EE];
__device__ __nv_bfloat16 g_Hcat_h[TT * NU * 2 * HH], g_Hcat_l[TT * NU * 2 * HH];
__device__ __nv_bfloat16 g_tf_h[NU * EE], g_tf_l[NU * EE];
__device__ __nv_bfloat16 g_Hp_h[LPATH * NPATH * 2 * HH], g_Hp_l[LPATH * NPATH * 2 * HH];
__device__ __nv_bfloat16 g_Wih[4][G4 * EE], g_Wil[4][G4 * EE];
__device__ __nv_bfloat16 g_W2h[2][EE * 2 * HH], g_W2l[2][EE * 2 * HH];

// ============ fused setup ============
__global__ void k_prep(const int* __restrict__ units,
                       const float* __restrict__ W0, const float* __restrict__ W1,
                       const float* __restrict__ W2, const float* __restrict__ W3,
                       const int* __restrict__ paths,
                       const int* __restrict__ upd, const int* __restrict__ ppd) {
    int seg = blockIdx.y;
    int idx = blockIdx.x * blockDim.x + threadIdx.x;
    if (seg == 0) {
        if (idx >= NU) return;
        int len = TT;
        for (int t = 0; t < TT; t++) if (units[t * NU + idx] == 0) { len = t; break; }
        g_tok_len[idx] = len;
    } else if (seg <= 4) {
        if (idx >= G4 * HH) return;
        const float* W = (seg == 1) ? W0 : (seg == 2) ? W1 : (seg == 3) ? W2 : W3;
        int j = idx >> 7, k = idx & 127;
        g_WhT[seg - 1][k * G4 + j] = W[idx];
    } else {
        int p = idx;
        if (p >= NPATH) return;
        int dd = NB - 1, cum = 0;
        for (int i = 0; i < NB; i++) { int nx = cum + ppd[i]; if (p >= cum && p < nx) { dd = i; break; } cum = nx; }
        int off = 0;
        for (int i = 0; i < dd; i++) off += upd[i];
        int un = upd[dd];
        int fe = LPATH;
        for (int t = 0; t < LPATH; t++) if (paths[t * NPATH + p] == -1) { fe = t; break; }
        int plen = LPATH;
        for (int t = 0; t < LPATH; t++) {
            bool msk;
            if (t >= fe) msk = true;
            else { int v = paths[t * NPATH + p]; msk = (v < 0) || (v > un); }
            if (msk) { plen = t; break; }
        }
        g_p_len[p] = plen; g_p_fe[p] = fe; g_p_off[p] = off; g_p_un[p] = un;
    }
}

__device__ __forceinline__ void hilo_one(const float* src, __nv_bfloat16* hi,
                                         __nv_bfloat16* lo, int i) {
    float4 v = reinterpret_cast<const float4*>(src)[i];
    __nv_bfloat16 h0 = __float2bfloat16(v.x), h1 = __float2bfloat16(v.y);
    __nv_bfloat16 h2 = __float2bfloat16(v.z), h3 = __float2bfloat16(v.w);
    __nv_bfloat162* H = reinterpret_cast<__nv_bfloat162*>(hi);
    __nv_bfloat162* L = reinterpret_cast<__nv_bfloat162*>(lo);
    H[2 * i] = __nv_bfloat162(h0, h1); H[2 * i + 1] = __nv_bfloat162(h2, h3);
    L[2 * i] = __nv_bfloat162(__float2bfloat16(v.x - __bfloat162float(h0)),
                              __float2bfloat16(v.y - __bfloat162float(h1)));
    L[2 * i + 1] = __nv_bfloat162(__float2bfloat16(v.z - __bfloat162float(h2)),
                                  __float2bfloat16(v.w - __bfloat162float(h3)));
}
struct HiloArgs { const float* s[4]; __nv_bfloat16* h[4]; __nv_bfloat16* l[4]; int n[4]; };
__global__ void k_hilo_multi(HiloArgs a) {
    int seg = blockIdx.y;
    int i = blockIdx.x * blockDim.x + threadIdx.x;
    if (i < a.n[seg]) hilo_one(a.s[seg], a.h[seg], a.l[seg], i);
}

// ============ warp-MMA split-bf16 GEMM (dual via gridDim.z; passing) ============
template <int K>
__global__ __launch_bounds__(256) void k_mm2(
    const __nv_bfloat16* __restrict__ Ah, const __nv_bfloat16* __restrict__ Al,
    const __nv_bfloat16* __restrict__ Bh0, const __nv_bfloat16* __restrict__ Bl0,
    const float* __restrict__ bias0, float* __restrict__ C0,
    const __nv_bfloat16* __restrict__ Bh1, const __nv_bfloat16* __restrict__ Bl1,
    const float* __restrict__ bias1, float* __restrict__ C1, int Ntot)
{
    const __nv_bfloat16* __restrict__ Bh = blockIdx.z ? Bh1 : Bh0;
    const __nv_bfloat16* __restrict__ Bl = blockIdx.z ? Bl1 : Bl0;
    const float* __restrict__ bias = blockIdx.z ? bias1 : bias0;
    float* __restrict__ C = blockIdx.z ? C1 : C0;

    constexpr int LDS = 72;
    extern __shared__ __nv_bfloat16 sm[];
    __nv_bfloat16* sAh = sm;
    __nv_bfloat16* sAl = sAh + 128 * LDS;
    __nv_bfloat16* sBh = sAl + 128 * LDS;
    __nv_bfloat16* sBl = sBh + 128 * LDS;

    const int tid = threadIdx.x, lane = tid & 31, wid = tid >> 5;
    const int m0 = blockIdx.y * 128, n0 = blockIdx.x * 128;
    const int wm = (wid & 3) * 32, wn = (wid >> 2) * 64;
    const int g = lane >> 2, tg = lane & 3;
    const int seg = lane >> 3, i8 = lane & 7;
    const uint32_t sAh_b = smem_to_u32(sAh), sAl_b = smem_to_u32(sAl);
    const uint32_t sBh_b = smem_to_u32(sBh), sBl_b = smem_to_u32(sBl);

    float acc[2][8][4];
#pragma unroll
    for (int im = 0; im < 2; im++)
#pragma unroll
        for (int jn = 0; jn < 8; jn++)
#pragma unroll
            for (int q = 0; q < 4; q++) acc[im][jn][q] = 0.f;

    for (int kc = 0; kc < K; kc += 64) {
        if (kc) __syncthreads();
        {
            const __nv_bfloat16* srcs[4] = {Ah, Al, Bh, Bl};
            __nv_bfloat16* dsts[4] = {sAh, sAl, sBh, sBl};
            const int r0s[4] = {m0, m0, n0, n0};
#pragma unroll
            for (int t = 0; t < 4; t++) {
                for (int v = tid; v < 1024; v += 256) {
                    int row = v >> 3, q = (v & 7) * 8;
                    *reinterpret_cast<uint4*>(dsts[t] + row * LDS + q) =
                        *reinterpret_cast<const uint4*>(srcs[t] + (size_t)(r0s[t] + row) * K + kc + q);
                }
            }
        }
        __syncthreads();
#pragma unroll
        for (int ks = 0; ks < 4; ks++) {
            const int k0 = ks * 16;
            uint32_t ah[2][4], al[2][4];
#pragma unroll
            for (int im = 0; im < 2; im++) {
                int arow = wm + im * 16 + (seg & 1) * 8 + i8;
                int acol = k0 + (seg >> 1) * 8;
                LDSM_X4(ah[im], sAh_b + (uint32_t)(arow * LDS + acol) * 2u);
                LDSM_X4(al[im], sAl_b + (uint32_t)(arow * LDS + acol) * 2u);
            }
#pragma unroll
            for (int ip = 0; ip < 4; ip++) {
                int brow = wn + ip * 16 + (seg >> 1) * 8 + i8;
                int bcol = k0 + (seg & 1) * 8;
                uint32_t bh4[4], bl4[4];
                LDSM_X4(bh4, sBh_b + (uint32_t)(brow * LDS + bcol) * 2u);
                LDSM_X4(bl4, sBl_b + (uint32_t)(brow * LDS + bcol) * 2u);
#pragma unroll
                for (int im = 0; im < 2; im++) {
#pragma unroll
                    for (int hf = 0; hf < 2; hf++) {
                        float* c = acc[im][ip * 2 + hf];
                        mma16816(c, ah[im], bh4[2 * hf], bh4[2 * hf + 1]);
                        mma16816(c, al[im], bh4[2 * hf], bh4[2 * hf + 1]);
                        mma16816(c, ah[im], bl4[2 * hf], bl4[2 * hf + 1]);
                    }
                }
            }
        }
    }
#pragma unroll
    for (int im = 0; im < 2; im++) {
#pragma unroll
        for (int jn = 0; jn < 8; jn++) {
            int col = n0 + wn + jn * 8 + tg * 2;
            float b0v = bias[col], b1v = bias[col + 1];
            int row0 = m0 + wm + im * 16 + g;
            float2 v0 = make_float2(acc[im][jn][0] + b0v, acc[im][jn][1] + b1v);
            float2 v1 = make_float2(acc[im][jn][2] + b0v, acc[im][jn][3] + b1v);
            *reinterpret_cast<float2*>(C + (size_t)row0 * Ntot + col) = v0;
            *reinterpret_cast<float2*>(C + (size_t)(row0 + 8) * Ntot + col) = v1;
        }
    }
}

// ============ persistent BiLSTM: BOTH dirs in one CTA (warp-specialized halves) ============
// Half h = warps [h*NWH, (h+1)*NWH) handles direction h for the CTA's ROWS rows.
// Within a half: ch = hwid&1 (column half), rg = hwid>>1; thread owns cols e0,e0+1
// of all 4 gate blocks for RPT rows (R15 inner loop, unchanged). Per-half 16k-chunk
// cp.async double buffer + per-half named barriers -> one half's pointwise/MUFU
// overlaps the other half's GEMV FMA stream.
template <int MODE, int TSTEPS, int NSEQ, int ROWS, int THREADS>
__global__ __launch_bounds__(THREADS) void k_lstm(
    const int* __restrict__ idxmat,
    const float* __restrict__ tab_f, const float* __restrict__ tab_b,
    const float* __restrict__ bias_f, const float* __restrict__ bias_b,
    __nv_bfloat16* __restrict__ Hh, __nv_bfloat16* __restrict__ Hl)
{
    constexpr int HALF = THREADS / 2, NWH = HALF / 32, RG = NWH / 2, RPT = ROWS / RG;
    constexpr int CHF = 16 * G4;                 // 8192 floats per 16-k chunk
    constexpr int NCP = (CHF / 4) / HALF;
    extern __shared__ char dsm[];
    float* hs    = reinterpret_cast<float*>(dsm);      // [2][ROWS][HH]
    float* wbuf  = hs + 2 * ROWS * HH;                 // [2][2][CHF]
    float* sbias = wbuf + 4 * CHF;                     // [2][G4]
    int* slen = reinterpret_cast<int*>(sbias + 2 * G4);
    int* sfe = slen + ROWS; int* soff = sfe + ROWS; int* sun = soff + ROWS;

    const int tid = threadIdx.x, lane = tid & 31, wid = tid >> 5;
    const int half = (wid >= NWH) ? 1 : 0;
    const int hwid = wid - half * NWH, htid = tid - half * HALF;
    const int dir = half;
    const float* __restrict__ tab = dir ? tab_b : tab_f;
    const float* __restrict__ WhT = g_WhT[2 * MODE + dir];
    const int ch = hwid & 1, rg = hwid >> 1;
    const int e0 = ch * 64 + lane * 2;
    const int r0 = rg * RPT;
    const int n0 = blockIdx.x * ROWS;
    float* hsd = hs + dir * ROWS * HH;
    float* wbd = wbuf + dir * 2 * CHF;
    float* sbd = sbias + dir * G4;
    const uint32_t wbd_a = smem_to_u32(wbd);
    const int barid = 1 + half;

    if (MODE == 1) {
        const float* b = dir ? bias_b : bias_f;
        for (int i = htid; i < G4; i += HALF) sbd[i] = b[i];
    }
    float cst[RPT][2];
#pragma unroll
    for (int r = 0; r < RPT; r++) { cst[r][0] = 0.f; cst[r][1] = 0.f; }
    for (int i = tid; i < 2 * ROWS * HH / 4; i += THREADS)
        reinterpret_cast<float4*>(hs)[i] = make_float4(0.f, 0.f, 0.f, 0.f);
    if (tid < ROWS) {
        int n = n0 + tid;
        slen[tid] = MODE ? g_p_len[n] : g_tok_len[n];
        if (MODE) { sfe[tid] = g_p_fe[n]; soff[tid] = g_p_off[n]; sun[tid] = g_p_un[n]; }
    }
    for (int i = htid; i < CHF / 4; i += HALF)
        reinterpret_cast<float4*>(wbd)[i] = reinterpret_cast<const float4*>(WhT)[i];
    __syncthreads();

    for (int s = 0; s < TSTEPS; s++) {
        u64 acc[RPT][4];
#pragma unroll
        for (int r = 0; r < RPT; r++)
#pragma unroll
            for (int g = 0; g < 4; g++) acc[r][g] = 0ull;

#pragma unroll
        for (int cno = 0; cno < 8; cno++) {
            {   // per-half async-prefetch of next 16-k chunk
                const int nxt = (cno + 1) & 7;
                const float4* src = reinterpret_cast<const float4*>(WhT + nxt * CHF);
                uint32_t dsta = wbd_a + (uint32_t)(((cno + 1) & 1) * CHF) * 4u;
#pragma unroll
                for (int t = 0; t < NCP; t++)
                    CP_ASYNC16(dsta + (uint32_t)(htid + t * HALF) * 16u, src + htid + t * HALF);
                CP_COMMIT;
            }
            const float* wcur = wbd + (cno & 1) * CHF;
#pragma unroll
            for (int kp = 0; kp < 8; kp++) {
                const int kk = kp * 2;
                u64 w0i = *reinterpret_cast<const u64*>(&wcur[kk * G4 + e0]);
                u64 w0f = *reinterpret_cast<const u64*>(&wcur[kk * G4 + 128 + e0]);
                u64 w0g = *reinterpret_cast<const u64*>(&wcur[kk * G4 + 256 + e0]);
                u64 w0o = *reinterpret_cast<const u64*>(&wcur[kk * G4 + 384 + e0]);
                u64 w1i = *reinterpret_cast<const u64*>(&wcur[(kk + 1) * G4 + e0]);
                u64 w1f = *reinterpret_cast<const u64*>(&wcur[(kk + 1) * G4 + 128 + e0]);
                u64 w1g = *reinterpret_cast<const u64*>(&wcur[(kk + 1) * G4 + 256 + e0]);
                u64 w1o = *reinterpret_cast<const u64*>(&wcur[(kk + 1) * G4 + 384 + e0]);
#pragma unroll
                for (int r = 0; r < RPT; r++) {
                    float2 hp = *reinterpret_cast<const float2*>(&hsd[(r0 + r) * HH + cno * 16 + kk]);
                    u64 ha = dup2(hp.x), hb = dup2(hp.y);
                    ffma2(acc[r][0], ha, w0i); ffma2(acc[r][1], ha, w0f);
                    ffma2(acc[r][2], ha, w0g); ffma2(acc[r][3], ha, w0o);
                    ffma2(acc[r][0], hb, w1i); ffma2(acc[r][1], hb, w1f);
                    ffma2(acc[r][2], hb, w1g); ffma2(acc[r][3], hb, w1o);
                }
            }
            CP_WAIT0;
            BAR_HALF(barid, HALF);
        }

        // pointwise: thread owns cells (e0, e0+1) for rows r0..r0+RPT-1 of own dir
#pragma unroll
        for (int r = 0; r < RPT; r++) {
            const int row = r0 + r, n = n0 + row, len = slen[row];
            const int gi = dir ? min(max(len - 1 - s, 0), TSTEPS - 1) : s;
            float2 ai = unpack2(acc[r][0]), af = unpack2(acc[r][1]);
            float2 ag = unpack2(acc[r][2]), ao = unpack2(acc[r][3]);
            float2 gvi, gvf, gvg, gvo;
            if (MODE == 0) {
                int id = idxmat[(size_t)gi * NSEQ + n];
                const float* grow = tab + (size_t)id * G4;
                gvi = *reinterpret_cast<const float2*>(&grow[e0]);
                gvf = *reinterpret_cast<const float2*>(&grow[128 + e0]);
                gvg = *reinterpret_cast<const float2*>(&grow[256 + e0]);
                gvo = *reinterpret_cast<const float2*>(&grow[384 + e0]);
            } else {
                int pl = idxmat[(size_t)gi * NSEQ + n];
                bool keep = (gi < sfe[row]) && (pl >= 0) && (pl < sun[row]);
                gvi = *reinterpret_cast<const float2*>(&sbd[e0]);
                gvf = *reinterpret_cast<const float2*>(&sbd[128 + e0]);
                gvg = *reinterpret_cast<const float2*>(&sbd[256 + e0]);
                gvo = *reinterpret_cast<const float2*>(&sbd[384 + e0]);
                if (keep) {
                    int gidx = min(pl + soff[row], NU - 1);
                    const float* grow = tab + (size_t)gidx * G4;
                    float2 t0 = *reinterpret_cast<const float2*>(&grow[e0]);
                    float2 t1 = *reinterpret_cast<const float2*>(&grow[128 + e0]);
                    float2 t2 = *reinterpret_cast<const float2*>(&grow[256 + e0]);
                    float2 t3 = *reinterpret_cast<const float2*>(&grow[384 + e0]);
                    gvi.x += t0.x; gvi.y += t0.y; gvf.x += t1.x; gvf.y += t1.y;
                    gvg.x += t2.x; gvg.y += t2.y; gvo.x += t3.x; gvo.y += t3.y;
                }
            }
            float h0, h1;
            {
                float iv = ai.x + gvi.x, fv = af.x + gvf.x, gg = ag.x + gvg.x, ov = ao.x + gvo.x;
                float cn = sigm(fv) * cst[r][0] + sigm(iv) * ftanh(gg);
                cst[r][0] = cn; h0 = sigm(ov) * ftanh(cn);
            }
            {
                float iv = ai.y + gvi.y, fv = af.y + gvf.y, gg = ag.y + gvg.y, ov = ao.y + gvo.y;
                float cn = sigm(fv) * cst[r][1] + sigm(iv) * ftanh(gg);
                cst[r][1] = cn; h1 = sigm(ov) * ftanh(cn);
            }
            *reinterpret_cast<float2*>(&hsd[row * HH + e0]) = make_float2(h0, h1);
            __nv_bfloat16 hb0 = __float2bfloat16(h0), hb1 = __float2bfloat16(h1);
            __nv_bfloat162 hb(hb0, hb1);
            __nv_bfloat162 lb(__float2bfloat16(h0 - __bfloat162float(hb0)),
                              __float2bfloat16(h1 - __bfloat162float(hb1)));
            if (s < len) {
                int wi = dir ? (len - 1 - s) : s;
                size_t base = ((size_t)wi * NSEQ + n) * (2 * HH) + dir * HH + e0;
                *reinterpret_cast<__nv_bfloat162*>(Hh + base) = hb;
                *reinterpret_cast<__nv_bfloat162*>(Hl + base) = lb;
            } else if (dir == 0) {
                __nv_bfloat162 z(__float2bfloat16(0.f), __float2bfloat16(0.f));
                size_t b0 = ((size_t)s * NSEQ + n) * (2 * HH) + e0;
                *reinterpret_cast<__nv_bfloat162*>(Hh + b0) = z;
                *reinterpret_cast<__nv_bfloat162*>(Hl + b0) = z;
                *reinterpret_cast<__nv_bfloat162*>(Hh + b0 + HH) = z;
                *reinterpret_cast<__nv_bfloat162*>(Hl + b0 + HH) = z;
            }
        }
        BAR_HALF(barid, HALF);
    }
}

// ============ attention pooling ============
__global__ void k_attn(const float* __restrict__ ln_g, const float* __restrict__ ln_b,
                       const float* __restrict__ attn_w, const float* __restrict__ attn_bp) {
    int gwarp = (blockIdx.x * blockDim.x + threadIdx.x) >> 5;
    int lane = threadIdx.x & 31;
    if (gwarp >= NU) return;
    int n = gwarp, len = g_tok_len[n];
    float gg[4], bb[4], aw[4];
#pragma unroll
    for (int q = 0; q < 4; q++) {
        int e = lane + 32 * q;
        gg[q] = ln_g[e]; bb[q] = ln_b[e]; aw[q] = attn_w[e];
    }
    float ab = attn_bp[0];
    float sc[TT], smax = -1e30f;
#pragma unroll
    for (int t = 0; t < TT; t++) {
        sc[t] = -1e30f;
        if (t < len) {
            float o[4], lsum = 0.f;
#pragma unroll
            for (int q = 0; q < 4; q++) {
                o[q] = g_lin[((size_t)t * NU + n) * EE + lane + 32 * q];
                lsum += o[q];
            }
#pragma unroll
            for (int off = 16; off; off >>= 1) lsum += __shfl_xor_sync(0xffffffffu, lsum, off);
            float mean = lsum * (1.f / 128.f);
            float vs = 0.f;
#pragma unroll
            for (int q = 0; q < 4; q++) { float d = o[q] - mean; vs += d * d; }
#pragma unroll
            for (int off = 16; off; off >>= 1) vs += __shfl_xor_sync(0xffffffffu, vs, off);
            float inv = rsqrtf(vs * (1.f / 128.f) + 1e-5f);
            float ssum = 0.f;
#pragma unroll
            for (int q = 0; q < 4; q++)
                ssum += ftanh((o[q] - mean) * inv * gg[q] + bb[q]) * aw[q];
#pragma unroll
            for (int off = 16; off; off >>= 1) ssum += __shfl_xor_sync(0xffffffffu, ssum, off);
            sc[t] = ssum + ab;
            smax = fmaxf(smax, sc[t]);
        }
    }
    float den = 0.f, wts[TT];
#pragma unroll
    for (int t = 0; t < TT; t++) {
        wts[t] = (t < len) ? __expf(sc[t] - smax) : 0.f;
        den += wts[t];
    }
    float invden = 1.f / den;
    float accq[4] = {0.f, 0.f, 0.f, 0.f};
#pragma unroll
    for (int t = 0; t < TT; t++) {
        if (t < len) {
            float wt = wts[t] * invden;
#pragma unroll
            for (int q = 0; q < 4; q++)
                accq[q] += wt * g_lin[((size_t)t * NU + n) * EE + lane + 32 * q];
        }
    }
#pragma unroll
    for (int q = 0; q < 4; q++) {
        __nv_bfloat16 h = __float2bfloat16(accq[q]);
        __nv_bfloat16 l = __float2bfloat16(accq[q] - __bfloat162float(h));
        g_tf_h[(size_t)n * EE + lane + 32 * q] = h;
        g_tf_l[(size_t)n * EE + lane + 32 * q] = l;
    }
}

// ============ host launcher ============
extern "C" void kernel_launch(void* const* d_in, const int* in_sizes, int n_in,
                              void* d_out, int out_size) {
    const int*   units  = (const int*)d_in[0];
    const int*   paths  = (const int*)d_in[1];
    const int*   upd    = (const int*)d_in[2];
    const int*   ppd    = (const int*)d_in[3];
    const float* emb    = (const float*)d_in[4];
    const float* tl_Wif = (const float*)d_in[5];
    const float* tl_Whf = (const float*)d_in[6];
    const float* tl_bf  = (const float*)d_in[7];
    const float* tl_Wib = (const float*)d_in[8];
    const float* tl_Whb = (const float*)d_in[9];
    const float* tl_bb  = (const float*)d_in[10];
    const float* lin_W  = (const float*)d_in[11];
    const float* lin_b  = (const float*)d_in[12];
    const float* ln_g   = (const float*)d_in[13];
    const float* ln_bv  = (const float*)d_in[14];
    const float* attn_w = (const float*)d_in[15];
    const float* attn_b = (const float*)d_in[16];
    const float* pl_Wif = (const float*)d_in[17];
    const float* pl_Whf = (const float*)d_in[18];
    const float* pl_bf  = (const float*)d_in[19];
    const float* pl_Wib = (const float*)d_in[20];
    const float* pl_Whb = (const float*)d_in[21];
    const float* pl_bb  = (const float*)d_in[22];
    const float* ul_W   = (const float*)d_in[23];
    const float* ul_b   = (const float*)d_in[24];
    float* out = (float*)d_out;

    void *pVTf, *pVTb, *pPTf, *pPTb, *pZero, *pLin;
    cudaGetSymbolAddress(&pVTf, g_VTf);    cudaGetSymbolAddress(&pVTb, g_VTb);
    cudaGetSymbolAddress(&pPTf, g_PTf);    cudaGetSymbolAddress(&pPTb, g_PTb);
    cudaGetSymbolAddress(&pZero, g_zero);  cudaGetSymbolAddress(&pLin, g_lin);
    void *pEh, *pEl, *pHch, *pHcl, *pTfh, *pTfl, *pHph, *pHpl, *pWih, *pWil, *pW2h, *pW2l;
    cudaGetSymbolAddress(&pEh, g_emb_h);   cudaGetSymbolAddress(&pEl, g_emb_l);
    cudaGetSymbolAddress(&pHch, g_Hcat_h); cudaGetSymbolAddress(&pHcl, g_Hcat_l);
    cudaGetSymbolAddress(&pTfh, g_tf_h);   cudaGetSymbolAddress(&pTfl, g_tf_l);
    cudaGetSymbolAddress(&pHph, g_Hp_h);   cudaGetSymbolAddress(&pHpl, g_Hp_l);
    cudaGetSymbolAddress(&pWih, g_Wih);    cudaGetSymbolAddress(&pWil, g_Wil);
    cudaGetSymbolAddress(&pW2h, g_W2h);    cudaGetSymbolAddress(&pW2l, g_W2l);
    __nv_bfloat16* Wih = (__nv_bfloat16*)pWih;  __nv_bfloat16* Wil = (__nv_bfloat16*)pWil;
    __nv_bfloat16* W2h = (__nv_bfloat16*)pW2h;  __nv_bfloat16* W2l = (__nv_bfloat16*)pW2l;

    const int MM_SMEM = 4 * 128 * 72 * 2;
    // [2][ROWS][HH] + [2][2][CHF=8192] + [2][G4] + meta
    const int LS_T = 2 * 32 * HH * 4 + 4 * 8192 * 4 + 2 * G4 * 4 + 4 * 32 * 4;  // 168448
    const int LS_P = 2 * 8 * HH * 4 + 4 * 8192 * 4 + 2 * G4 * 4 + 4 * 8 * 4;    // 143616
    cudaFuncSetAttribute(k_mm2<128>, cudaFuncAttributeMaxDynamicSharedMemorySize, MM_SMEM);
    cudaFuncSetAttribute(k_mm2<256>, cudaFuncAttributeMaxDynamicSharedMemorySize, MM_SMEM);
    cudaFuncSetAttribute((const void*)k_lstm<0, TT, NU, 32, 512>,
                         cudaFuncAttributeMaxDynamicSharedMemorySize, LS_T + 1024);
    cudaFuncSetAttribute((const void*)k_lstm<1, LPATH, NPATH, 8, 256>,
                         cudaFuncAttributeMaxDynamicSharedMemorySize, LS_P + 1024);

    k_prep<<<dim3(256, 6), 256>>>(units, tl_Whf, tl_Whb, pl_Whf, pl_Whb, paths, upd, ppd);
    {
        HiloArgs a;
        a.s[0] = emb;    a.h[0] = (__nv_bfloat16*)pEh; a.l[0] = (__nv_bfloat16*)pEl; a.n[0] = VOCAB * EE / 4;
        a.s[1] = tl_Wif; a.h[1] = Wih + 0 * G4 * EE;   a.l[1] = Wil + 0 * G4 * EE;   a.n[1] = G4 * EE / 4;
        a.s[2] = tl_Wib; a.h[2] = Wih + 1 * G4 * EE;   a.l[2] = Wil + 1 * G4 * EE;   a.n[2] = G4 * EE / 4;
        a.s[3] = lin_W;  a.h[3] = W2h;                 a.l[3] = W2l;                 a.n[3] = EE * 256 / 4;
        k_hilo_multi<<<dim3((VOCAB * EE / 4 + 255) / 256, 4), 256>>>(a);
    }
    k_mm2<128><<<dim3(4, VOCAB / 128, 2), 256, MM_SMEM>>>(
        (const __nv_bfloat16*)pEh, (const __nv_bfloat16*)pEl,
        Wih + 0 * G4 * EE, Wil + 0 * G4 * EE, tl_bf, (float*)pVTf,
        Wih + 1 * G4 * EE, Wil + 1 * G4 * EE, tl_bb, (float*)pVTb, G4);
    // launch 3 (PROFILE TARGET): token BiLSTM (both dirs per CTA)
    k_lstm<0, TT, NU, 32, 512><<<NU / 32, 512, LS_T>>>(
        units, (const float*)pVTf, (const float*)pVTb, nullptr, nullptr,
        (__nv_bfloat16*)pHch, (__nv_bfloat16*)pHcl);
    {
        HiloArgs a;
        a.s[0] = pl_Wif; a.h[0] = Wih + 2 * G4 * EE; a.l[0] = Wil + 2 * G4 * EE; a.n[0] = G4 * EE / 4;
        a.s[1] = pl_Wib; a.h[1] = Wih + 3 * G4 * EE; a.l[1] = Wil + 3 * G4 * EE; a.n[1] = G4 * EE / 4;
        a.s[2] = ul_W;   a.h[2] = W2h + EE * 256;    a.l[2] = W2l + EE * 256;    a.n[2] = EE * 256 / 4;
        a.s[3] = ul_W;   a.h[3] = W2h + EE * 256;    a.l[3] = W2l + EE * 256;    a.n[3] = 0;
        k_hilo_multi<<<dim3((G4 * EE / 4 + 255) / 256, 4), 256>>>(a);
    }
    k_mm2<256><<<dim3(1, TT * NU / 128, 1), 256, MM_SMEM>>>(
        (const __nv_bfloat16*)pHch, (const __nv_bfloat16*)pHcl,
        W2h, W2l, lin_b, (float*)pLin, W2h, W2l, lin_b, (float*)pLin, EE);
    k_attn<<<(NU * 32) / 256, 256>>>(ln_g, ln_bv, attn_w, attn_b);
    k_mm2<128><<<dim3(4, NU / 128, 2), 256, MM_SMEM>>>(
        (const __nv_bfloat16*)pTfh, (const __nv_bfloat16*)pTfl,
        Wih + 2 * G4 * EE, Wil + 2 * G4 * EE, (const float*)pZero, (float*)pPTf,
        Wih + 3 * G4 * EE, Wil + 3 * G4 * EE, (const float*)pZero, (float*)pPTb, G4);
    k_lstm<1, LPATH, NPATH, 8, 256><<<NPATH / 8, 256, LS_P>>>(
        paths, (const float*)pPTf, (const float*)pPTb, pl_bf, pl_bb,
        (__nv_bfloat16*)pHph, (__nv_bfloat16*)pHpl);
    k_mm2<256><<<dim3(1, LPATH * NPATH / 128, 1), 256, MM_SMEM>>>(
        (const __nv_bfloat16*)pHph, (const __nv_bfloat16*)pHpl,
        W2h + EE * 256, W2l + EE * 256, ul_b, out,
        W2h + EE * 256, W2l + EE * 256, ul_b, out, EE);
}

// round 17
// speedup vs baseline: 1.8044x; 1.1666x over previous
#include <cuda_runtime.h>
#include <cuda_bf16.h>
#include <cstdint>

#define TT 16
#define NU 4096
#define EE 128
#define HH 128
#define G4 512
#define LPATH 32
#define NPATH 1024
#define NB 8
#define VOCAB 16384

typedef unsigned long long u64;

__device__ __forceinline__ uint32_t smem_to_u32(const void* p) {
    uint32_t a;
    asm("{ .reg .u64 t; cvta.to.shared.u64 t, %1; cvt.u32.u64 %0, t; }" : "=r"(a) : "l"(p));
    return a;
}
#define LDSM_X4(r, addr) \
    asm volatile("ldmatrix.sync.aligned.m8n8.x4.shared.b16 {%0,%1,%2,%3}, [%4];" \
        : "=r"((r)[0]), "=r"((r)[1]), "=r"((r)[2]), "=r"((r)[3]) : "r"(addr))
__device__ __forceinline__ void mma16816(float* c, const uint32_t* a, uint32_t b0, uint32_t b1) {
    asm volatile("mma.sync.aligned.m16n8k16.row.col.f32.bf16.bf16.f32 "
        "{%0,%1,%2,%3}, {%4,%5,%6,%7}, {%8,%9}, {%0,%1,%2,%3};"
        : "+f"(c[0]), "+f"(c[1]), "+f"(c[2]), "+f"(c[3])
        : "r"(a[0]), "r"(a[1]), "r"(a[2]), "r"(a[3]), "r"(b0), "r"(b1));
}
__device__ __forceinline__ void ffma2(u64& d, u64 a, u64 b) {
    asm("fma.rn.f32x2 %0, %1, %2, %0;" : "+l"(d) : "l"(a), "l"(b));
}
__device__ __forceinline__ u64 dup2(float x) {
    u64 r; asm("mov.b64 %0, {%1, %1};" : "=l"(r) : "f"(x)); return r;
}
__device__ __forceinline__ float2 unpack2(u64 v) {
    float2 f; asm("mov.b64 {%0, %1}, %2;" : "=f"(f.x), "=f"(f.y) : "l"(v)); return f;
}
#define CP_ASYNC16(dst_u32, src_ptr) \
    asm volatile("cp.async.cg.shared.global [%0], [%1], 16;" :: "r"(dst_u32), "l"(src_ptr))
#define CP_COMMIT asm volatile("cp.async.commit_group;" ::: "memory")
#define CP_WAIT0  asm volatile("cp.async.wait_group 0;" ::: "memory")
#define BAR_HALF(id, cnt) asm volatile("bar.sync %0, %1;" :: "r"(id), "r"(cnt) : "memory")

__device__ __forceinline__ float sigm(float x) {
    return __fdividef(1.f, 1.f + __expf(-x));
}
__device__ __forceinline__ float ftanh(float x) {
    float e = __expf(2.f * fabsf(x));
    return copysignf(1.f - __fdividef(2.f, e + 1.f), x);
}

// ============ device scratch ============
__device__ int   g_tok_len[NU];
__device__ int   g_perm_t[NU];
__device__ int   g_p_len[NPATH], g_p_fe[NPATH], g_p_off[NPATH], g_p_un[NPATH];
__device__ float g_VTf[VOCAB * G4], g_VTb[VOCAB * G4];
__device__ float g_PTf[NU * G4],    g_PTb[NU * G4];
__device__ float g_lin[TT * NU * EE];
__device__ float g_WhT[4][HH * G4];
__device__ float g_zero[G4];
__device__ __nv_bfloat16 g_emb_h[VOCAB * EE],  g_emb_l[VOCAB * EE];
__device__ __nv_bfloat16 g_Hcat_h[TT * NU * 2 * HH], g_Hcat_l[TT * NU * 2 * HH];
__device__ __nv_bfloat16 g_tf_h[NU * EE], g_tf_l[NU * EE];
__device__ __nv_bfloat16 g_Hp_h[LPATH * NPATH * 2 * HH], g_Hp_l[LPATH * NPATH * 2 * HH];
__device__ __nv_bfloat16 g_Wih[4][G4 * EE], g_Wil[4][G4 * EE];
__device__ __nv_bfloat16 g_W2h[2][EE * 2 * HH], g_W2l[2][EE * 2 * HH];

// ============ fused setup ============
__global__ void k_prep(const int* __restrict__ units,
                       const float* __restrict__ W0, const float* __restrict__ W1,
                       const float* __restrict__ W2, const float* __restrict__ W3,
                       const int* __restrict__ paths,
                       const int* __restrict__ upd, const int* __restrict__ ppd) {
    int seg = blockIdx.y;
    int idx = blockIdx.x * blockDim.x + threadIdx.x;
    if (seg == 0) {
        if (idx >= NU) return;
        int len = TT;
        for (int t = 0; t < TT; t++) if (units[t * NU + idx] == 0) { len = t; break; }
        g_tok_len[idx] = len;
    } else if (seg <= 4) {
        if (idx >= G4 * HH) return;
        const float* W = (seg == 1) ? W0 : (seg == 2) ? W1 : (seg == 3) ? W2 : W3;
        int j = idx >> 7, k = idx & 127;
        g_WhT[seg - 1][k * G4 + j] = W[idx];
    } else {
        int p = idx;
        if (p >= NPATH) return;
        int dd = NB - 1, cum = 0;
        for (int i = 0; i < NB; i++) { int nx = cum + ppd[i]; if (p >= cum && p < nx) { dd = i; break; } cum = nx; }
        int off = 0;
        for (int i = 0; i < dd; i++) off += upd[i];
        int un = upd[dd];
        int fe = LPATH;
        for (int t = 0; t < LPATH; t++) if (paths[t * NPATH + p] == -1) { fe = t; break; }
        int plen = LPATH;
        for (int t = 0; t < LPATH; t++) {
            bool msk;
            if (t >= fe) msk = true;
            else { int v = paths[t * NPATH + p]; msk = (v < 0) || (v > un); }
            if (msk) { plen = t; break; }
        }
        g_p_len[p] = plen; g_p_fe[p] = fe; g_p_off[p] = off; g_p_un[p] = un;
    }
}

// counting sort of token indices by length (ascending); one 256-thread block
__device__ void sort_tokens() {
    __shared__ int cnt[20];
    int tid = threadIdx.x;
    if (tid < 20) cnt[tid] = 0;
    __syncthreads();
    for (int i = tid; i < NU; i += blockDim.x) atomicAdd(&cnt[g_tok_len[i]], 1);
    __syncthreads();
    if (tid == 0) {
        int a = 0;
        for (int b = 0; b < 20; b++) { int c = cnt[b]; cnt[b] = a; a += c; }
    }
    __syncthreads();
    for (int i = tid; i < NU; i += blockDim.x) {
        int pos = atomicAdd(&cnt[g_tok_len[i]], 1);
        g_perm_t[pos] = i;
    }
}

__device__ __forceinline__ void hilo_one(const float* src, __nv_bfloat16* hi,
                                         __nv_bfloat16* lo, int i) {
    float4 v = reinterpret_cast<const float4*>(src)[i];
    __nv_bfloat16 h0 = __float2bfloat16(v.x), h1 = __float2bfloat16(v.y);
    __nv_bfloat16 h2 = __float2bfloat16(v.z), h3 = __float2bfloat16(v.w);
    __nv_bfloat162* H = reinterpret_cast<__nv_bfloat162*>(hi);
    __nv_bfloat162* L = reinterpret_cast<__nv_bfloat162*>(lo);
    H[2 * i] = __nv_bfloat162(h0, h1); H[2 * i + 1] = __nv_bfloat162(h2, h3);
    L[2 * i] = __nv_bfloat162(__float2bfloat16(v.x - __bfloat162float(h0)),
                              __float2bfloat16(v.y - __bfloat162float(h1)));
    L[2 * i + 1] = __nv_bfloat162(__float2bfloat16(v.z - __bfloat162float(h2)),
                                  __float2bfloat16(v.w - __bfloat162float(h3)));
}
struct HiloArgs { const float* s[4]; __nv_bfloat16* h[4]; __nv_bfloat16* l[4]; int n[4]; };
__global__ void k_hilo_multi(HiloArgs a) {
    int seg = blockIdx.y;
    if (seg >= 4) {            // seg 4: sort tokens (single block)
        if (blockIdx.x == 0) sort_tokens();
        return;
    }
    int i = blockIdx.x * blockDim.x + threadIdx.x;
    if (i < a.n[seg]) hilo_one(a.s[seg], a.h[seg], a.l[seg], i);
}

// ============ warp-MMA split-bf16 GEMM (dual via gridDim.z; passing) ============
template <int K>
__global__ __launch_bounds__(256) void k_mm2(
    const __nv_bfloat16* __restrict__ Ah, const __nv_bfloat16* __restrict__ Al,
    const __nv_bfloat16* __restrict__ Bh0, const __nv_bfloat16* __restrict__ Bl0,
    const float* __restrict__ bias0, float* __restrict__ C0,
    const __nv_bfloat16* __restrict__ Bh1, const __nv_bfloat16* __restrict__ Bl1,
    const float* __restrict__ bias1, float* __restrict__ C1, int Ntot)
{
    const __nv_bfloat16* __restrict__ Bh = blockIdx.z ? Bh1 : Bh0;
    const __nv_bfloat16* __restrict__ Bl = blockIdx.z ? Bl1 : Bl0;
    const float* __restrict__ bias = blockIdx.z ? bias1 : bias0;
    float* __restrict__ C = blockIdx.z ? C1 : C0;

    constexpr int LDS = 72;
    extern __shared__ __nv_bfloat16 sm[];
    __nv_bfloat16* sAh = sm;
    __nv_bfloat16* sAl = sAh + 128 * LDS;
    __nv_bfloat16* sBh = sAl + 128 * LDS;
    __nv_bfloat16* sBl = sBh + 128 * LDS;

    const int tid = threadIdx.x, lane = tid & 31, wid = tid >> 5;
    const int m0 = blockIdx.y * 128, n0 = blockIdx.x * 128;
    const int wm = (wid & 3) * 32, wn = (wid >> 2) * 64;
    const int g = lane >> 2, tg = lane & 3;
    const int seg = lane >> 3, i8 = lane & 7;
    const uint32_t sAh_b = smem_to_u32(sAh), sAl_b = smem_to_u32(sAl);
    const uint32_t sBh_b = smem_to_u32(sBh), sBl_b = smem_to_u32(sBl);

    float acc[2][8][4];
#pragma unroll
    for (int im = 0; im < 2; im++)
#pragma unroll
        for (int jn = 0; jn < 8; jn++)
#pragma unroll
            for (int q = 0; q < 4; q++) acc[im][jn][q] = 0.f;

    for (int kc = 0; kc < K; kc += 64) {
        if (kc) __syncthreads();
        {
            const __nv_bfloat16* srcs[4] = {Ah, Al, Bh, Bl};
            __nv_bfloat16* dsts[4] = {sAh, sAl, sBh, sBl};
            const int r0s[4] = {m0, m0, n0, n0};
#pragma unroll
            for (int t = 0; t < 4; t++) {
                for (int v = tid; v < 1024; v += 256) {
                    int row = v >> 3, q = (v & 7) * 8;
                    *reinterpret_cast<uint4*>(dsts[t] + row * LDS + q) =
                        *reinterpret_cast<const uint4*>(srcs[t] + (size_t)(r0s[t] + row) * K + kc + q);
                }
            }
        }
        __syncthreads();
#pragma unroll
        for (int ks = 0; ks < 4; ks++) {
            const int k0 = ks * 16;
            uint32_t ah[2][4], al[2][4];
#pragma unroll
            for (int im = 0; im < 2; im++) {
                int arow = wm + im * 16 + (seg & 1) * 8 + i8;
                int acol = k0 + (seg >> 1) * 8;
                LDSM_X4(ah[im], sAh_b + (uint32_t)(arow * LDS + acol) * 2u);
                LDSM_X4(al[im], sAl_b + (uint32_t)(arow * LDS + acol) * 2u);
            }
#pragma unroll
            for (int ip = 0; ip < 4; ip++) {
                int brow = wn + ip * 16 + (seg >> 1) * 8 + i8;
                int bcol = k0 + (seg & 1) * 8;
                uint32_t bh4[4], bl4[4];
                LDSM_X4(bh4, sBh_b + (uint32_t)(brow * LDS + bcol) * 2u);
                LDSM_X4(bl4, sBl_b + (uint32_t)(brow * LDS + bcol) * 2u);
#pragma unroll
                for (int im = 0; im < 2; im++) {
#pragma unroll
                    for (int hf = 0; hf < 2; hf++) {
                        float* c = acc[im][ip * 2 + hf];
                        mma16816(c, ah[im], bh4[2 * hf], bh4[2 * hf + 1]);
                        mma16816(c, al[im], bh4[2 * hf], bh4[2 * hf + 1]);
                        mma16816(c, ah[im], bl4[2 * hf], bl4[2 * hf + 1]);
                    }
                }
            }
        }
    }
#pragma unroll
    for (int im = 0; im < 2; im++) {
#pragma unroll
        for (int jn = 0; jn < 8; jn++) {
            int col = n0 + wn + jn * 8 + tg * 2;
            float b0v = bias[col], b1v = bias[col + 1];
            int row0 = m0 + wm + im * 16 + g;
            float2 v0 = make_float2(acc[im][jn][0] + b0v, acc[im][jn][1] + b1v);
            float2 v1 = make_float2(acc[im][jn][2] + b0v, acc[im][jn][3] + b1v);
            *reinterpret_cast<float2*>(C + (size_t)row0 * Ntot + col) = v0;
            *reinterpret_cast<float2*>(C + (size_t)(row0 + 8) * Ntot + col) = v1;
        }
    }
}

// ============ persistent BiLSTM: warp-spec halves + (PERM) sorted early-exit ============
template <int MODE, int PERM, int TSTEPS, int NSEQ, int ROWS, int THREADS>
__global__ __launch_bounds__(THREADS) void k_lstm(
    const int* __restrict__ idxmat, const int* __restrict__ perm,
    const float* __restrict__ tab_f, const float* __restrict__ tab_b,
    const float* __restrict__ bias_f, const float* __restrict__ bias_b,
    __nv_bfloat16* __restrict__ Hh, __nv_bfloat16* __restrict__ Hl)
{
    constexpr int HALF = THREADS / 2, NWH = HALF / 32, RG = NWH / 2, RPT = ROWS / RG;
    constexpr int CHF = 16 * G4;
    constexpr int NCP = (CHF / 4) / HALF;
    extern __shared__ char dsm[];
    float* hs    = reinterpret_cast<float*>(dsm);      // [2][ROWS][HH]
    float* wbuf  = hs + 2 * ROWS * HH;                 // [2][2][CHF]
    float* sbias = wbuf + 4 * CHF;                     // [2][G4]
    int* snmap = reinterpret_cast<int*>(sbias + 2 * G4);
    int* slen = snmap + ROWS;
    int* sfe = slen + ROWS; int* soff = sfe + ROWS; int* sun = soff + ROWS;

    const int tid = threadIdx.x, lane = tid & 31, wid = tid >> 5;
    const int half = (wid >= NWH) ? 1 : 0;
    const int hwid = wid - half * NWH, htid = tid - half * HALF;
    const int dir = half;
    const float* __restrict__ tab = dir ? tab_b : tab_f;
    const float* __restrict__ WhT = g_WhT[2 * MODE + dir];
    const int ch = hwid & 1, rg = hwid >> 1;
    const int e0 = ch * 64 + lane * 2;
    const int r0 = rg * RPT;
    // anti-imbalance group mapping for PERM (pairs small+large smax on one SM)
    int grp = blockIdx.x;
    if (PERM) {
        const int NG = NSEQ / ROWS;
        grp = (blockIdx.x < NG / 2) ? blockIdx.x : (NG + NG / 2 - 1 - blockIdx.x);
    }
    const int n0 = grp * ROWS;
    float* hsd = hs + dir * ROWS * HH;
    float* wbd = wbuf + dir * 2 * CHF;
    float* sbd = sbias + dir * G4;
    const uint32_t wbd_a = smem_to_u32(wbd);
    const int barid = 1 + half;

    if (MODE == 1) {
        const float* b = dir ? bias_b : bias_f;
        for (int i = htid; i < G4; i += HALF) sbd[i] = b[i];
    }
    float cst[RPT][2];
#pragma unroll
    for (int r = 0; r < RPT; r++) { cst[r][0] = 0.f; cst[r][1] = 0.f; }
    for (int i = tid; i < 2 * ROWS * HH / 4; i += THREADS)
        reinterpret_cast<float4*>(hs)[i] = make_float4(0.f, 0.f, 0.f, 0.f);
    if (tid < ROWS) {
        int n = PERM ? perm[n0 + tid] : (n0 + tid);
        snmap[tid] = n;
        slen[tid] = MODE ? g_p_len[n] : g_tok_len[n];
        if (MODE) { sfe[tid] = g_p_fe[n]; soff[tid] = g_p_off[n]; sun[tid] = g_p_un[n]; }
    }
    for (int i = htid; i < CHF / 4; i += HALF)
        reinterpret_cast<float4*>(wbd)[i] = reinterpret_cast<const float4*>(WhT)[i];
    __syncthreads();

    const int smax_v = PERM ? slen[ROWS - 1] : TSTEPS;   // sorted ascending => last is max

    for (int s = 0; s < smax_v; s++) {
        u64 acc[RPT][4];
#pragma unroll
        for (int r = 0; r < RPT; r++)
#pragma unroll
            for (int g = 0; g < 4; g++) acc[r][g] = 0ull;

#pragma unroll
        for (int cno = 0; cno < 8; cno++) {
            {
                const int nxt = (cno + 1) & 7;
                const float4* src = reinterpret_cast<const float4*>(WhT + nxt * CHF);
                uint32_t dsta = wbd_a + (uint32_t)(((cno + 1) & 1) * CHF) * 4u;
#pragma unroll
                for (int t = 0; t < NCP; t++)
                    CP_ASYNC16(dsta + (uint32_t)(htid + t * HALF) * 16u, src + htid + t * HALF);
                CP_COMMIT;
            }
            const float* wcur = wbd + (cno & 1) * CHF;
#pragma unroll
            for (int kp = 0; kp < 8; kp++) {
                const int kk = kp * 2;
                u64 w0i = *reinterpret_cast<const u64*>(&wcur[kk * G4 + e0]);
                u64 w0f = *reinterpret_cast<const u64*>(&wcur[kk * G4 + 128 + e0]);
                u64 w0g = *reinterpret_cast<const u64*>(&wcur[kk * G4 + 256 + e0]);
                u64 w0o = *reinterpret_cast<const u64*>(&wcur[kk * G4 + 384 + e0]);
                u64 w1i = *reinterpret_cast<const u64*>(&wcur[(kk + 1) * G4 + e0]);
                u64 w1f = *reinterpret_cast<const u64*>(&wcur[(kk + 1) * G4 + 128 + e0]);
                u64 w1g = *reinterpret_cast<const u64*>(&wcur[(kk + 1) * G4 + 256 + e0]);
                u64 w1o = *reinterpret_cast<const u64*>(&wcur[(kk + 1) * G4 + 384 + e0]);
#pragma unroll
                for (int r = 0; r < RPT; r++) {
                    float2 hp = *reinterpret_cast<const float2*>(&hsd[(r0 + r) * HH + cno * 16 + kk]);
                    u64 ha = dup2(hp.x), hb = dup2(hp.y);
                    ffma2(acc[r][0], ha, w0i); ffma2(acc[r][1], ha, w0f);
                    ffma2(acc[r][2], ha, w0g); ffma2(acc[r][3], ha, w0o);
                    ffma2(acc[r][0], hb, w1i); ffma2(acc[r][1], hb, w1f);
                    ffma2(acc[r][2], hb, w1g); ffma2(acc[r][3], hb, w1o);
                }
            }
            CP_WAIT0;
            BAR_HALF(barid, HALF);
        }

#pragma unroll
        for (int r = 0; r < RPT; r++) {
            const int row = r0 + r, len = slen[row];
            const int n = snmap[row];
            const int gi = dir ? min(max(len - 1 - s, 0), TSTEPS - 1) : s;
            float2 ai = unpack2(acc[r][0]), af = unpack2(acc[r][1]);
            float2 ag = unpack2(acc[r][2]), ao = unpack2(acc[r][3]);
            float2 gvi, gvf, gvg, gvo;
            if (MODE == 0) {
                int id = idxmat[(size_t)gi * NSEQ + n];
                const float* grow = tab + (size_t)id * G4;
                gvi = *reinterpret_cast<const float2*>(&grow[e0]);
                gvf = *reinterpret_cast<const float2*>(&grow[128 + e0]);
                gvg = *reinterpret_cast<const float2*>(&grow[256 + e0]);
                gvo = *reinterpret_cast<const float2*>(&grow[384 + e0]);
            } else {
                int pl = idxmat[(size_t)gi * NSEQ + n];
                bool keep = (gi < sfe[row]) && (pl >= 0) && (pl < sun[row]);
                gvi = *reinterpret_cast<const float2*>(&sbd[e0]);
                gvf = *reinterpret_cast<const float2*>(&sbd[128 + e0]);
                gvg = *reinterpret_cast<const float2*>(&sbd[256 + e0]);
                gvo = *reinterpret_cast<const float2*>(&sbd[384 + e0]);
                if (keep) {
                    int gidx = min(pl + soff[row], NU - 1);
                    const float* grow = tab + (size_t)gidx * G4;
                    float2 t0 = *reinterpret_cast<const float2*>(&grow[e0]);
                    float2 t1 = *reinterpret_cast<const float2*>(&grow[128 + e0]);
                    float2 t2 = *reinterpret_cast<const float2*>(&grow[256 + e0]);
                    float2 t3 = *reinterpret_cast<const float2*>(&grow[384 + e0]);
                    gvi.x += t0.x; gvi.y += t0.y; gvf.x += t1.x; gvf.y += t1.y;
                    gvg.x += t2.x; gvg.y += t2.y; gvo.x += t3.x; gvo.y += t3.y;
                }
            }
            float h0, h1;
            {
                float iv = ai.x + gvi.x, fv = af.x + gvf.x, gg = ag.x + gvg.x, ov = ao.x + gvo.x;
                float cn = sigm(fv) * cst[r][0] + sigm(iv) * ftanh(gg);
                cst[r][0] = cn; h0 = sigm(ov) * ftanh(cn);
            }
            {
                float iv = ai.y + gvi.y, fv = af.y + gvf.y, gg = ag.y + gvg.y, ov = ao.y + gvo.y;
                float cn = sigm(fv) * cst[r][1] + sigm(iv) * ftanh(gg);
                cst[r][1] = cn; h1 = sigm(ov) * ftanh(cn);
            }
            *reinterpret_cast<float2*>(&hsd[row * HH + e0]) = make_float2(h0, h1);
            __nv_bfloat16 hb0 = __float2bfloat16(h0), hb1 = __float2bfloat16(h1);
            __nv_bfloat162 hb(hb0, hb1);
            __nv_bfloat162 lb(__float2bfloat16(h0 - __bfloat162float(hb0)),
                              __float2bfloat16(h1 - __bfloat162float(hb1)));
            if (s < len) {
                int wi = dir ? (len - 1 - s) : s;
                size_t base = ((size_t)wi * NSEQ + n) * (2 * HH) + dir * HH + e0;
                *reinterpret_cast<__nv_bfloat162*>(Hh + base) = hb;
                *reinterpret_cast<__nv_bfloat162*>(Hl + base) = lb;
            } else if (dir == 0) {
                __nv_bfloat162 z(__float2bfloat16(0.f), __float2bfloat16(0.f));
                size_t b0 = ((size_t)s * NSEQ + n) * (2 * HH) + e0;
                *reinterpret_cast<__nv_bfloat162*>(Hh + b0) = z;
                *reinterpret_cast<__nv_bfloat162*>(Hl + b0) = z;
                *reinterpret_cast<__nv_bfloat162*>(Hh + b0 + HH) = z;
                *reinterpret_cast<__nv_bfloat162*>(Hl + b0 + HH) = z;
            }
        }
        BAR_HALF(barid, HALF);
    }
}

// ============ attention pooling ============
__global__ void k_attn(const float* __restrict__ ln_g, const float* __restrict__ ln_b,
                       const float* __restrict__ attn_w, const float* __restrict__ attn_bp) {
    int gwarp = (blockIdx.x * blockDim.x + threadIdx.x) >> 5;
    int lane = threadIdx.x & 31;
    if (gwarp >= NU) return;
    int n = gwarp, len = g_tok_len[n];
    float gg[4], bb[4], aw[4];
#pragma unroll
    for (int q = 0; q < 4; q++) {
        int e = lane + 32 * q;
        gg[q] = ln_g[e]; bb[q] = ln_b[e]; aw[q] = attn_w[e];
    }
    float ab = attn_bp[0];
    float sc[TT], smax = -1e30f;
#pragma unroll
    for (int t = 0; t < TT; t++) {
        sc[t] = -1e30f;
        if (t < len) {
            float o[4], lsum = 0.f;
#pragma unroll
            for (int q = 0; q < 4; q++) {
                o[q] = g_lin[((size_t)t * NU + n) * EE + lane + 32 * q];
                lsum += o[q];
            }
#pragma unroll
            for (int off = 16; off; off >>= 1) lsum += __shfl_xor_sync(0xffffffffu, lsum, off);
            float mean = lsum * (1.f / 128.f);
            float vs = 0.f;
#pragma unroll
            for (int q = 0; q < 4; q++) { float d = o[q] - mean; vs += d * d; }
#pragma unroll
            for (int off = 16; off; off >>= 1) vs += __shfl_xor_sync(0xffffffffu, vs, off);
            float inv = rsqrtf(vs * (1.f / 128.f) + 1e-5f);
            float ssum = 0.f;
#pragma unroll
            for (int q = 0; q < 4; q++)
                ssum += ftanh((o[q] - mean) * inv * gg[q] + bb[q]) * aw[q];
#pragma unroll
            for (int off = 16; off; off >>= 1) ssum += __shfl_xor_sync(0xffffffffu, ssum, off);
            sc[t] = ssum + ab;
            smax = fmaxf(smax, sc[t]);
        }
    }
    float den = 0.f, wts[TT];
#pragma unroll
    for (int t = 0; t < TT; t++) {
        wts[t] = (t < len) ? __expf(sc[t] - smax) : 0.f;
        den += wts[t];
    }
    float invden = 1.f / den;
    float accq[4] = {0.f, 0.f, 0.f, 0.f};
#pragma unroll
    for (int t = 0; t < TT; t++) {
        if (t < len) {
            float wt = wts[t] * invden;
#pragma unroll
            for (int q = 0; q < 4; q++)
                accq[q] += wt * g_lin[((size_t)t * NU + n) * EE + lane + 32 * q];
        }
    }
#pragma unroll
    for (int q = 0; q < 4; q++) {
        __nv_bfloat16 h = __float2bfloat16(accq[q]);
        __nv_bfloat16 l = __float2bfloat16(accq[q] - __bfloat162float(h));
        g_tf_h[(size_t)n * EE + lane + 32 * q] = h;
        g_tf_l[(size_t)n * EE + lane + 32 * q] = l;
    }
}

// ============ host launcher ============
extern "C" void kernel_launch(void* const* d_in, const int* in_sizes, int n_in,
                              void* d_out, int out_size) {
    const int*   units  = (const int*)d_in[0];
    const int*   paths  = (const int*)d_in[1];
    const int*   upd    = (const int*)d_in[2];
    const int*   ppd    = (const int*)d_in[3];
    const float* emb    = (const float*)d_in[4];
    const float* tl_Wif = (const float*)d_in[5];
    const float* tl_Whf = (const float*)d_in[6];
    const float* tl_bf  = (const float*)d_in[7];
    const float* tl_Wib = (const float*)d_in[8];
    const float* tl_Whb = (const float*)d_in[9];
    const float* tl_bb  = (const float*)d_in[10];
    const float* lin_W  = (const float*)d_in[11];
    const float* lin_b  = (const float*)d_in[12];
    const float* ln_g   = (const float*)d_in[13];
    const float* ln_bv  = (const float*)d_in[14];
    const float* attn_w = (const float*)d_in[15];
    const float* attn_b = (const float*)d_in[16];
    const float* pl_Wif = (const float*)d_in[17];
    const float* pl_Whf = (const float*)d_in[18];
    const float* pl_bf  = (const float*)d_in[19];
    const float* pl_Wib = (const float*)d_in[20];
    const float* pl_Whb = (const float*)d_in[21];
    const float* pl_bb  = (const float*)d_in[22];
    const float* ul_W   = (const float*)d_in[23];
    const float* ul_b   = (const float*)d_in[24];
    float* out = (float*)d_out;

    void *pVTf, *pVTb, *pPTf, *pPTb, *pZero, *pLin, *pPerm;
    cudaGetSymbolAddress(&pVTf, g_VTf);    cudaGetSymbolAddress(&pVTb, g_VTb);
    cudaGetSymbolAddress(&pPTf, g_PTf);    cudaGetSymbolAddress(&pPTb, g_PTb);
    cudaGetSymbolAddress(&pZero, g_zero);  cudaGetSymbolAddress(&pLin, g_lin);
    cudaGetSymbolAddress(&pPerm, g_perm_t);
    void *pEh, *pEl, *pHch, *pHcl, *pTfh, *pTfl, *pHph, *pHpl, *pWih, *pWil, *pW2h, *pW2l;
    cudaGetSymbolAddress(&pEh, g_emb_h);   cudaGetSymbolAddress(&pEl, g_emb_l);
    cudaGetSymbolAddress(&pHch, g_Hcat_h); cudaGetSymbolAddress(&pHcl, g_Hcat_l);
    cudaGetSymbolAddress(&pTfh, g_tf_h);   cudaGetSymbolAddress(&pTfl, g_tf_l);
    cudaGetSymbolAddress(&pHph, g_Hp_h);   cudaGetSymbolAddress(&pHpl, g_Hp_l);
    cudaGetSymbolAddress(&pWih, g_Wih);    cudaGetSymbolAddress(&pWil, g_Wil);
    cudaGetSymbolAddress(&pW2h, g_W2h);    cudaGetSymbolAddress(&pW2l, g_W2l);
    __nv_bfloat16* Wih = (__nv_bfloat16*)pWih;  __nv_bfloat16* Wil = (__nv_bfloat16*)pWil;
    __nv_bfloat16* W2h = (__nv_bfloat16*)pW2h;  __nv_bfloat16* W2l = (__nv_bfloat16*)pW2l;
    const int* permT = (const int*)pPerm;

    const int MM_SMEM = 4 * 128 * 72 * 2;
    const int LS_T = 2 * 16 * HH * 4 + 4 * 8192 * 4 + 2 * G4 * 4 + 5 * 16 * 4;  // 151872
    const int LS_P = 2 * 8 * HH * 4 + 4 * 8192 * 4 + 2 * G4 * 4 + 5 * 8 * 4;    // 143680
    cudaFuncSetAttribute(k_mm2<128>, cudaFuncAttributeMaxDynamicSharedMemorySize, MM_SMEM);
    cudaFuncSetAttribute(k_mm2<256>, cudaFuncAttributeMaxDynamicSharedMemorySize, MM_SMEM);
    cudaFuncSetAttribute((const void*)k_lstm<0, 1, TT, NU, 16, 512>,
                         cudaFuncAttributeMaxDynamicSharedMemorySize, LS_T + 1024);
    cudaFuncSetAttribute((const void*)k_lstm<1, 0, LPATH, NPATH, 8, 256>,
                         cudaFuncAttributeMaxDynamicSharedMemorySize, LS_P + 1024);

    // launch 0: fused setup
    k_prep<<<dim3(256, 6), 256>>>(units, tl_Whf, tl_Whb, pl_Whf, pl_Whb, paths, upd, ppd);
    // launch 1: hilo emb + tl weights + lin_W  (+ seg 4: token sort)
    {
        HiloArgs a;
        a.s[0] = emb;    a.h[0] = (__nv_bfloat16*)pEh; a.l[0] = (__nv_bfloat16*)pEl; a.n[0] = VOCAB * EE / 4;
        a.s[1] = tl_Wif; a.h[1] = Wih + 0 * G4 * EE;   a.l[1] = Wil + 0 * G4 * EE;   a.n[1] = G4 * EE / 4;
        a.s[2] = tl_Wib; a.h[2] = Wih + 1 * G4 * EE;   a.l[2] = Wil + 1 * G4 * EE;   a.n[2] = G4 * EE / 4;
        a.s[3] = lin_W;  a.h[3] = W2h;                 a.l[3] = W2l;                 a.n[3] = EE * 256 / 4;
        k_hilo_multi<<<dim3((VOCAB * EE / 4 + 255) / 256, 5), 256>>>(a);
    }
    // launch 2: VT (both dirs)
    k_mm2<128><<<dim3(4, VOCAB / 128, 2), 256, MM_SMEM>>>(
        (const __nv_bfloat16*)pEh, (const __nv_bfloat16*)pEl,
        Wih + 0 * G4 * EE, Wil + 0 * G4 * EE, tl_bf, (float*)pVTf,
        Wih + 1 * G4 * EE, Wil + 1 * G4 * EE, tl_bb, (float*)pVTb, G4);
    // launch 3 (PROFILE TARGET): token BiLSTM, sorted + early-exit, 256 CTAs
    k_lstm<0, 1, TT, NU, 16, 512><<<NU / 16, 512, LS_T>>>(
        units, permT, (const float*)pVTf, (const float*)pVTb, nullptr, nullptr,
        (__nv_bfloat16*)pHch, (__nv_bfloat16*)pHcl);
    // launch 4: hilo pl weights + ul_W
    {
        HiloArgs a;
        a.s[0] = pl_Wif; a.h[0] = Wih + 2 * G4 * EE; a.l[0] = Wil + 2 * G4 * EE; a.n[0] = G4 * EE / 4;
        a.s[1] = pl_Wib; a.h[1] = Wih + 3 * G4 * EE; a.l[1] = Wil + 3 * G4 * EE; a.n[1] = G4 * EE / 4;
        a.s[2] = ul_W;   a.h[2] = W2h + EE * 256;    a.l[2] = W2l + EE * 256;    a.n[2] = EE * 256 / 4;
        a.s[3] = ul_W;   a.h[3] = W2h + EE * 256;    a.l[3] = W2l + EE * 256;    a.n[3] = 0;
        k_hilo_multi<<<dim3((G4 * EE / 4 + 255) / 256, 4), 256>>>(a);
    }
    // launch 5: lin
    k_mm2<256><<<dim3(1, TT * NU / 128, 1), 256, MM_SMEM>>>(
        (const __nv_bfloat16*)pHch, (const __nv_bfloat16*)pHcl,
        W2h, W2l, lin_b, (float*)pLin, W2h, W2l, lin_b, (float*)pLin, EE);
    // launch 6: attention
    k_attn<<<(NU * 32) / 256, 256>>>(ln_g, ln_bv, attn_w, attn_b);
    // launch 7: PT (both dirs)
    k_mm2<128><<<dim3(4, NU / 128, 2), 256, MM_SMEM>>>(
        (const __nv_bfloat16*)pTfh, (const __nv_bfloat16*)pTfl,
        Wih + 2 * G4 * EE, Wil + 2 * G4 * EE, (const float*)pZero, (float*)pPTf,
        Wih + 3 * G4 * EE, Wil + 3 * G4 * EE, (const float*)pZero, (float*)pPTb, G4);
    // launch 8: path BiLSTM (unchanged scheduling)
    k_lstm<1, 0, LPATH, NPATH, 8, 256><<<NPATH / 8, 256, LS_P>>>(
        paths, permT, (const float*)pPTf, (const float*)pPTb, pl_bf, pl_bb,
        (__nv_bfloat16*)pHph, (__nv_bfloat16*)pHpl);
    // launch 9: out
    k_mm2<256><<<dim3(1, LPATH * NPATH / 128, 1), 256, MM_SMEM>>>(
        (const __nv_bfloat16*)pHph, (const __nv_bfloat16*)pHpl,
        W2h + EE * 256, W2l + EE * 256, ul_b, out,
        W2h + EE * 256, W2l + EE * 256, ul_b, out, EE);
}